// round 11
// baseline (speedup 1.0000x reference)
#include <cuda_runtime.h>
#include <cuda_bf16.h>
#include <cstdint>

#define Bb   8
#define Tt   4096
#define Dd   1024
#define Hh   16
#define DHh  64
#define UMAX 64
#define MPMAX 1024
#define BUPMAX 512

typedef long long ll;
typedef __nv_bfloat16 bf16;

// ---------------- scratch (static __device__, allocation-free) ----------------
__device__ bf16  g_xsh[Bb * UMAX * Dd];
__device__ bf16  g_xsl[Bb * UMAX * Dd];
__device__ bf16  g_Wqh[Dd * Dd];
__device__ bf16  g_Wql[Dd * Dd];
__device__ bf16  g_WkTh[Dd * Dd];
__device__ bf16  g_WkTl[Dd * Dd];
__device__ bf16  g_Wvh[(Dd + 128) * Dd];     // row-padded for OOB-safe tile loads
__device__ bf16  g_Wvl[(Dd + 128) * Dd];
__device__ bf16  g_Woh[Dd * Dd];
__device__ bf16  g_Wol[Dd * Dd];
__device__ float g_qsp[4 * BUPMAX * Dd];     // step-2 split-K partials
__device__ bf16  g_Qsh[Bb * UMAX * Dd];
__device__ bf16  g_Qsl[Bb * UMAX * Dd];
__device__ bf16  g_Qth[(size_t)Bb * MPMAX * Dd];
__device__ bf16  g_Qtl[(size_t)Bb * MPMAX * Dd];
__device__ bf16  g_xh[(size_t)Bb * Tt * Dd];
__device__ bf16  g_xl[(size_t)Bb * Tt * Dd];
__device__ bf16  g_xth[(size_t)Bb * Dd * Tt];
__device__ bf16  g_xtl[(size_t)Bb * Dd * Tt];
__device__ float g_sc[(size_t)Bb * MPMAX * Tt];
__device__ bf16  g_ah[(size_t)Bb * MPMAX * Tt];
__device__ bf16  g_al[(size_t)Bb * MPMAX * Tt];
__device__ float g_rsum[Bb * Hh * UMAX];
__device__ float g_wxp[(size_t)2 * Bb * MPMAX * Dd];  // step-6 split-K partials
__device__ bf16  g_wxh[(size_t)Bb * MPMAX * Dd];
__device__ bf16  g_wxl[(size_t)Bb * MPMAX * Dd];
__device__ float g_ctx[Bb * Hh * UMAX * DHh];
__device__ bf16  g_crh[Bb * (UMAX + 2) * Dd];
__device__ bf16  g_crl[Bb * (UMAX + 2) * Dd];
__device__ float g_ys[Bb * (UMAX + 1) * Dd];

// ---------------- PTX helpers (sm_80/sm_90 portable only) ----------------
__device__ __forceinline__ uint32_t smem_u32(const void* p) {
    uint32_t a;
    asm("{ .reg .u64 t; cvta.to.shared.u64 t, %1; cvt.u32.u64 %0, t; }" : "=r"(a) : "l"(p));
    return a;
}
__device__ __forceinline__ void cp_async16(uint32_t s, const void* g) {
    asm volatile("cp.async.cg.shared.global [%0], [%1], 16;" :: "r"(s), "l"(g) : "memory");
}
__device__ __forceinline__ void ldsm_x4(uint32_t* r, uint32_t a) {
    asm volatile("ldmatrix.sync.aligned.m8n8.x4.shared.b16 {%0,%1,%2,%3}, [%4];"
                 : "=r"(r[0]), "=r"(r[1]), "=r"(r[2]), "=r"(r[3]) : "r"(a));
}
__device__ __forceinline__ void ldsm_x2(uint32_t* r, uint32_t a) {
    asm volatile("ldmatrix.sync.aligned.m8n8.x2.shared.b16 {%0,%1}, [%2];"
                 : "=r"(r[0]), "=r"(r[1]) : "r"(a));
}
__device__ __forceinline__ void mma16816(float* c, const uint32_t* a, const uint32_t* b) {
    asm volatile(
        "mma.sync.aligned.m16n8k16.row.col.f32.bf16.bf16.f32 "
        "{%0,%1,%2,%3}, {%4,%5,%6,%7}, {%8,%9}, {%0,%1,%2,%3};"
        : "+f"(c[0]), "+f"(c[1]), "+f"(c[2]), "+f"(c[3])
        : "r"(a[0]), "r"(a[1]), "r"(a[2]), "r"(a[3]), "r"(b[0]), "r"(b[1]));
}

__device__ __forceinline__ void split2(float v, bf16& h, bf16& l) {
    h = __float2bfloat16(v);
    l = __float2bfloat16(v - __bfloat162float(h));
}

// ============ WIDE merged-pass warp-MMA GEMM (steps 4, 6) ============
// C = 3-term split(A) @ split(B)^T.  Block 128x256, 8 warps (2x4), warp 64x64,
// BK=32, 3-stage cp.async (48KB/stage).  z = bb*KS + ks; K window ks.
#define WSTG 49152u

template <int EPI>
__global__ __launch_bounds__(256, 1) void mma_wide_k(
    float* __restrict__ C, bf16* __restrict__ Ch, bf16* __restrict__ Cl,
    const bf16* __restrict__ Ah, const bf16* __restrict__ Al,
    const bf16* __restrict__ Bh, const bf16* __restrict__ Bl,
    int Kext, int lda, int ldb, int ldc, int Mreal, int Nreal,
    ll sAb, ll sBb, ll sCb, int KS, ll sCs) {
    extern __shared__ char smem[];
    uint32_t sbase = smem_u32(smem);
    int tid = threadIdx.x, wid = tid >> 5, lane = tid & 31;
    int z = blockIdx.z;
    int ks = z % KS, bb = z / KS;
    int m0 = blockIdx.y * 128, n0 = blockIdx.x * 256;

    const bf16* A0 = Ah + bb * sAb + (ll)ks * Kext + (size_t)m0 * lda;
    const bf16* A1 = Al + bb * sAb + (ll)ks * Kext + (size_t)m0 * lda;
    const bf16* B0 = Bh + bb * sBb + (ll)ks * Kext + (size_t)n0 * ldb;
    const bf16* B1 = Bl + bb * sBb + (ll)ks * Kext + (size_t)n0 * ldb;

    // A cp mapping: row = tid>>1, two k-chunk pairs per thread
    int arowl = tid >> 1, cq = tid & 1, rxa = arowl & 7;
    size_t gA0 = (size_t)arowl * lda + cq * 8, gA1 = gA0 + 16;
    uint32_t dh0 = arowl * 128 + ((cq)     ^ rxa) * 16;
    uint32_t dh1 = arowl * 128 + ((cq + 2) ^ rxa) * 16;
    uint32_t dl0 = arowl * 128 + ((cq + 4) ^ rxa) * 16;
    uint32_t dl1 = arowl * 128 + ((cq + 6) ^ rxa) * 16;
    // B cp mapping: whole row per thread (256 rows)
    int rxb = tid & 7;
    size_t gB = (size_t)tid * ldb;
    uint32_t bbse = 16384u + tid * 128;

    // ldsm per-lane offsets
    int warp_m = wid >> 2, warp_n = wid & 3;
    int rl = lane & 15, cl = lane >> 4, arx = lane & 7;
    int bq = (lane >> 3) & 1;
    uint32_t arow[4], brow[4];
#pragma unroll
    for (int i = 0; i < 4; i++) arow[i] = (warp_m * 64 + i * 16 + rl) * 128;
#pragma unroll
    for (int jj = 0; jj < 4; jj++)
        brow[jj] = 16384u + (warp_n * 64 + jj * 16 + (lane & 7) + ((lane >> 4) & 1) * 8) * 128;

    float acc[4][8][4];
#pragma unroll
    for (int i = 0; i < 4; i++)
#pragma unroll
        for (int j = 0; j < 8; j++)
#pragma unroll
            for (int q = 0; q < 4; q++) acc[i][j][q] = 0.f;

    const int NC = Kext >> 5;

#define WISSUE(c_) do {                                                       \
    size_t ko_ = (size_t)(c_) * 32;                                           \
    uint32_t st_ = sbase + ((c_) % 3) * WSTG;                                 \
    cp_async16(st_ + dh0, A0 + ko_ + gA0);                                    \
    cp_async16(st_ + dh1, A0 + ko_ + gA1);                                    \
    cp_async16(st_ + dl0, A1 + ko_ + gA0);                                    \
    cp_async16(st_ + dl1, A1 + ko_ + gA1);                                    \
    _Pragma("unroll") for (int cc_ = 0; cc_ < 4; cc_++) {                     \
        cp_async16(st_ + bbse + (((cc_)     ^ rxb) * 16), B0 + ko_ + gB + cc_ * 8); \
        cp_async16(st_ + bbse + (((cc_ + 4) ^ rxb) * 16), B1 + ko_ + gB + cc_ * 8); \
    }                                                                         \
    asm volatile("cp.async.commit_group;" ::: "memory");                      \
} while (0)

    WISSUE(0);
    if (NC > 1) WISSUE(1);

    for (int c = 0; c < NC; c++) {
        if (c + 1 < NC) asm volatile("cp.async.wait_group 1;" ::: "memory");
        else            asm volatile("cp.async.wait_group 0;" ::: "memory");
        __syncthreads();
        if (c + 2 < NC) WISSUE(c + 2);

        uint32_t sa = sbase + (c % 3) * WSTG;
#pragma unroll
        for (int kk = 0; kk < 2; kk++) {
            uint32_t Bhf[4][4], Blf[4][4], Af[4][4];
#pragma unroll
            for (int jj = 0; jj < 4; jj++)
                ldsm_x4(Bhf[jj], sa + brow[jj] + (((kk * 2 + bq)     ^ arx) << 4));
#pragma unroll
            for (int jj = 0; jj < 4; jj++)
                ldsm_x4(Blf[jj], sa + brow[jj] + (((kk * 2 + bq + 4) ^ arx) << 4));
#pragma unroll
            for (int i = 0; i < 4; i++)
                ldsm_x4(Af[i], sa + arow[i] + (((kk * 2 + cl)     ^ arx) << 4));
#pragma unroll
            for (int i = 0; i < 4; i++)
#pragma unroll
                for (int jj = 0; jj < 4; jj++) {
                    mma16816(acc[i][jj * 2 + 0], Af[i], &Bhf[jj][0]);
                    mma16816(acc[i][jj * 2 + 1], Af[i], &Bhf[jj][2]);
                }
#pragma unroll
            for (int i = 0; i < 4; i++)
#pragma unroll
                for (int jj = 0; jj < 4; jj++) {
                    mma16816(acc[i][jj * 2 + 0], Af[i], &Blf[jj][0]);
                    mma16816(acc[i][jj * 2 + 1], Af[i], &Blf[jj][2]);
                }
#pragma unroll
            for (int i = 0; i < 4; i++)
                ldsm_x4(Af[i], sa + arow[i] + (((kk * 2 + cl + 4) ^ arx) << 4));
#pragma unroll
            for (int i = 0; i < 4; i++)
#pragma unroll
                for (int jj = 0; jj < 4; jj++) {
                    mma16816(acc[i][jj * 2 + 0], Af[i], &Bhf[jj][0]);
                    mma16816(acc[i][jj * 2 + 1], Af[i], &Bhf[jj][2]);
                }
        }
        __syncthreads();
    }

    // ---- epilogue ----
    ll cbase = bb * sCb + (ll)ks * sCs;
#pragma unroll
    for (int i = 0; i < 4; i++) {
        int m = m0 + warp_m * 64 + i * 16 + (lane >> 2);
#pragma unroll
        for (int jj = 0; jj < 4; jj++)
#pragma unroll
            for (int p = 0; p < 2; p++) {
                int n = n0 + warp_n * 64 + jj * 16 + p * 8 + (lane & 3) * 2;
                int j = jj * 2 + p;
                if (n < Nreal) {
#pragma unroll
                    for (int q = 0; q < 2; q++) {
                        int mm = m + q * 8;
                        if (mm < Mreal) {
                            if (EPI == 0) {
                                *(float2*)&C[cbase + (size_t)mm * ldc + n] =
                                    make_float2(acc[i][j][q * 2], acc[i][j][q * 2 + 1]);
                            } else {
                                bf16 h0, l0, h1, l1;
                                split2(acc[i][j][q * 2], h0, l0);
                                split2(acc[i][j][q * 2 + 1], h1, l1);
                                __nv_bfloat162 hp, lp;
                                hp.x = h0; hp.y = h1; lp.x = l0; lp.y = l1;
                                *(__nv_bfloat162*)&Ch[cbase + (size_t)mm * ldc + n] = hp;
                                *(__nv_bfloat162*)&Cl[cbase + (size_t)mm * ldc + n] = lp;
                            }
                        }
                    }
                }
            }
    }
}

// ============ narrow merged-pass warp-MMA GEMM (steps 2,3,7,9) ============
#define BMt 128
#define BNt 128
#define STG_SZ 32768u
#define NSTAGE 3

template <int EPI>
__global__ __launch_bounds__(256, 2) void mma_gemm_k(
    float* __restrict__ C, bf16* __restrict__ Ch, bf16* __restrict__ Cl,
    const bf16* __restrict__ Ah, const bf16* __restrict__ Al,
    const bf16* __restrict__ Bh, const bf16* __restrict__ Bl,
    int Kext, int lda, int ldb, int ldc, int Mreal, int Nreal,
    ll sAb, ll sAh, ll sBb, ll sBh, ll sCb, ll sCh,
    int nh, int KS, ll sCs) {
    extern __shared__ char smem[];
    uint32_t sbase = smem_u32(smem);
    int tid = threadIdx.x, wid = tid >> 5, lane = tid & 31;
    int z = blockIdx.z;
    int ks = z % KS, bh2 = z / KS;
    int hh = bh2 % nh, bb = bh2 / nh;
    int m0 = blockIdx.y * BMt, n0 = blockIdx.x * BNt;

    const bf16* A0 = Ah + bb * sAb + hh * sAh + (ll)ks * Kext + (size_t)m0 * lda;
    const bf16* A1 = Al + bb * sAb + hh * sAh + (ll)ks * Kext + (size_t)m0 * lda;
    const bf16* B0 = Bh + bb * sBb + hh * sBh + (ll)ks * Kext + (size_t)n0 * ldb;
    const bf16* B1 = Bl + bb * sBb + hh * sBh + (ll)ks * Kext + (size_t)n0 * ldb;

    int row = tid >> 1, cq = tid & 1, rx = row & 7;
    size_t   gA0 = (size_t)row * lda + cq * 8, gA1 = gA0 + 16;
    size_t   gB0 = (size_t)row * ldb + cq * 8, gB1 = gB0 + 16;
    uint32_t dh0 = row * 128 + ((cq)     ^ rx) * 16;
    uint32_t dh1 = row * 128 + ((cq + 2) ^ rx) * 16;
    uint32_t dl0 = row * 128 + ((cq + 4) ^ rx) * 16;
    uint32_t dl1 = row * 128 + ((cq + 6) ^ rx) * 16;

    int warp_m = wid >> 2, warp_n = wid & 3;
    int rl = lane & 15, cl = lane >> 4, arx = lane & 7;
    int rb = lane & 7,  cb = (lane >> 3) & 1;
    uint32_t arow[4], brow[4];
#pragma unroll
    for (int i = 0; i < 4; i++) arow[i] = (warp_m * 64 + i * 16 + rl) * 128;
#pragma unroll
    for (int j = 0; j < 4; j++) brow[j] = (warp_n * 32 + j * 8 + rb) * 128;

    float acc[4][4][4];
#pragma unroll
    for (int i = 0; i < 4; i++)
#pragma unroll
        for (int j = 0; j < 4; j++)
#pragma unroll
            for (int q = 0; q < 4; q++) acc[i][j][q] = 0.f;

    const int NC = Kext >> 5;

#define ISSUE(c_) do {                                                        \
    size_t ko_ = (size_t)(c_) * 32;                                           \
    uint32_t st_ = sbase + ((c_) % NSTAGE) * STG_SZ;                          \
    cp_async16(st_ + dh0, A0 + ko_ + gA0);                                    \
    cp_async16(st_ + dh1, A0 + ko_ + gA1);                                    \
    cp_async16(st_ + dl0, A1 + ko_ + gA0);                                    \
    cp_async16(st_ + dl1, A1 + ko_ + gA1);                                    \
    cp_async16(st_ + 16384u + dh0, B0 + ko_ + gB0);                           \
    cp_async16(st_ + 16384u + dh1, B0 + ko_ + gB1);                           \
    cp_async16(st_ + 16384u + dl0, B1 + ko_ + gB0);                           \
    cp_async16(st_ + 16384u + dl1, B1 + ko_ + gB1);                           \
    asm volatile("cp.async.commit_group;" ::: "memory");                      \
} while (0)

    ISSUE(0);
    if (NC > 1) ISSUE(1);

    for (int c = 0; c < NC; c++) {
        if (c + 1 < NC) asm volatile("cp.async.wait_group 1;" ::: "memory");
        else            asm volatile("cp.async.wait_group 0;" ::: "memory");
        __syncthreads();
        if (c + 2 < NC) ISSUE(c + 2);

        uint32_t sa = sbase + (c % NSTAGE) * STG_SZ;
        uint32_t sb = sa + 16384u;
#pragma unroll
        for (int kk = 0; kk < 2; kk++) {
            uint32_t bh[4][2], blo[4][2], af[4][4];
#pragma unroll
            for (int j = 0; j < 4; j++)
                ldsm_x2(bh[j], sb + brow[j] + (((kk * 2 + cb)     ^ rb) << 4));
#pragma unroll
            for (int j = 0; j < 4; j++)
                ldsm_x2(blo[j], sb + brow[j] + (((kk * 2 + cb + 4) ^ rb) << 4));
#pragma unroll
            for (int i = 0; i < 4; i++)
                ldsm_x4(af[i], sa + arow[i] + (((kk * 2 + cl)     ^ arx) << 4));
#pragma unroll
            for (int i = 0; i < 4; i++)
#pragma unroll
                for (int j = 0; j < 4; j++) mma16816(acc[i][j], af[i], bh[j]);
#pragma unroll
            for (int i = 0; i < 4; i++)
#pragma unroll
                for (int j = 0; j < 4; j++) mma16816(acc[i][j], af[i], blo[j]);
#pragma unroll
            for (int i = 0; i < 4; i++)
                ldsm_x4(af[i], sa + arow[i] + (((kk * 2 + cl + 4) ^ arx) << 4));
#pragma unroll
            for (int i = 0; i < 4; i++)
#pragma unroll
                for (int j = 0; j < 4; j++) mma16816(acc[i][j], af[i], bh[j]);
        }
        __syncthreads();
    }

    ll cbase = bb * sCb + hh * sCh + (ll)ks * sCs;
#pragma unroll
    for (int i = 0; i < 4; i++) {
        int m = m0 + warp_m * 64 + i * 16 + (lane >> 2);
#pragma unroll
        for (int j = 0; j < 4; j++) {
            int n = n0 + warp_n * 32 + j * 8 + (lane & 3) * 2;
            if (n < Nreal) {
#pragma unroll
                for (int p = 0; p < 2; p++) {
                    int mm = m + p * 8;
                    if (mm < Mreal) {
                        if (EPI == 0) {
                            *(float2*)&C[cbase + (size_t)mm * ldc + n] =
                                make_float2(acc[i][j][p * 2], acc[i][j][p * 2 + 1]);
                        } else {
                            bf16 h0, l0, h1, l1;
                            split2(acc[i][j][p * 2], h0, l0);
                            split2(acc[i][j][p * 2 + 1], h1, l1);
                            __nv_bfloat162 hp, lp;
                            hp.x = h0; hp.y = h1; lp.x = l0; lp.y = l1;
                            *(__nv_bfloat162*)&Ch[cbase + (size_t)mm * ldc + n] = hp;
                            *(__nv_bfloat162*)&Cl[cbase + (size_t)mm * ldc + n] = lp;
                        }
                    }
                }
            }
        }
    }
}

// ---------------- x -> bf16 hi/lo (straight + transposed) ----------------
__global__ __launch_bounds__(256) void convx_k(const float* __restrict__ x,
                                               bf16* __restrict__ xh, bf16* __restrict__ xl,
                                               bf16* __restrict__ xth, bf16* __restrict__ xtl) {
    __shared__ float ts[32][33];
    int b = blockIdx.z;
    int t0 = blockIdx.x * 32, d0 = blockIdx.y * 32;
    int tx = threadIdx.x & 31, ty = threadIdx.x >> 5;
#pragma unroll
    for (int i = 0; i < 4; i++) {
        int t = ty * 4 + i;
        size_t o = ((size_t)b * Tt + t0 + t) * Dd + d0 + tx;
        float v = x[o];
        ts[t][tx] = v;
        bf16 h, l; split2(v, h, l);
        xh[o] = h; xl[o] = l;
    }
    __syncthreads();
#pragma unroll
    for (int i = 0; i < 4; i++) {
        int d = ty * 4 + i;
        float v = ts[tx][d];
        bf16 h, l; split2(v, h, l);
        size_t o = ((size_t)b * Dd + d0 + d) * Tt + t0 + tx;
        xth[o] = h; xtl[o] = l;
    }
}

// ---------------- three straight weight conversions in one launch ----------------
__global__ __launch_bounds__(256) void convw3_k(
    const float* __restrict__ Wq, bf16* __restrict__ Wqh, bf16* __restrict__ Wql,
    const float* __restrict__ Wv, bf16* __restrict__ Wvh, bf16* __restrict__ Wvl,
    const float* __restrict__ Wo, bf16* __restrict__ Woh, bf16* __restrict__ Wol) {
    const float* W; bf16 *Wh, *Wl;
    if (blockIdx.y == 0)      { W = Wq; Wh = Wqh; Wl = Wql; }
    else if (blockIdx.y == 1) { W = Wv; Wh = Wvh; Wl = Wvl; }
    else                      { W = Wo; Wh = Woh; Wl = Wol; }
    for (int i = blockIdx.x * 256 + threadIdx.x; i < Dd * Dd; i += gridDim.x * 256) {
        bf16 h, l; split2(W[i], h, l);
        Wh[i] = h; Wl[i] = l;
    }
}

// ---------------- weight fp32 -> transposed + scaled bf16 hi/lo ----------------
__global__ __launch_bounds__(256) void convwT_k(const float* __restrict__ W,
                                                bf16* __restrict__ Wh, bf16* __restrict__ Wl,
                                                float alpha) {
    __shared__ float ts[32][33];
    int r0 = blockIdx.x * 32, c0 = blockIdx.y * 32;
    int tx = threadIdx.x & 31, ty = threadIdx.x >> 5;
#pragma unroll
    for (int i = 0; i < 4; i++) {
        int r = ty * 4 + i;
        ts[r][tx] = W[(size_t)(r0 + r) * Dd + c0 + tx];
    }
    __syncthreads();
#pragma unroll
    for (int i = 0; i < 4; i++) {
        int c = ty * 4 + i;
        bf16 h, l; split2(alpha * ts[tx][c], h, l);
        size_t o = (size_t)(c0 + c) * Dd + r0 + tx;
        Wh[o] = h; Wl[o] = l;
    }
}

// ---------------- gather x rows at idx, split to bf16 hi/lo ----------------
__global__ __launch_bounds__(256) void gather_xs_k(bf16* __restrict__ xsh,
                                                   bf16* __restrict__ xsl,
                                                   const float4* __restrict__ x,
                                                   const int* __restrict__ idx, int u) {
    int b = blockIdx.x / u, j = blockIdx.x % u;
    int t = idx[j];
    float4 v = x[((size_t)b * Tt + t) * (Dd / 4) + threadIdx.x];
    size_t o = ((size_t)b * u + j) * Dd + threadIdx.x * 4;
    bf16 h, l;
    split2(v.x, h, l); xsh[o + 0] = h; xsl[o + 0] = l;
    split2(v.y, h, l); xsh[o + 1] = h; xsl[o + 1] = l;
    split2(v.z, h, l); xsh[o + 2] = h; xsl[o + 2] = l;
    split2(v.w, h, l); xsh[o + 3] = h; xsl[o + 3] = l;
}

// ---------------- split-K reduce (4-way) -> bf16 hi/lo ----------------
__global__ __launch_bounds__(256) void redsplit4_k(const float* __restrict__ p,
                                                   bf16* __restrict__ oh, bf16* __restrict__ ol,
                                                   int n, int stride) {
    for (int i = blockIdx.x * 256 + threadIdx.x; i < n; i += gridDim.x * 256) {
        float s = p[i] + p[i + stride] + p[i + 2 * stride] + p[i + 3 * stride];
        bf16 h, l; split2(s, h, l);
        oh[i] = h; ol[i] = l;
    }
}

// ---------------- split-K reduce (2-way) -> bf16 hi/lo ----------------
__global__ __launch_bounds__(256) void redsplit2_k(const float* __restrict__ p,
                                                   bf16* __restrict__ oh, bf16* __restrict__ ol,
                                                   int n, ll stride) {
    for (int i = blockIdx.x * 256 + threadIdx.x; i < n; i += gridDim.x * 256) {
        float s = p[i] + p[i + stride];
        bf16 h, l; split2(s, h, l);
        oh[i] = h; ol[i] = l;
    }
}

// ---------------- softmax: UNNORMALIZED exp hi/lo + row sums ----------------
__global__ __launch_bounds__(256) void softmax_k(const float* __restrict__ s,
                                                 bf16* __restrict__ ah, bf16* __restrict__ al,
                                                 float* __restrict__ rsum, int Hu, int mp) {
    __shared__ float red[256];
    int b = blockIdx.x / Hu, r = blockIdx.x % Hu;
    size_t base = ((size_t)b * mp + r) * Tt;
    int tid = threadIdx.x;
    float m = -3.4e38f;
    for (int t = tid; t < Tt; t += 256) m = fmaxf(m, s[base + t]);
    red[tid] = m; __syncthreads();
    for (int o = 128; o > 0; o >>= 1) {
        if (tid < o) red[tid] = fmaxf(red[tid], red[tid + o]);
        __syncthreads();
    }
    float mx = red[0];
    __syncthreads();
    float sum = 0.f;
    for (int t = tid; t < Tt; t += 256) {
        float e = __expf(s[base + t] - mx);
        sum += e;
        bf16 h, l; split2(e, h, l);
        ah[base + t] = h; al[base + t] = l;
    }
    red[tid] = sum; __syncthreads();
    for (int o = 128; o > 0; o >>= 1) {
        if (tid < o) red[tid] += red[tid + o];
        __syncthreads();
    }
    if (tid == 0) rsum[blockIdx.x] = red[0];
}

// ---------------- ctx -> per-token rows (normalized) + mean row, bf16 split ----------------
__global__ __launch_bounds__(64) void ctxrow_mean_k(bf16* __restrict__ crh,
                                                    bf16* __restrict__ crl,
                                                    const float* __restrict__ ctx,
                                                    const float* __restrict__ rsum,
                                                    int u, int Hu) {
    int b = blockIdx.x, h = blockIdx.y, d = threadIdx.x;
    float s = 0.f;
    for (int j = 0; j < u; j++) {
        float inv = 1.f / rsum[b * Hu + h * u + j];
        float v = ctx[((size_t)(b * Hh + h) * u + j) * DHh + d] * inv;
        bf16 hh, ll2; split2(v, hh, ll2);
        size_t o = ((size_t)b * (u + 1) + j) * Dd + h * DHh + d;
        crh[o] = hh; crl[o] = ll2;
        s += v;
    }
    bf16 hh, ll2; split2(s / (float)u, hh, ll2);
    size_t o = ((size_t)b * (u + 1) + u) * Dd + h * DHh + d;
    crh[o] = hh; crl[o] = ll2;
}

// ---------------- broadcast fill + scatter ----------------
__global__ __launch_bounds__(256) void fill_k(float4* __restrict__ y,
                                              const float4* __restrict__ ys,
                                              const float4* __restrict__ bo, int u) {
    int b = blockIdx.x / Tt;
    float4 v = ys[((size_t)b * (u + 1) + u) * 256 + threadIdx.x];
    float4 bb = bo[threadIdx.x];
    y[(size_t)blockIdx.x * 256 + threadIdx.x] =
        make_float4(v.x + bb.x, v.y + bb.y, v.z + bb.z, v.w + bb.w);
}
__global__ __launch_bounds__(256) void scatter_k(float4* __restrict__ y,
                                                 const float4* __restrict__ ys,
                                                 const float4* __restrict__ bo,
                                                 const int* __restrict__ idx, int u) {
    int b = blockIdx.x, j = blockIdx.y;
    int t = idx[j];
    float4 v = ys[((size_t)b * (u + 1) + j) * 256 + threadIdx.x];
    float4 bb = bo[threadIdx.x];
    y[((size_t)b * Tt + t) * 256 + threadIdx.x] =
        make_float4(v.x + bb.x, v.y + bb.y, v.z + bb.z, v.w + bb.w);
}

// ---------------- launch ----------------
extern "C" void kernel_launch(void* const* d_in, const int* in_sizes, int n_in,
                              void* d_out, int out_size) {
    const float* x  = (const float*)d_in[0];
    const float* Wq = (const float*)d_in[1];
    const float* Wk = (const float*)d_in[2];
    const float* Wv = (const float*)d_in[3];
    const float* Wo = (const float*)d_in[4];
    const float* bo = (const float*)d_in[5];
    const int* idx  = (const int*)d_in[6];
    int u = in_sizes[6];
    if (u > UMAX) u = UMAX;
    if (u < 1) u = 1;
    float* y = (float*)d_out;

    float *qsp, *sc, *rsum, *wxp, *ctx, *ys;
    bf16 *xsh, *xsl, *Wqh, *Wql, *WkTh, *WkTl, *Wvh, *Wvl, *Woh, *Wol;
    bf16 *Qsh, *Qsl, *Qth, *Qtl, *xh, *xl, *xth, *xtl, *ah, *al, *wxh, *wxl, *crh, *crl;
    cudaGetSymbolAddress((void**)&xsh,  g_xsh);
    cudaGetSymbolAddress((void**)&xsl,  g_xsl);
    cudaGetSymbolAddress((void**)&Wqh,  g_Wqh);
    cudaGetSymbolAddress((void**)&Wql,  g_Wql);
    cudaGetSymbolAddress((void**)&WkTh, g_WkTh);
    cudaGetSymbolAddress((void**)&WkTl, g_WkTl);
    cudaGetSymbolAddress((void**)&Wvh,  g_Wvh);
    cudaGetSymbolAddress((void**)&Wvl,  g_Wvl);
    cudaGetSymbolAddress((void**)&Woh,  g_Woh);
    cudaGetSymbolAddress((void**)&Wol,  g_Wol);
    cudaGetSymbolAddress((void**)&qsp,  g_qsp);
    cudaGetSymbolAddress((void**)&Qsh,  g_Qsh);
    cudaGetSymbolAddress((void**)&Qsl,  g_Qsl);
    cudaGetSymbolAddress((void**)&Qth,  g_Qth);
    cudaGetSymbolAddress((void**)&Qtl,  g_Qtl);
    cudaGetSymbolAddress((void**)&xh,   g_xh);
    cudaGetSymbolAddress((void**)&xl,   g_xl);
    cudaGetSymbolAddress((void**)&xth,  g_xth);
    cudaGetSymbolAddress((void**)&xtl,  g_xtl);
    cudaGetSymbolAddress((void**)&sc,   g_sc);
    cudaGetSymbolAddress((void**)&ah,   g_ah);
    cudaGetSymbolAddress((void**)&al,   g_al);
    cudaGetSymbolAddress((void**)&rsum, g_rsum);
    cudaGetSymbolAddress((void**)&wxp,  g_wxp);
    cudaGetSymbolAddress((void**)&wxh,  g_wxh);
    cudaGetSymbolAddress((void**)&wxl,  g_wxl);
    cudaGetSymbolAddress((void**)&ctx,  g_ctx);
    cudaGetSymbolAddress((void**)&crh,  g_crh);
    cudaGetSymbolAddress((void**)&crl,  g_crl);
    cudaGetSymbolAddress((void**)&ys,   g_ys);

    const int Hu = Hh * u;
    const int mp = ((Hu + 127) / 128) * 128;
    const int Bu = Bb * u;
    const int bup = ((Bu + 127) / 128) * 128;
    const float scale = 0.125f;

    const int smem_n = NSTAGE * (int)STG_SZ;   // 98304
    const int smem_w = 3 * (int)WSTG;          // 147456
    cudaFuncSetAttribute(mma_gemm_k<0>, cudaFuncAttributeMaxDynamicSharedMemorySize, smem_n);
    cudaFuncSetAttribute(mma_gemm_k<1>, cudaFuncAttributeMaxDynamicSharedMemorySize, smem_n);
    cudaFuncSetAttribute(mma_wide_k<0>, cudaFuncAttributeMaxDynamicSharedMemorySize, smem_w);
    cudaFuncSetAttribute(mma_wide_k<1>, cudaFuncAttributeMaxDynamicSharedMemorySize, smem_w);

    // 0) conversions
    convx_k<<<dim3(Tt / 32, Dd / 32, Bb), 256>>>(x, xh, xl, xth, xtl);
    convw3_k<<<dim3(256, 3), 256>>>(Wq, Wqh, Wql, Wv, Wvh, Wvl, Wo, Woh, Wol);
    convwT_k<<<dim3(32, 32), 256>>>(Wk, WkTh, WkTl, scale);

    // 1) gather+split x rows at idx
    gather_xs_k<<<Bb * u, 256>>>(xsh, xsl, (const float4*)x, idx, u);

    // 2) Qs partials = xs @ Wq^T   (narrow, split-K=4)
    mma_gemm_k<0><<<dim3(Dd / BNt, bup / BMt, 4), 256, smem_n>>>(
        qsp, nullptr, nullptr, xsh, xsl, Wqh, Wql,
        256, Dd, Dd, Dd, Bu, Dd,
        0, 0, 0, 0, 0, 0, 1, 4, (ll)bup * Dd);
    redsplit4_k<<<512, 256>>>(qsp, Qsh, Qsl, Bu * Dd, bup * Dd);

    // 3) Qt[b,h] = Qs[b](cols h*64..) @ (scale*Wk_h)  -> bf16 hi/lo padded
    mma_gemm_k<1><<<dim3(Dd / BNt, 1, Bb * Hh), 256, smem_n>>>(
        nullptr, Qth, Qtl, Qsh, Qsl, WkTh, WkTl,
        DHh, Dd, Dd, Dd, u, Dd,
        (ll)u * Dd, (ll)DHh, 0, (ll)DHh, (ll)mp * Dd, (ll)u * Dd, Hh, 1, 0);

    // 4) scores[b] = Qt[b] @ x[b]^T   (WIDE)
    mma_wide_k<0><<<dim3(Tt / 256, mp / 128, Bb), 256, smem_w>>>(
        sc, nullptr, nullptr, Qth, Qtl, xh, xl,
        Dd, Dd, Dd, Tt, mp, Tt,
        (ll)mp * Dd, (ll)Tt * Dd, (ll)mp * Tt, 1, 0);

    // 5) softmax -> unnormalized exp hi/lo + row sums
    softmax_k<<<Bb * Hu, 256>>>(sc, ah, al, rsum, Hu, mp);

    // 6) wx partials = e[b] @ x[b]   (WIDE, split-K=2, B = x^T layout)
    mma_wide_k<0><<<dim3(Dd / 256, mp / 128, Bb * 2), 256, smem_w>>>(
        wxp, nullptr, nullptr, ah, al, xth, xtl,
        Tt / 2, Tt, Tt, Dd, mp, Dd,
        (ll)mp * Tt, (ll)Dd * Tt, (ll)mp * Dd, 2, (ll)Bb * mp * Dd);
    redsplit2_k<<<1024, 256>>>(wxp, wxh, wxl, Bb * mp * Dd, (ll)Bb * mp * Dd);

    // 7) ctx[b,h] = wx[b,h] @ Wv_h^T   (narrow, fp32 out)
    mma_gemm_k<0><<<dim3(1, 1, Bb * Hh), 256, smem_n>>>(
        ctx, nullptr, nullptr, wxh, wxl, Wvh, Wvl,
        Dd, Dd, Dd, DHh, u, DHh,
        (ll)mp * Dd, (ll)u * Dd, 0, (ll)DHh * Dd, (ll)Hh * u * DHh, (ll)u * DHh, Hh, 1, 0);

    // 8) reorder ctx + normalize + mean row -> bf16 split
    ctxrow_mean_k<<<dim3(Bb, Hh), 64>>>(crh, crl, ctx, rsum, u, Hu);

    // 9) ys = cr @ Wo^T   (narrow, fp32 out)
    mma_gemm_k<0><<<dim3(Dd / BNt, 1, Bb), 256, smem_n>>>(
        ys, nullptr, nullptr, crh, crl, Woh, Wol,
        Dd, Dd, Dd, Dd, u + 1, Dd,
        (ll)(u + 1) * Dd, 0, 0, 0, (ll)(u + 1) * Dd, 0, 1, 1, 0);

    // 10) broadcast + scatter
    fill_k<<<Bb * Tt, 256>>>((float4*)y, (const float4*)ys, (const float4*)bo, u);
    scatter_k<<<dim3(Bb, u), 256>>>((float4*)y, (const float4*)ys, (const float4*)bo, idx, u);
}

// round 12
// speedup vs baseline: 1.2143x; 1.2143x over previous
#include <cuda_runtime.h>
#include <cuda_bf16.h>
#include <cstdint>

#define Bb   8
#define Tt   4096
#define Dd   1024
#define Hh   16
#define DHh  64
#define UMAX 64
#define MPMAX 1024
#define BUPMAX 512

typedef long long ll;
typedef __nv_bfloat16 bf16;

// ---------------- scratch (static __device__, allocation-free) ----------------
__device__ bf16  g_xsh[Bb * UMAX * Dd];
__device__ bf16  g_xsl[Bb * UMAX * Dd];
__device__ bf16  g_Wqh[Dd * Dd];
__device__ bf16  g_Wql[Dd * Dd];
__device__ bf16  g_WkTh[Dd * Dd];
__device__ bf16  g_WkTl[Dd * Dd];
__device__ bf16  g_Wvh[(Dd + 128) * Dd];     // row-padded for OOB-safe tile loads
__device__ bf16  g_Wvl[(Dd + 128) * Dd];
__device__ bf16  g_Woh[Dd * Dd];
__device__ bf16  g_Wol[Dd * Dd];
__device__ float g_qsp[4 * BUPMAX * Dd];     // step-2 split-K partials
__device__ bf16  g_Qsh[Bb * UMAX * Dd];
__device__ bf16  g_Qsl[Bb * UMAX * Dd];
__device__ bf16  g_Qth[(size_t)Bb * MPMAX * Dd];
__device__ bf16  g_Qtl[(size_t)Bb * MPMAX * Dd];
__device__ bf16  g_xh[(size_t)Bb * Tt * Dd];
__device__ bf16  g_xl[(size_t)Bb * Tt * Dd];
__device__ bf16  g_xth[(size_t)Bb * Dd * Tt];
__device__ bf16  g_xtl[(size_t)Bb * Dd * Tt];
__device__ float g_sc[(size_t)Bb * MPMAX * Tt];
__device__ bf16  g_ah[(size_t)Bb * MPMAX * Tt];
__device__ bf16  g_al[(size_t)Bb * MPMAX * Tt];
__device__ float g_rsum[Bb * Hh * UMAX];
__device__ float g_wxp[(size_t)2 * Bb * MPMAX * Dd];  // step-6 split-K partials
__device__ bf16  g_wxh[(size_t)Bb * MPMAX * Dd];
__device__ bf16  g_wxl[(size_t)Bb * MPMAX * Dd];
__device__ float g_ctx[Bb * Hh * UMAX * DHh];
__device__ bf16  g_crh[Bb * (UMAX + 2) * Dd];
__device__ bf16  g_crl[Bb * (UMAX + 2) * Dd];
__device__ float g_ys[Bb * (UMAX + 1) * Dd];

// ---------------- PTX helpers (sm_80/sm_90 portable only) ----------------
__device__ __forceinline__ uint32_t smem_u32(const void* p) {
    uint32_t a;
    asm("{ .reg .u64 t; cvta.to.shared.u64 t, %1; cvt.u32.u64 %0, t; }" : "=r"(a) : "l"(p));
    return a;
}
__device__ __forceinline__ void cp_async16(uint32_t s, const void* g) {
    asm volatile("cp.async.cg.shared.global [%0], [%1], 16;" :: "r"(s), "l"(g) : "memory");
}
__device__ __forceinline__ void ldsm_x4(uint32_t* r, uint32_t a) {
    asm volatile("ldmatrix.sync.aligned.m8n8.x4.shared.b16 {%0,%1,%2,%3}, [%4];"
                 : "=r"(r[0]), "=r"(r[1]), "=r"(r[2]), "=r"(r[3]) : "r"(a));
}
__device__ __forceinline__ void mma16816(float* c, const uint32_t* a, const uint32_t* b) {
    asm volatile(
        "mma.sync.aligned.m16n8k16.row.col.f32.bf16.bf16.f32 "
        "{%0,%1,%2,%3}, {%4,%5,%6,%7}, {%8,%9}, {%0,%1,%2,%3};"
        : "+f"(c[0]), "+f"(c[1]), "+f"(c[2]), "+f"(c[3])
        : "r"(a[0]), "r"(a[1]), "r"(a[2]), "r"(a[3]), "r"(b[0]), "r"(b[1]));
}

__device__ __forceinline__ void split2(float v, bf16& h, bf16& l) {
    h = __float2bfloat16(v);
    l = __float2bfloat16(v - __bfloat162float(h));
}

// ============ narrow merged-pass warp-MMA GEMM (all GEMM steps) ============
// C = 3-term split(A) @ split(B)^T  (AhBh + AhBl + AlBh, fp32 acc).
// Block 128x128, BK=32, 8 warps (2x4), warp tile 64x32, 3-stage cp.async, 2 CTA/SM.
#define BMt 128
#define BNt 128
#define STG_SZ 32768u
#define NSTAGE 3

template <int EPI>
__global__ __launch_bounds__(256, 2) void mma_gemm_k(
    float* __restrict__ C, bf16* __restrict__ Ch, bf16* __restrict__ Cl,
    const bf16* __restrict__ Ah, const bf16* __restrict__ Al,
    const bf16* __restrict__ Bh, const bf16* __restrict__ Bl,
    int Kext, int lda, int ldb, int ldc, int Mreal, int Nreal,
    ll sAb, ll sAh, ll sBb, ll sBh, ll sCb, ll sCh,
    int nh, int KS, ll sCs) {
    extern __shared__ char smem[];
    uint32_t sbase = smem_u32(smem);
    int tid = threadIdx.x, wid = tid >> 5, lane = tid & 31;
    int z = blockIdx.z;
    int ks = z % KS, bh2 = z / KS;
    int hh = bh2 % nh, bb = bh2 / nh;
    int m0 = blockIdx.y * BMt, n0 = blockIdx.x * BNt;

    const bf16* A0 = Ah + bb * sAb + hh * sAh + (ll)ks * Kext + (size_t)m0 * lda;
    const bf16* A1 = Al + bb * sAb + hh * sAh + (ll)ks * Kext + (size_t)m0 * lda;
    const bf16* B0 = Bh + bb * sBb + hh * sBh + (ll)ks * Kext + (size_t)n0 * ldb;
    const bf16* B1 = Bl + bb * sBb + hh * sBh + (ll)ks * Kext + (size_t)n0 * ldb;

    int row = tid >> 1, cq = tid & 1, rx = row & 7;
    size_t   gA0 = (size_t)row * lda + cq * 8, gA1 = gA0 + 16;
    size_t   gB0 = (size_t)row * ldb + cq * 8, gB1 = gB0 + 16;
    uint32_t dh0 = row * 128 + ((cq)     ^ rx) * 16;
    uint32_t dh1 = row * 128 + ((cq + 2) ^ rx) * 16;
    uint32_t dl0 = row * 128 + ((cq + 4) ^ rx) * 16;
    uint32_t dl1 = row * 128 + ((cq + 6) ^ rx) * 16;

    int warp_m = wid >> 2, warp_n = wid & 3;
    int rl = lane & 15, cl = lane >> 4, arx = lane & 7;
    int rb = lane & 7,  cb = (lane >> 3) & 1;
    uint32_t arow[4], b4row[2];
#pragma unroll
    for (int i = 0; i < 4; i++) arow[i] = (warp_m * 64 + i * 16 + rl) * 128;
    // x4 B loads: lanes 0-15 -> j-group 2*j2 (k-lo/k-hi), lanes 16-31 -> j-group 2*j2+1
#pragma unroll
    for (int j2 = 0; j2 < 2; j2++)
        b4row[j2] = (warp_n * 32 + (j2 * 2 + (lane >> 4)) * 8 + rb) * 128;

    float acc[4][4][4];
#pragma unroll
    for (int i = 0; i < 4; i++)
#pragma unroll
        for (int j = 0; j < 4; j++)
#pragma unroll
            for (int q = 0; q < 4; q++) acc[i][j][q] = 0.f;

    const int NC = Kext >> 5;

#define ISSUE(c_) do {                                                        \
    size_t ko_ = (size_t)(c_) * 32;                                           \
    uint32_t st_ = sbase + ((c_) % NSTAGE) * STG_SZ;                          \
    cp_async16(st_ + dh0, A0 + ko_ + gA0);                                    \
    cp_async16(st_ + dh1, A0 + ko_ + gA1);                                    \
    cp_async16(st_ + dl0, A1 + ko_ + gA0);                                    \
    cp_async16(st_ + dl1, A1 + ko_ + gA1);                                    \
    cp_async16(st_ + 16384u + dh0, B0 + ko_ + gB0);                           \
    cp_async16(st_ + 16384u + dh1, B0 + ko_ + gB1);                           \
    cp_async16(st_ + 16384u + dl0, B1 + ko_ + gB0);                           \
    cp_async16(st_ + 16384u + dl1, B1 + ko_ + gB1);                           \
    asm volatile("cp.async.commit_group;" ::: "memory");                      \
} while (0)

    ISSUE(0);
    if (NC > 1) ISSUE(1);

    for (int c = 0; c < NC; c++) {
        if (c + 1 < NC) asm volatile("cp.async.wait_group 1;" ::: "memory");
        else            asm volatile("cp.async.wait_group 0;" ::: "memory");
        __syncthreads();
        if (c + 2 < NC) ISSUE(c + 2);

        uint32_t sa = sbase + (c % NSTAGE) * STG_SZ;
        uint32_t sb = sa + 16384u;
#pragma unroll
        for (int kk = 0; kk < 2; kk++) {
            uint32_t bh[4][2], blo[4][2], af[4][4];
#pragma unroll
            for (int j2 = 0; j2 < 2; j2++)
                ldsm_x4(&bh[j2 * 2][0],  sb + b4row[j2] + (((kk * 2 + cb)     ^ rb) << 4));
#pragma unroll
            for (int j2 = 0; j2 < 2; j2++)
                ldsm_x4(&blo[j2 * 2][0], sb + b4row[j2] + (((kk * 2 + cb + 4) ^ rb) << 4));
#pragma unroll
            for (int i = 0; i < 4; i++)
                ldsm_x4(af[i], sa + arow[i] + (((kk * 2 + cl)     ^ arx) << 4));
#pragma unroll
            for (int i = 0; i < 4; i++)
#pragma unroll
                for (int j = 0; j < 4; j++) mma16816(acc[i][j], af[i], bh[j]);
#pragma unroll
            for (int i = 0; i < 4; i++)
#pragma unroll
                for (int j = 0; j < 4; j++) mma16816(acc[i][j], af[i], blo[j]);
#pragma unroll
            for (int i = 0; i < 4; i++)
                ldsm_x4(af[i], sa + arow[i] + (((kk * 2 + cl + 4) ^ arx) << 4));
#pragma unroll
            for (int i = 0; i < 4; i++)
#pragma unroll
                for (int j = 0; j < 4; j++) mma16816(acc[i][j], af[i], bh[j]);
        }
        __syncthreads();
    }

    ll cbase = bb * sCb + hh * sCh + (ll)ks * sCs;
#pragma unroll
    for (int i = 0; i < 4; i++) {
        int m = m0 + warp_m * 64 + i * 16 + (lane >> 2);
#pragma unroll
        for (int j = 0; j < 4; j++) {
            int n = n0 + warp_n * 32 + j * 8 + (lane & 3) * 2;
            if (n < Nreal) {
#pragma unroll
                for (int p = 0; p < 2; p++) {
                    int mm = m + p * 8;
                    if (mm < Mreal) {
                        if (EPI == 0) {
                            *(float2*)&C[cbase + (size_t)mm * ldc + n] =
                                make_float2(acc[i][j][p * 2], acc[i][j][p * 2 + 1]);
                        } else {
                            bf16 h0, l0, h1, l1;
                            split2(acc[i][j][p * 2], h0, l0);
                            split2(acc[i][j][p * 2 + 1], h1, l1);
                            __nv_bfloat162 hp, lp;
                            hp.x = h0; hp.y = h1; lp.x = l0; lp.y = l1;
                            *(__nv_bfloat162*)&Ch[cbase + (size_t)mm * ldc + n] = hp;
                            *(__nv_bfloat162*)&Cl[cbase + (size_t)mm * ldc + n] = lp;
                        }
                    }
                }
            }
        }
    }
}

// ---------------- x -> bf16 hi/lo (straight + transposed) ----------------
__global__ __launch_bounds__(256) void convx_k(const float* __restrict__ x,
                                               bf16* __restrict__ xh, bf16* __restrict__ xl,
                                               bf16* __restrict__ xth, bf16* __restrict__ xtl) {
    __shared__ float ts[32][33];
    int b = blockIdx.z;
    int t0 = blockIdx.x * 32, d0 = blockIdx.y * 32;
    int tx = threadIdx.x & 31, ty = threadIdx.x >> 5;
#pragma unroll
    for (int i = 0; i < 4; i++) {
        int t = ty * 4 + i;
        size_t o = ((size_t)b * Tt + t0 + t) * Dd + d0 + tx;
        float v = x[o];
        ts[t][tx] = v;
        bf16 h, l; split2(v, h, l);
        xh[o] = h; xl[o] = l;
    }
    __syncthreads();
#pragma unroll
    for (int i = 0; i < 4; i++) {
        int d = ty * 4 + i;
        float v = ts[tx][d];
        bf16 h, l; split2(v, h, l);
        size_t o = ((size_t)b * Dd + d0 + d) * Tt + t0 + tx;
        xth[o] = h; xtl[o] = l;
    }
}

// ---------------- three straight weight conversions in one launch ----------------
__global__ __launch_bounds__(256) void convw3_k(
    const float* __restrict__ Wq, bf16* __restrict__ Wqh, bf16* __restrict__ Wql,
    const float* __restrict__ Wv, bf16* __restrict__ Wvh, bf16* __restrict__ Wvl,
    const float* __restrict__ Wo, bf16* __restrict__ Woh, bf16* __restrict__ Wol) {
    const float* W; bf16 *Wh, *Wl;
    if (blockIdx.y == 0)      { W = Wq; Wh = Wqh; Wl = Wql; }
    else if (blockIdx.y == 1) { W = Wv; Wh = Wvh; Wl = Wvl; }
    else                      { W = Wo; Wh = Woh; Wl = Wol; }
    for (int i = blockIdx.x * 256 + threadIdx.x; i < Dd * Dd; i += gridDim.x * 256) {
        bf16 h, l; split2(W[i], h, l);
        Wh[i] = h; Wl[i] = l;
    }
}

// ---------------- weight fp32 -> transposed + scaled bf16 hi/lo ----------------
__global__ __launch_bounds__(256) void convwT_k(const float* __restrict__ W,
                                                bf16* __restrict__ Wh, bf16* __restrict__ Wl,
                                                float alpha) {
    __shared__ float ts[32][33];
    int r0 = blockIdx.x * 32, c0 = blockIdx.y * 32;
    int tx = threadIdx.x & 31, ty = threadIdx.x >> 5;
#pragma unroll
    for (int i = 0; i < 4; i++) {
        int r = ty * 4 + i;
        ts[r][tx] = W[(size_t)(r0 + r) * Dd + c0 + tx];
    }
    __syncthreads();
#pragma unroll
    for (int i = 0; i < 4; i++) {
        int c = ty * 4 + i;
        bf16 h, l; split2(alpha * ts[tx][c], h, l);
        size_t o = (size_t)(c0 + c) * Dd + r0 + tx;
        Wh[o] = h; Wl[o] = l;
    }
}

// ---------------- gather x rows at idx, split to bf16 hi/lo ----------------
__global__ __launch_bounds__(256) void gather_xs_k(bf16* __restrict__ xsh,
                                                   bf16* __restrict__ xsl,
                                                   const float4* __restrict__ x,
                                                   const int* __restrict__ idx, int u) {
    int b = blockIdx.x / u, j = blockIdx.x % u;
    int t = idx[j];
    float4 v = x[((size_t)b * Tt + t) * (Dd / 4) + threadIdx.x];
    size_t o = ((size_t)b * u + j) * Dd + threadIdx.x * 4;
    bf16 h, l;
    split2(v.x, h, l); xsh[o + 0] = h; xsl[o + 0] = l;
    split2(v.y, h, l); xsh[o + 1] = h; xsl[o + 1] = l;
    split2(v.z, h, l); xsh[o + 2] = h; xsl[o + 2] = l;
    split2(v.w, h, l); xsh[o + 3] = h; xsl[o + 3] = l;
}

// ---------------- split-K reduce (4-way) -> bf16 hi/lo ----------------
__global__ __launch_bounds__(256) void redsplit4_k(const float* __restrict__ p,
                                                   bf16* __restrict__ oh, bf16* __restrict__ ol,
                                                   int n, int stride) {
    for (int i = blockIdx.x * 256 + threadIdx.x; i < n; i += gridDim.x * 256) {
        float s = p[i] + p[i + stride] + p[i + 2 * stride] + p[i + 3 * stride];
        bf16 h, l; split2(s, h, l);
        oh[i] = h; ol[i] = l;
    }
}

// ---------------- split-K reduce (2-way) -> bf16 hi/lo ----------------
__global__ __launch_bounds__(256) void redsplit2_k(const float* __restrict__ p,
                                                   bf16* __restrict__ oh, bf16* __restrict__ ol,
                                                   int n, ll stride) {
    for (int i = blockIdx.x * 256 + threadIdx.x; i < n; i += gridDim.x * 256) {
        float s = p[i] + p[i + stride];
        bf16 h, l; split2(s, h, l);
        oh[i] = h; ol[i] = l;
    }
}

// ---------------- softmax: UNNORMALIZED exp hi/lo + row sums ----------------
__global__ __launch_bounds__(256) void softmax_k(const float* __restrict__ s,
                                                 bf16* __restrict__ ah, bf16* __restrict__ al,
                                                 float* __restrict__ rsum, int Hu, int mp) {
    __shared__ float red[256];
    int b = blockIdx.x / Hu, r = blockIdx.x % Hu;
    size_t base = ((size_t)b * mp + r) * Tt;
    int tid = threadIdx.x;
    float m = -3.4e38f;
    for (int t = tid; t < Tt; t += 256) m = fmaxf(m, s[base + t]);
    red[tid] = m; __syncthreads();
    for (int o = 128; o > 0; o >>= 1) {
        if (tid < o) red[tid] = fmaxf(red[tid], red[tid + o]);
        __syncthreads();
    }
    float mx = red[0];
    __syncthreads();
    float sum = 0.f;
    for (int t = tid; t < Tt; t += 256) {
        float e = __expf(s[base + t] - mx);
        sum += e;
        bf16 h, l; split2(e, h, l);
        ah[base + t] = h; al[base + t] = l;
    }
    red[tid] = sum; __syncthreads();
    for (int o = 128; o > 0; o >>= 1) {
        if (tid < o) red[tid] += red[tid + o];
        __syncthreads();
    }
    if (tid == 0) rsum[blockIdx.x] = red[0];
}

// ---------------- ctx -> per-token rows (normalized) + mean row, bf16 split ----------------
__global__ __launch_bounds__(64) void ctxrow_mean_k(bf16* __restrict__ crh,
                                                    bf16* __restrict__ crl,
                                                    const float* __restrict__ ctx,
                                                    const float* __restrict__ rsum,
                                                    int u, int Hu) {
    int b = blockIdx.x, h = blockIdx.y, d = threadIdx.x;
    float s = 0.f;
    for (int j = 0; j < u; j++) {
        float inv = 1.f / rsum[b * Hu + h * u + j];
        float v = ctx[((size_t)(b * Hh + h) * u + j) * DHh + d] * inv;
        bf16 hh, ll2; split2(v, hh, ll2);
        size_t o = ((size_t)b * (u + 1) + j) * Dd + h * DHh + d;
        crh[o] = hh; crl[o] = ll2;
        s += v;
    }
    bf16 hh, ll2; split2(s / (float)u, hh, ll2);
    size_t o = ((size_t)b * (u + 1) + u) * Dd + h * DHh + d;
    crh[o] = hh; crl[o] = ll2;
}

// ---------------- broadcast fill + scatter ----------------
__global__ __launch_bounds__(256) void fill_k(float4* __restrict__ y,
                                              const float4* __restrict__ ys,
                                              const float4* __restrict__ bo, int u) {
    int b = blockIdx.x / Tt;
    float4 v = ys[((size_t)b * (u + 1) + u) * 256 + threadIdx.x];
    float4 bb = bo[threadIdx.x];
    y[(size_t)blockIdx.x * 256 + threadIdx.x] =
        make_float4(v.x + bb.x, v.y + bb.y, v.z + bb.z, v.w + bb.w);
}
__global__ __launch_bounds__(256) void scatter_k(float4* __restrict__ y,
                                                 const float4* __restrict__ ys,
                                                 const float4* __restrict__ bo,
                                                 const int* __restrict__ idx, int u) {
    int b = blockIdx.x, j = blockIdx.y;
    int t = idx[j];
    float4 v = ys[((size_t)b * (u + 1) + j) * 256 + threadIdx.x];
    float4 bb = bo[threadIdx.x];
    y[((size_t)b * Tt + t) * 256 + threadIdx.x] =
        make_float4(v.x + bb.x, v.y + bb.y, v.z + bb.z, v.w + bb.w);
}

// ---------------- launch ----------------
extern "C" void kernel_launch(void* const* d_in, const int* in_sizes, int n_in,
                              void* d_out, int out_size) {
    const float* x  = (const float*)d_in[0];
    const float* Wq = (const float*)d_in[1];
    const float* Wk = (const float*)d_in[2];
    const float* Wv = (const float*)d_in[3];
    const float* Wo = (const float*)d_in[4];
    const float* bo = (const float*)d_in[5];
    const int* idx  = (const int*)d_in[6];
    int u = in_sizes[6];
    if (u > UMAX) u = UMAX;
    if (u < 1) u = 1;
    float* y = (float*)d_out;

    float *qsp, *sc, *rsum, *wxp, *ctx, *ys;
    bf16 *xsh, *xsl, *Wqh, *Wql, *WkTh, *WkTl, *Wvh, *Wvl, *Woh, *Wol;
    bf16 *Qsh, *Qsl, *Qth, *Qtl, *xh, *xl, *xth, *xtl, *ah, *al, *wxh, *wxl, *crh, *crl;
    cudaGetSymbolAddress((void**)&xsh,  g_xsh);
    cudaGetSymbolAddress((void**)&xsl,  g_xsl);
    cudaGetSymbolAddress((void**)&Wqh,  g_Wqh);
    cudaGetSymbolAddress((void**)&Wql,  g_Wql);
    cudaGetSymbolAddress((void**)&WkTh, g_WkTh);
    cudaGetSymbolAddress((void**)&WkTl, g_WkTl);
    cudaGetSymbolAddress((void**)&Wvh,  g_Wvh);
    cudaGetSymbolAddress((void**)&Wvl,  g_Wvl);
    cudaGetSymbolAddress((void**)&Woh,  g_Woh);
    cudaGetSymbolAddress((void**)&Wol,  g_Wol);
    cudaGetSymbolAddress((void**)&qsp,  g_qsp);
    cudaGetSymbolAddress((void**)&Qsh,  g_Qsh);
    cudaGetSymbolAddress((void**)&Qsl,  g_Qsl);
    cudaGetSymbolAddress((void**)&Qth,  g_Qth);
    cudaGetSymbolAddress((void**)&Qtl,  g_Qtl);
    cudaGetSymbolAddress((void**)&xh,   g_xh);
    cudaGetSymbolAddress((void**)&xl,   g_xl);
    cudaGetSymbolAddress((void**)&xth,  g_xth);
    cudaGetSymbolAddress((void**)&xtl,  g_xtl);
    cudaGetSymbolAddress((void**)&sc,   g_sc);
    cudaGetSymbolAddress((void**)&ah,   g_ah);
    cudaGetSymbolAddress((void**)&al,   g_al);
    cudaGetSymbolAddress((void**)&rsum, g_rsum);
    cudaGetSymbolAddress((void**)&wxp,  g_wxp);
    cudaGetSymbolAddress((void**)&wxh,  g_wxh);
    cudaGetSymbolAddress((void**)&wxl,  g_wxl);
    cudaGetSymbolAddress((void**)&ctx,  g_ctx);
    cudaGetSymbolAddress((void**)&crh,  g_crh);
    cudaGetSymbolAddress((void**)&crl,  g_crl);
    cudaGetSymbolAddress((void**)&ys,   g_ys);

    const int Hu = Hh * u;
    const int mp = ((Hu + 127) / 128) * 128;
    const int Bu = Bb * u;
    const int bup = ((Bu + 127) / 128) * 128;
    const float scale = 0.125f;

    const int smem_n = NSTAGE * (int)STG_SZ;   // 98304
    cudaFuncSetAttribute(mma_gemm_k<0>, cudaFuncAttributeMaxDynamicSharedMemorySize, smem_n);
    cudaFuncSetAttribute(mma_gemm_k<1>, cudaFuncAttributeMaxDynamicSharedMemorySize, smem_n);

    // 0) conversions
    convx_k<<<dim3(Tt / 32, Dd / 32, Bb), 256>>>(x, xh, xl, xth, xtl);
    convw3_k<<<dim3(256, 3), 256>>>(Wq, Wqh, Wql, Wv, Wvh, Wvl, Wo, Woh, Wol);
    convwT_k<<<dim3(32, 32), 256>>>(Wk, WkTh, WkTl, scale);

    // 1) gather+split x rows at idx
    gather_xs_k<<<Bb * u, 256>>>(xsh, xsl, (const float4*)x, idx, u);

    // 2) Qs partials = xs @ Wq^T   (split-K=4)
    mma_gemm_k<0><<<dim3(Dd / BNt, bup / BMt, 4), 256, smem_n>>>(
        qsp, nullptr, nullptr, xsh, xsl, Wqh, Wql,
        256, Dd, Dd, Dd, Bu, Dd,
        0, 0, 0, 0, 0, 0, 1, 4, (ll)bup * Dd);
    redsplit4_k<<<512, 256>>>(qsp, Qsh, Qsl, Bu * Dd, bup * Dd);

    // 3) Qt[b,h] = Qs[b](cols h*64..) @ (scale*Wk_h)  -> bf16 hi/lo padded
    mma_gemm_k<1><<<dim3(Dd / BNt, 1, Bb * Hh), 256, smem_n>>>(
        nullptr, Qth, Qtl, Qsh, Qsl, WkTh, WkTl,
        DHh, Dd, Dd, Dd, u, Dd,
        (ll)u * Dd, (ll)DHh, 0, (ll)DHh, (ll)mp * Dd, (ll)u * Dd, Hh, 1, 0);

    // 4) scores[b] = Qt[b] @ x[b]^T
    mma_gemm_k<0><<<dim3(Tt / BNt, mp / BMt, Bb), 256, smem_n>>>(
        sc, nullptr, nullptr, Qth, Qtl, xh, xl,
        Dd, Dd, Dd, Tt, mp, Tt,
        (ll)mp * Dd, 0, (ll)Tt * Dd, 0, (ll)mp * Tt, 0, 1, 1, 0);

    // 5) softmax -> unnormalized exp hi/lo + row sums
    softmax_k<<<Bb * Hu, 256>>>(sc, ah, al, rsum, Hu, mp);

    // 6) wx partials = e[b] @ x[b]   (split-K=2, B = x^T layout)
    mma_gemm_k<0><<<dim3(Dd / BNt, mp / BMt, Bb * 2), 256, smem_n>>>(
        wxp, nullptr, nullptr, ah, al, xth, xtl,
        Tt / 2, Tt, Tt, Dd, mp, Dd,
        (ll)mp * Tt, 0, (ll)Dd * Tt, 0, (ll)mp * Dd, 0, 1, 2, (ll)Bb * mp * Dd);
    redsplit2_k<<<1024, 256>>>(wxp, wxh, wxl, Bb * mp * Dd, (ll)Bb * mp * Dd);

    // 7) ctx[b,h] = wx[b,h] @ Wv_h^T   (fp32 out)
    mma_gemm_k<0><<<dim3(1, 1, Bb * Hh), 256, smem_n>>>(
        ctx, nullptr, nullptr, wxh, wxl, Wvh, Wvl,
        Dd, Dd, Dd, DHh, u, DHh,
        (ll)mp * Dd, (ll)u * Dd, 0, (ll)DHh * Dd, (ll)Hh * u * DHh, (ll)u * DHh, Hh, 1, 0);

    // 8) reorder ctx + normalize + mean row -> bf16 split
    ctxrow_mean_k<<<dim3(Bb, Hh), 64>>>(crh, crl, ctx, rsum, u, Hu);

    // 9) ys = cr @ Wo^T   (fp32 out)
    mma_gemm_k<0><<<dim3(Dd / BNt, 1, Bb), 256, smem_n>>>(
        ys, nullptr, nullptr, crh, crl, Woh, Wol,
        Dd, Dd, Dd, Dd, u + 1, Dd,
        (ll)(u + 1) * Dd, 0, 0, 0, (ll)(u + 1) * Dd, 0, 1, 1, 0);

    // 10) broadcast + scatter
    fill_k<<<Bb * Tt, 256>>>((float4*)y, (const float4*)ys, (const float4*)bo, u);
    scatter_k<<<dim3(Bb, u), 256>>>((float4*)y, (const float4*)ys, (const float4*)bo, idx, u);
}

// round 13
// speedup vs baseline: 1.2762x; 1.0510x over previous
#include <cuda_runtime.h>
#include <cuda_bf16.h>
#include <cstdint>

#define Bb   8
#define Tt   4096
#define Dd   1024
#define Hh   16
#define DHh  64
#define UMAX 64
#define MPMAX 1024
#define BUPMAX 512

typedef long long ll;
typedef __nv_bfloat16 bf16;

// ---------------- scratch (static __device__, allocation-free) ----------------
__device__ bf16  g_xsh[Bb * UMAX * Dd];
__device__ bf16  g_xsl[Bb * UMAX * Dd];
__device__ bf16  g_Wqh[Dd * Dd];
__device__ bf16  g_Wql[Dd * Dd];
__device__ bf16  g_WkTh[Dd * Dd];
__device__ bf16  g_WkTl[Dd * Dd];
__device__ bf16  g_Wvh[(Dd + 128) * Dd];     // row-padded for OOB-safe tile loads
__device__ bf16  g_Wvl[(Dd + 128) * Dd];
__device__ bf16  g_Woh[Dd * Dd];
__device__ bf16  g_Wol[Dd * Dd];
__device__ float g_qsp[4 * BUPMAX * Dd];     // step-2 split-K partials
__device__ bf16  g_Qsh[Bb * UMAX * Dd];
__device__ bf16  g_Qsl[Bb * UMAX * Dd];
__device__ bf16  g_Qth[(size_t)Bb * MPMAX * Dd];
__device__ bf16  g_Qtl[(size_t)Bb * MPMAX * Dd];
__device__ bf16  g_xh[(size_t)Bb * Tt * Dd];
__device__ bf16  g_xl[(size_t)Bb * Tt * Dd];
__device__ bf16  g_xth[(size_t)Bb * Dd * Tt];
__device__ bf16  g_xtl[(size_t)Bb * Dd * Tt];
__device__ float g_sc[(size_t)Bb * MPMAX * Tt];
__device__ bf16  g_ah[(size_t)Bb * MPMAX * Tt];
__device__ bf16  g_al[(size_t)Bb * MPMAX * Tt];
__device__ float g_rsum[Bb * Hh * UMAX];
__device__ float g_wxp[(size_t)2 * Bb * MPMAX * Dd];  // step-6 split-K partials
__device__ bf16  g_wxh[(size_t)Bb * MPMAX * Dd];
__device__ bf16  g_wxl[(size_t)Bb * MPMAX * Dd];
__device__ float g_ctx[Bb * Hh * UMAX * DHh];
__device__ bf16  g_crh[Bb * (UMAX + 2) * Dd];
__device__ bf16  g_crl[Bb * (UMAX + 2) * Dd];
__device__ float g_ys[Bb * (UMAX + 1) * Dd];

// ---------------- PTX helpers (sm_80/sm_90 portable only) ----------------
__device__ __forceinline__ uint32_t smem_u32(const void* p) {
    uint32_t a;
    asm("{ .reg .u64 t; cvta.to.shared.u64 t, %1; cvt.u32.u64 %0, t; }" : "=r"(a) : "l"(p));
    return a;
}
__device__ __forceinline__ void cp_async16(uint32_t s, const void* g) {
    asm volatile("cp.async.cg.shared.global [%0], [%1], 16;" :: "r"(s), "l"(g) : "memory");
}
__device__ __forceinline__ void ldsm_x4(uint32_t* r, uint32_t a) {
    asm volatile("ldmatrix.sync.aligned.m8n8.x4.shared.b16 {%0,%1,%2,%3}, [%4];"
                 : "=r"(r[0]), "=r"(r[1]), "=r"(r[2]), "=r"(r[3]) : "r"(a));
}
__device__ __forceinline__ void mma16816(float* c, const uint32_t* a, const uint32_t* b) {
    asm volatile(
        "mma.sync.aligned.m16n8k16.row.col.f32.bf16.bf16.f32 "
        "{%0,%1,%2,%3}, {%4,%5,%6,%7}, {%8,%9}, {%0,%1,%2,%3};"
        : "+f"(c[0]), "+f"(c[1]), "+f"(c[2]), "+f"(c[3])
        : "r"(a[0]), "r"(a[1]), "r"(a[2]), "r"(a[3]), "r"(b[0]), "r"(b[1]));
}

__device__ __forceinline__ void split2(float v, bf16& h, bf16& l) {
    h = __float2bfloat16(v);
    l = __float2bfloat16(v - __bfloat162float(h));
}
__device__ __forceinline__ __nv_bfloat162 pack2h(float a, float b) {
    bf16 h0, l0, h1, l1; split2(a, h0, l0); split2(b, h1, l1);
    __nv_bfloat162 r; r.x = h0; r.y = h1; return r;
}
__device__ __forceinline__ void packpair(float a, float b,
                                         __nv_bfloat162& hp, __nv_bfloat162& lp) {
    bf16 h0, l0, h1, l1; split2(a, h0, l0); split2(b, h1, l1);
    hp.x = h0; hp.y = h1; lp.x = l0; lp.y = l1;
}

// ============ narrow merged-pass warp-MMA GEMM (all GEMM steps) ============
// C = 3-term split(A) @ split(B)^T  (AhBh + AhBl + AlBh, fp32 acc).
// Block 128x128, BK=32, 8 warps (2x4), warp tile 64x32, 3-stage cp.async, 2 CTA/SM.
#define BMt 128
#define BNt 128
#define STG_SZ 32768u
#define NSTAGE 3

template <int EPI>
__global__ __launch_bounds__(256, 2) void mma_gemm_k(
    float* __restrict__ C, bf16* __restrict__ Ch, bf16* __restrict__ Cl,
    const bf16* __restrict__ Ah, const bf16* __restrict__ Al,
    const bf16* __restrict__ Bh, const bf16* __restrict__ Bl,
    int Kext, int lda, int ldb, int ldc, int Mreal, int Nreal,
    ll sAb, ll sAh, ll sBb, ll sBh, ll sCb, ll sCh,
    int nh, int KS, ll sCs) {
    extern __shared__ char smem[];
    uint32_t sbase = smem_u32(smem);
    int tid = threadIdx.x, wid = tid >> 5, lane = tid & 31;
    int z = blockIdx.z;
    int ks = z % KS, bh2 = z / KS;
    int hh = bh2 % nh, bb = bh2 / nh;
    int m0 = blockIdx.y * BMt, n0 = blockIdx.x * BNt;

    const bf16* A0 = Ah + bb * sAb + hh * sAh + (ll)ks * Kext + (size_t)m0 * lda;
    const bf16* A1 = Al + bb * sAb + hh * sAh + (ll)ks * Kext + (size_t)m0 * lda;
    const bf16* B0 = Bh + bb * sBb + hh * sBh + (ll)ks * Kext + (size_t)n0 * ldb;
    const bf16* B1 = Bl + bb * sBb + hh * sBh + (ll)ks * Kext + (size_t)n0 * ldb;

    int row = tid >> 1, cq = tid & 1, rx = row & 7;
    size_t   gA0 = (size_t)row * lda + cq * 8, gA1 = gA0 + 16;
    size_t   gB0 = (size_t)row * ldb + cq * 8, gB1 = gB0 + 16;
    uint32_t dh0 = row * 128 + ((cq)     ^ rx) * 16;
    uint32_t dh1 = row * 128 + ((cq + 2) ^ rx) * 16;
    uint32_t dl0 = row * 128 + ((cq + 4) ^ rx) * 16;
    uint32_t dl1 = row * 128 + ((cq + 6) ^ rx) * 16;

    int warp_m = wid >> 2, warp_n = wid & 3;
    int rl = lane & 15, cl = lane >> 4, arx = lane & 7;
    int rb = lane & 7,  cb = (lane >> 3) & 1;
    uint32_t arow[4], b4row[2];
#pragma unroll
    for (int i = 0; i < 4; i++) arow[i] = (warp_m * 64 + i * 16 + rl) * 128;
    // x4 B loads: lanes 0-15 -> j-group 2*j2, lanes 16-31 -> j-group 2*j2+1
#pragma unroll
    for (int j2 = 0; j2 < 2; j2++)
        b4row[j2] = (warp_n * 32 + (j2 * 2 + (lane >> 4)) * 8 + rb) * 128;

    float acc[4][4][4];
#pragma unroll
    for (int i = 0; i < 4; i++)
#pragma unroll
        for (int j = 0; j < 4; j++)
#pragma unroll
            for (int q = 0; q < 4; q++) acc[i][j][q] = 0.f;

    const int NC = Kext >> 5;

#define ISSUE(c_) do {                                                        \
    size_t ko_ = (size_t)(c_) * 32;                                           \
    uint32_t st_ = sbase + ((c_) % NSTAGE) * STG_SZ;                          \
    cp_async16(st_ + dh0, A0 + ko_ + gA0);                                    \
    cp_async16(st_ + dh1, A0 + ko_ + gA1);                                    \
    cp_async16(st_ + dl0, A1 + ko_ + gA0);                                    \
    cp_async16(st_ + dl1, A1 + ko_ + gA1);                                    \
    cp_async16(st_ + 16384u + dh0, B0 + ko_ + gB0);                           \
    cp_async16(st_ + 16384u + dh1, B0 + ko_ + gB1);                           \
    cp_async16(st_ + 16384u + dl0, B1 + ko_ + gB0);                           \
    cp_async16(st_ + 16384u + dl1, B1 + ko_ + gB1);                           \
    asm volatile("cp.async.commit_group;" ::: "memory");                      \
} while (0)

    ISSUE(0);
    if (NC > 1) ISSUE(1);

    for (int c = 0; c < NC; c++) {
        if (c + 1 < NC) asm volatile("cp.async.wait_group 1;" ::: "memory");
        else            asm volatile("cp.async.wait_group 0;" ::: "memory");
        __syncthreads();
        // This sync also orders compute(c-1) (all warps) before the stage
        // reuse below, making a trailing barrier unnecessary.
        if (c + 2 < NC) ISSUE(c + 2);

        uint32_t sa = sbase + (c % NSTAGE) * STG_SZ;
        uint32_t sb = sa + 16384u;
#pragma unroll
        for (int kk = 0; kk < 2; kk++) {
            uint32_t bh[4][2], blo[4][2], af[4][4];
#pragma unroll
            for (int j2 = 0; j2 < 2; j2++)
                ldsm_x4(&bh[j2 * 2][0],  sb + b4row[j2] + (((kk * 2 + cb)     ^ rb) << 4));
#pragma unroll
            for (int j2 = 0; j2 < 2; j2++)
                ldsm_x4(&blo[j2 * 2][0], sb + b4row[j2] + (((kk * 2 + cb + 4) ^ rb) << 4));
#pragma unroll
            for (int i = 0; i < 4; i++)
                ldsm_x4(af[i], sa + arow[i] + (((kk * 2 + cl)     ^ arx) << 4));
#pragma unroll
            for (int i = 0; i < 4; i++)
#pragma unroll
                for (int j = 0; j < 4; j++) mma16816(acc[i][j], af[i], bh[j]);
#pragma unroll
            for (int i = 0; i < 4; i++)
#pragma unroll
                for (int j = 0; j < 4; j++) mma16816(acc[i][j], af[i], blo[j]);
#pragma unroll
            for (int i = 0; i < 4; i++)
                ldsm_x4(af[i], sa + arow[i] + (((kk * 2 + cl + 4) ^ arx) << 4));
#pragma unroll
            for (int i = 0; i < 4; i++)
#pragma unroll
                for (int j = 0; j < 4; j++) mma16816(acc[i][j], af[i], bh[j]);
        }
    }

    ll cbase = bb * sCb + hh * sCh + (ll)ks * sCs;
#pragma unroll
    for (int i = 0; i < 4; i++) {
        int m = m0 + warp_m * 64 + i * 16 + (lane >> 2);
#pragma unroll
        for (int j = 0; j < 4; j++) {
            int n = n0 + warp_n * 32 + j * 8 + (lane & 3) * 2;
            if (n < Nreal) {
#pragma unroll
                for (int p = 0; p < 2; p++) {
                    int mm = m + p * 8;
                    if (mm < Mreal) {
                        if (EPI == 0) {
                            *(float2*)&C[cbase + (size_t)mm * ldc + n] =
                                make_float2(acc[i][j][p * 2], acc[i][j][p * 2 + 1]);
                        } else {
                            __nv_bfloat162 hp, lp;
                            packpair(acc[i][j][p * 2], acc[i][j][p * 2 + 1], hp, lp);
                            *(__nv_bfloat162*)&Ch[cbase + (size_t)mm * ldc + n] = hp;
                            *(__nv_bfloat162*)&Cl[cbase + (size_t)mm * ldc + n] = lp;
                        }
                    }
                }
            }
        }
    }
}

// ---------------- x -> bf16 hi/lo (straight + transposed), vectorized ----------------
__global__ __launch_bounds__(256) void convx_k(const float* __restrict__ x,
                                               bf16* __restrict__ xh, bf16* __restrict__ xl,
                                               bf16* __restrict__ xth, bf16* __restrict__ xtl) {
    __shared__ float ts[32][33];
    int b = blockIdx.z;
    int t0 = blockIdx.x * 32, d0 = blockIdx.y * 32;
    int tid = threadIdx.x;
    int r = tid >> 4, p = tid & 15;
#pragma unroll
    for (int it = 0; it < 2; it++) {
        int rr = r + it * 16;
        size_t o = ((size_t)b * Tt + t0 + rr) * Dd + d0 + 2 * p;
        float2 v = *(const float2*)(x + o);
        __nv_bfloat162 hp, lp; packpair(v.x, v.y, hp, lp);
        *(__nv_bfloat162*)(xh + o) = hp;
        *(__nv_bfloat162*)(xl + o) = lp;
        ts[rr][2 * p] = v.x; ts[rr][2 * p + 1] = v.y;
    }
    __syncthreads();
#pragma unroll
    for (int it = 0; it < 2; it++) {
        int dr = r + it * 16;
        float v0 = ts[2 * p][dr], v1 = ts[2 * p + 1][dr];
        __nv_bfloat162 hp, lp; packpair(v0, v1, hp, lp);
        size_t o = ((size_t)b * Dd + d0 + dr) * Tt + t0 + 2 * p;
        *(__nv_bfloat162*)(xth + o) = hp;
        *(__nv_bfloat162*)(xtl + o) = lp;
    }
}

// ---------------- three straight weight conversions in one launch, vectorized ----------------
__global__ __launch_bounds__(256) void convw3_k(
    const float* __restrict__ Wq, bf16* __restrict__ Wqh, bf16* __restrict__ Wql,
    const float* __restrict__ Wv, bf16* __restrict__ Wvh, bf16* __restrict__ Wvl,
    const float* __restrict__ Wo, bf16* __restrict__ Woh, bf16* __restrict__ Wol) {
    const float* W; bf16 *Wh, *Wl;
    if (blockIdx.y == 0)      { W = Wq; Wh = Wqh; Wl = Wql; }
    else if (blockIdx.y == 1) { W = Wv; Wh = Wvh; Wl = Wvl; }
    else                      { W = Wo; Wh = Woh; Wl = Wol; }
    for (int i = (blockIdx.x * 256 + threadIdx.x) * 2; i < Dd * Dd; i += gridDim.x * 512) {
        float2 v = *(const float2*)(W + i);
        __nv_bfloat162 hp, lp; packpair(v.x, v.y, hp, lp);
        *(__nv_bfloat162*)(Wh + i) = hp;
        *(__nv_bfloat162*)(Wl + i) = lp;
    }
}

// ---------------- weight fp32 -> transposed + scaled bf16 hi/lo, vectorized ----------------
__global__ __launch_bounds__(256) void convwT_k(const float* __restrict__ W,
                                                bf16* __restrict__ Wh, bf16* __restrict__ Wl,
                                                float alpha) {
    __shared__ float ts[32][33];
    int r0 = blockIdx.x * 32, c0 = blockIdx.y * 32;
    int tx = threadIdx.x & 31, ty = threadIdx.x >> 5;
#pragma unroll
    for (int i = 0; i < 4; i++) {
        int rr = ty * 4 + i;
        ts[rr][tx] = W[(size_t)(r0 + rr) * Dd + c0 + tx];
    }
    __syncthreads();
    int r = threadIdx.x >> 4, p = threadIdx.x & 15;
#pragma unroll
    for (int it = 0; it < 2; it++) {
        int c = r + it * 16;
        float v0 = alpha * ts[2 * p][c], v1 = alpha * ts[2 * p + 1][c];
        __nv_bfloat162 hp, lp; packpair(v0, v1, hp, lp);
        size_t o = (size_t)(c0 + c) * Dd + r0 + 2 * p;
        *(__nv_bfloat162*)(Wh + o) = hp;
        *(__nv_bfloat162*)(Wl + o) = lp;
    }
}

// ---------------- gather x rows at idx, split to bf16 hi/lo ----------------
__global__ __launch_bounds__(256) void gather_xs_k(bf16* __restrict__ xsh,
                                                   bf16* __restrict__ xsl,
                                                   const float4* __restrict__ x,
                                                   const int* __restrict__ idx, int u) {
    int b = blockIdx.x / u, j = blockIdx.x % u;
    int t = idx[j];
    float4 v = x[((size_t)b * Tt + t) * (Dd / 4) + threadIdx.x];
    size_t o = ((size_t)b * u + j) * Dd + threadIdx.x * 4;
    __nv_bfloat162 hp, lp;
    packpair(v.x, v.y, hp, lp);
    *(__nv_bfloat162*)(xsh + o) = hp;
    *(__nv_bfloat162*)(xsl + o) = lp;
    packpair(v.z, v.w, hp, lp);
    *(__nv_bfloat162*)(xsh + o + 2) = hp;
    *(__nv_bfloat162*)(xsl + o + 2) = lp;
}

// ---------------- split-K reduce (4-way) -> bf16 hi/lo, vectorized ----------------
__global__ __launch_bounds__(256) void redsplit4_k(const float* __restrict__ p,
                                                   bf16* __restrict__ oh, bf16* __restrict__ ol,
                                                   int n, int stride) {
    for (int i = (blockIdx.x * 256 + threadIdx.x) * 2; i < n; i += gridDim.x * 512) {
        float2 a0 = *(const float2*)(p + i);
        float2 a1 = *(const float2*)(p + i + stride);
        float2 a2 = *(const float2*)(p + i + 2 * stride);
        float2 a3 = *(const float2*)(p + i + 3 * stride);
        __nv_bfloat162 hp, lp;
        packpair(a0.x + a1.x + a2.x + a3.x, a0.y + a1.y + a2.y + a3.y, hp, lp);
        *(__nv_bfloat162*)(oh + i) = hp;
        *(__nv_bfloat162*)(ol + i) = lp;
    }
}

// ---------------- split-K reduce (2-way) -> bf16 hi/lo, vectorized ----------------
__global__ __launch_bounds__(256) void redsplit2_k(const float* __restrict__ p,
                                                   bf16* __restrict__ oh, bf16* __restrict__ ol,
                                                   int n, ll stride) {
    for (int i = (blockIdx.x * 256 + threadIdx.x) * 2; i < n; i += gridDim.x * 512) {
        float2 a0 = *(const float2*)(p + i);
        float2 a1 = *(const float2*)(p + i + stride);
        __nv_bfloat162 hp, lp;
        packpair(a0.x + a1.x, a0.y + a1.y, hp, lp);
        *(__nv_bfloat162*)(oh + i) = hp;
        *(__nv_bfloat162*)(ol + i) = lp;
    }
}

// ---------------- softmax: UNNORMALIZED exp hi/lo + row sums, vectorized ----------------
__global__ __launch_bounds__(256) void softmax_k(const float* __restrict__ s,
                                                 bf16* __restrict__ ah, bf16* __restrict__ al,
                                                 float* __restrict__ rsum, int Hu, int mp) {
    __shared__ float red[256];
    int b = blockIdx.x / Hu, r = blockIdx.x % Hu;
    size_t base = ((size_t)b * mp + r) * Tt;
    int tid = threadIdx.x;
    float m = -3.4e38f;
    for (int t = tid * 2; t < Tt; t += 512) {
        float2 v = *(const float2*)(s + base + t);
        m = fmaxf(m, fmaxf(v.x, v.y));
    }
    red[tid] = m; __syncthreads();
    for (int o = 128; o > 0; o >>= 1) {
        if (tid < o) red[tid] = fmaxf(red[tid], red[tid + o]);
        __syncthreads();
    }
    float mx = red[0];
    __syncthreads();
    float sum = 0.f;
    for (int t = tid * 2; t < Tt; t += 512) {
        float2 v = *(const float2*)(s + base + t);
        float e0 = __expf(v.x - mx), e1 = __expf(v.y - mx);
        sum += e0 + e1;
        __nv_bfloat162 hp, lp; packpair(e0, e1, hp, lp);
        *(__nv_bfloat162*)(ah + base + t) = hp;
        *(__nv_bfloat162*)(al + base + t) = lp;
    }
    red[tid] = sum; __syncthreads();
    for (int o = 128; o > 0; o >>= 1) {
        if (tid < o) red[tid] += red[tid + o];
        __syncthreads();
    }
    if (tid == 0) rsum[blockIdx.x] = red[0];
}

// ---------------- ctx -> per-token rows (normalized) + mean row, bf16 split ----------------
__global__ __launch_bounds__(64) void ctxrow_mean_k(bf16* __restrict__ crh,
                                                    bf16* __restrict__ crl,
                                                    const float* __restrict__ ctx,
                                                    const float* __restrict__ rsum,
                                                    int u, int Hu) {
    int b = blockIdx.x, h = blockIdx.y, d = threadIdx.x;
    float s = 0.f;
    for (int j = 0; j < u; j++) {
        float inv = 1.f / rsum[b * Hu + h * u + j];
        float v = ctx[((size_t)(b * Hh + h) * u + j) * DHh + d] * inv;
        bf16 hh, ll2; split2(v, hh, ll2);
        size_t o = ((size_t)b * (u + 1) + j) * Dd + h * DHh + d;
        crh[o] = hh; crl[o] = ll2;
        s += v;
    }
    bf16 hh, ll2; split2(s / (float)u, hh, ll2);
    size_t o = ((size_t)b * (u + 1) + u) * Dd + h * DHh + d;
    crh[o] = hh; crl[o] = ll2;
}

// ---------------- broadcast fill (8 rows/block) + scatter ----------------
__global__ __launch_bounds__(256) void fill_k(float4* __restrict__ y,
                                              const float4* __restrict__ ys,
                                              const float4* __restrict__ bo, int u) {
    int b = blockIdx.x / (Tt / 8);
    int tt0 = (blockIdx.x % (Tt / 8)) * 8;
    float4 v = ys[((size_t)b * (u + 1) + u) * 256 + threadIdx.x];
    float4 bb = bo[threadIdx.x];
    float4 o = make_float4(v.x + bb.x, v.y + bb.y, v.z + bb.z, v.w + bb.w);
    size_t base = ((size_t)b * Tt + tt0) * 256 + threadIdx.x;
#pragma unroll
    for (int i = 0; i < 8; i++) y[base + (size_t)i * 256] = o;
}
__global__ __launch_bounds__(256) void scatter_k(float4* __restrict__ y,
                                                 const float4* __restrict__ ys,
                                                 const float4* __restrict__ bo,
                                                 const int* __restrict__ idx, int u) {
    int b = blockIdx.x, j = blockIdx.y;
    int t = idx[j];
    float4 v = ys[((size_t)b * (u + 1) + j) * 256 + threadIdx.x];
    float4 bb = bo[threadIdx.x];
    y[((size_t)b * Tt + t) * 256 + threadIdx.x] =
        make_float4(v.x + bb.x, v.y + bb.y, v.z + bb.z, v.w + bb.w);
}

// ---------------- launch ----------------
extern "C" void kernel_launch(void* const* d_in, const int* in_sizes, int n_in,
                              void* d_out, int out_size) {
    const float* x  = (const float*)d_in[0];
    const float* Wq = (const float*)d_in[1];
    const float* Wk = (const float*)d_in[2];
    const float* Wv = (const float*)d_in[3];
    const float* Wo = (const float*)d_in[4];
    const float* bo = (const float*)d_in[5];
    const int* idx  = (const int*)d_in[6];
    int u = in_sizes[6];
    if (u > UMAX) u = UMAX;
    if (u < 1) u = 1;
    float* y = (float*)d_out;

    float *qsp, *sc, *rsum, *wxp, *ctx, *ys;
    bf16 *xsh, *xsl, *Wqh, *Wql, *WkTh, *WkTl, *Wvh, *Wvl, *Woh, *Wol;
    bf16 *Qsh, *Qsl, *Qth, *Qtl, *xh, *xl, *xth, *xtl, *ah, *al, *wxh, *wxl, *crh, *crl;
    cudaGetSymbolAddress((void**)&xsh,  g_xsh);
    cudaGetSymbolAddress((void**)&xsl,  g_xsl);
    cudaGetSymbolAddress((void**)&Wqh,  g_Wqh);
    cudaGetSymbolAddress((void**)&Wql,  g_Wql);
    cudaGetSymbolAddress((void**)&WkTh, g_WkTh);
    cudaGetSymbolAddress((void**)&WkTl, g_WkTl);
    cudaGetSymbolAddress((void**)&Wvh,  g_Wvh);
    cudaGetSymbolAddress((void**)&Wvl,  g_Wvl);
    cudaGetSymbolAddress((void**)&Woh,  g_Woh);
    cudaGetSymbolAddress((void**)&Wol,  g_Wol);
    cudaGetSymbolAddress((void**)&qsp,  g_qsp);
    cudaGetSymbolAddress((void**)&Qsh,  g_Qsh);
    cudaGetSymbolAddress((void**)&Qsl,  g_Qsl);
    cudaGetSymbolAddress((void**)&Qth,  g_Qth);
    cudaGetSymbolAddress((void**)&Qtl,  g_Qtl);
    cudaGetSymbolAddress((void**)&xh,   g_xh);
    cudaGetSymbolAddress((void**)&xl,   g_xl);
    cudaGetSymbolAddress((void**)&xth,  g_xth);
    cudaGetSymbolAddress((void**)&xtl,  g_xtl);
    cudaGetSymbolAddress((void**)&sc,   g_sc);
    cudaGetSymbolAddress((void**)&ah,   g_ah);
    cudaGetSymbolAddress((void**)&al,   g_al);
    cudaGetSymbolAddress((void**)&rsum, g_rsum);
    cudaGetSymbolAddress((void**)&wxp,  g_wxp);
    cudaGetSymbolAddress((void**)&wxh,  g_wxh);
    cudaGetSymbolAddress((void**)&wxl,  g_wxl);
    cudaGetSymbolAddress((void**)&ctx,  g_ctx);
    cudaGetSymbolAddress((void**)&crh,  g_crh);
    cudaGetSymbolAddress((void**)&crl,  g_crl);
    cudaGetSymbolAddress((void**)&ys,   g_ys);

    const int Hu = Hh * u;
    const int mp = ((Hu + 127) / 128) * 128;
    const int Bu = Bb * u;
    const int bup = ((Bu + 127) / 128) * 128;
    const float scale = 0.125f;

    const int smem_n = NSTAGE * (int)STG_SZ;   // 98304
    cudaFuncSetAttribute(mma_gemm_k<0>, cudaFuncAttributeMaxDynamicSharedMemorySize, smem_n);
    cudaFuncSetAttribute(mma_gemm_k<1>, cudaFuncAttributeMaxDynamicSharedMemorySize, smem_n);

    // 0) conversions
    convx_k<<<dim3(Tt / 32, Dd / 32, Bb), 256>>>(x, xh, xl, xth, xtl);
    convw3_k<<<dim3(256, 3), 256>>>(Wq, Wqh, Wql, Wv, Wvh, Wvl, Wo, Woh, Wol);
    convwT_k<<<dim3(32, 32), 256>>>(Wk, WkTh, WkTl, scale);

    // 1) gather+split x rows at idx
    gather_xs_k<<<Bb * u, 256>>>(xsh, xsl, (const float4*)x, idx, u);

    // 2) Qs partials = xs @ Wq^T   (split-K=4)
    mma_gemm_k<0><<<dim3(Dd / BNt, bup / BMt, 4), 256, smem_n>>>(
        qsp, nullptr, nullptr, xsh, xsl, Wqh, Wql,
        256, Dd, Dd, Dd, Bu, Dd,
        0, 0, 0, 0, 0, 0, 1, 4, (ll)bup * Dd);
    redsplit4_k<<<512, 256>>>(qsp, Qsh, Qsl, Bu * Dd, bup * Dd);

    // 3) Qt[b,h] = Qs[b](cols h*64..) @ (scale*Wk_h)  -> bf16 hi/lo padded
    mma_gemm_k<1><<<dim3(Dd / BNt, 1, Bb * Hh), 256, smem_n>>>(
        nullptr, Qth, Qtl, Qsh, Qsl, WkTh, WkTl,
        DHh, Dd, Dd, Dd, u, Dd,
        (ll)u * Dd, (ll)DHh, 0, (ll)DHh, (ll)mp * Dd, (ll)u * Dd, Hh, 1, 0);

    // 4) scores[b] = Qt[b] @ x[b]^T   (only real Hu rows stored)
    mma_gemm_k<0><<<dim3(Tt / BNt, mp / BMt, Bb), 256, smem_n>>>(
        sc, nullptr, nullptr, Qth, Qtl, xh, xl,
        Dd, Dd, Dd, Tt, Hu, Tt,
        (ll)mp * Dd, 0, (ll)Tt * Dd, 0, (ll)mp * Tt, 0, 1, 1, 0);

    // 5) softmax -> unnormalized exp hi/lo + row sums
    softmax_k<<<Bb * Hu, 256>>>(sc, ah, al, rsum, Hu, mp);

    // 6) wx partials = e[b] @ x[b]   (split-K=2, B = x^T layout)
    mma_gemm_k<0><<<dim3(Dd / BNt, mp / BMt, Bb * 2), 256, smem_n>>>(
        wxp, nullptr, nullptr, ah, al, xth, xtl,
        Tt / 2, Tt, Tt, Dd, mp, Dd,
        (ll)mp * Tt, 0, (ll)Dd * Tt, 0, (ll)mp * Dd, 0, 1, 2, (ll)Bb * mp * Dd);
    redsplit2_k<<<1024, 256>>>(wxp, wxh, wxl, Bb * mp * Dd, (ll)Bb * mp * Dd);

    // 7) ctx[b,h] = wx[b,h] @ Wv_h^T   (fp32 out)
    mma_gemm_k<0><<<dim3(1, 1, Bb * Hh), 256, smem_n>>>(
        ctx, nullptr, nullptr, wxh, wxl, Wvh, Wvl,
        Dd, Dd, Dd, DHh, u, DHh,
        (ll)mp * Dd, (ll)u * Dd, 0, (ll)DHh * Dd, (ll)Hh * u * DHh, (ll)u * DHh, Hh, 1, 0);

    // 8) reorder ctx + normalize + mean row -> bf16 split
    ctxrow_mean_k<<<dim3(Bb, Hh), 64>>>(crh, crl, ctx, rsum, u, Hu);

    // 9) ys = cr @ Wo^T   (fp32 out)
    mma_gemm_k<0><<<dim3(Dd / BNt, 1, Bb), 256, smem_n>>>(
        ys, nullptr, nullptr, crh, crl, Woh, Wol,
        Dd, Dd, Dd, Dd, u + 1, Dd,
        (ll)(u + 1) * Dd, 0, 0, 0, (ll)(u + 1) * Dd, 0, 1, 1, 0);

    // 10) broadcast + scatter
    fill_k<<<Bb * (Tt / 8), 256>>>((float4*)y, (const float4*)ys, (const float4*)bo, u);
    scatter_k<<<dim3(Bb, u), 256>>>((float4*)y, (const float4*)ys, (const float4*)bo, idx, u);
}

// round 14
// speedup vs baseline: 1.4338x; 1.1235x over previous
#include <cuda_runtime.h>
#include <cuda_bf16.h>
#include <cuda_fp16.h>
#include <cstdint>

#define Bb   8
#define Tt   4096
#define Dd   1024
#define Hh   16
#define DHh  64
#define UMAX 64
#define MPMAX 1024
#define BUPMAX 512

typedef long long ll;
typedef __nv_bfloat16 bf16;

// ---------------- scratch (static __device__, allocation-free) ----------------
__device__ bf16  g_xsh[Bb * UMAX * Dd];
__device__ bf16  g_xsl[Bb * UMAX * Dd];
__device__ bf16  g_Wqh[Dd * Dd];
__device__ bf16  g_Wql[Dd * Dd];
__device__ bf16  g_WkTh[Dd * Dd];
__device__ bf16  g_WkTl[Dd * Dd];
__device__ bf16  g_Wvh[(Dd + 128) * Dd];     // row-padded for OOB-safe tile loads
__device__ bf16  g_Wvl[(Dd + 128) * Dd];
__device__ bf16  g_Woh[Dd * Dd];
__device__ bf16  g_Wol[Dd * Dd];
__device__ float g_qsp[4 * BUPMAX * Dd];     // step-2 split-K partials
__device__ bf16  g_Qsh[Bb * UMAX * Dd];
__device__ bf16  g_Qsl[Bb * UMAX * Dd];
__device__ bf16  g_Qth[(size_t)Bb * MPMAX * Dd];
__device__ bf16  g_Qtl[(size_t)Bb * MPMAX * Dd];
__device__ bf16  g_xh[(size_t)Bb * Tt * Dd];
__device__ bf16  g_xl[(size_t)Bb * Tt * Dd];
__device__ __half g_xthh[(size_t)Bb * Dd * Tt];   // x^T fp16 hi
__device__ __half g_xthl[(size_t)Bb * Dd * Tt];   // x^T fp16 lo
__device__ float g_sc[(size_t)Bb * MPMAX * Tt];
__device__ __half g_ahf[(size_t)Bb * MPMAX * Tt]; // exp weights, single fp16
__device__ float g_rsum[Bb * Hh * UMAX];
__device__ float g_wxp[(size_t)2 * Bb * MPMAX * Dd];  // step-6 split-K partials
__device__ bf16  g_wxh[(size_t)Bb * MPMAX * Dd];
__device__ bf16  g_wxl[(size_t)Bb * MPMAX * Dd];
__device__ float g_ctx[Bb * Hh * UMAX * DHh];
__device__ bf16  g_crh[Bb * (UMAX + 2) * Dd];
__device__ bf16  g_crl[Bb * (UMAX + 2) * Dd];
__device__ float g_ys[Bb * (UMAX + 1) * Dd];

// ---------------- PTX helpers (sm_80/sm_90 portable only) ----------------
__device__ __forceinline__ uint32_t smem_u32(const void* p) {
    uint32_t a;
    asm("{ .reg .u64 t; cvta.to.shared.u64 t, %1; cvt.u32.u64 %0, t; }" : "=r"(a) : "l"(p));
    return a;
}
__device__ __forceinline__ void cp_async16(uint32_t s, const void* g) {
    asm volatile("cp.async.cg.shared.global [%0], [%1], 16;" :: "r"(s), "l"(g) : "memory");
}
__device__ __forceinline__ void ldsm_x4(uint32_t* r, uint32_t a) {
    asm volatile("ldmatrix.sync.aligned.m8n8.x4.shared.b16 {%0,%1,%2,%3}, [%4];"
                 : "=r"(r[0]), "=r"(r[1]), "=r"(r[2]), "=r"(r[3]) : "r"(a));
}
__device__ __forceinline__ void mma16816(float* c, const uint32_t* a, const uint32_t* b) {
    asm volatile(
        "mma.sync.aligned.m16n8k16.row.col.f32.bf16.bf16.f32 "
        "{%0,%1,%2,%3}, {%4,%5,%6,%7}, {%8,%9}, {%0,%1,%2,%3};"
        : "+f"(c[0]), "+f"(c[1]), "+f"(c[2]), "+f"(c[3])
        : "r"(a[0]), "r"(a[1]), "r"(a[2]), "r"(a[3]), "r"(b[0]), "r"(b[1]));
}
__device__ __forceinline__ void mma16816h(float* c, const uint32_t* a, const uint32_t* b) {
    asm volatile(
        "mma.sync.aligned.m16n8k16.row.col.f32.f16.f16.f32 "
        "{%0,%1,%2,%3}, {%4,%5,%6,%7}, {%8,%9}, {%0,%1,%2,%3};"
        : "+f"(c[0]), "+f"(c[1]), "+f"(c[2]), "+f"(c[3])
        : "r"(a[0]), "r"(a[1]), "r"(a[2]), "r"(a[3]), "r"(b[0]), "r"(b[1]));
}

__device__ __forceinline__ void split2(float v, bf16& h, bf16& l) {
    h = __float2bfloat16(v);
    l = __float2bfloat16(v - __bfloat162float(h));
}
__device__ __forceinline__ void packpair(float a, float b,
                                         __nv_bfloat162& hp, __nv_bfloat162& lp) {
    bf16 h0, l0, h1, l1; split2(a, h0, l0); split2(b, h1, l1);
    hp.x = h0; hp.y = h1; lp.x = l0; lp.y = l1;
}
__device__ __forceinline__ void packpairh(float a, float b,
                                          __half2& hp, __half2& lp) {
    __half h0 = __float2half_rn(a), h1 = __float2half_rn(b);
    __half l0 = __float2half_rn(a - __half2float(h0));
    __half l1 = __float2half_rn(b - __half2float(h1));
    hp = __halves2half2(h0, h1);
    lp = __halves2half2(l0, l1);
}

// ============ narrow merged-pass warp-MMA GEMM, bf16 3-term ============
#define BMt 128
#define BNt 128
#define STG_SZ 32768u
#define NSTAGE 3

template <int EPI>
__global__ __launch_bounds__(256, 2) void mma_gemm_k(
    float* __restrict__ C, bf16* __restrict__ Ch, bf16* __restrict__ Cl,
    const bf16* __restrict__ Ah, const bf16* __restrict__ Al,
    const bf16* __restrict__ Bh, const bf16* __restrict__ Bl,
    int Kext, int lda, int ldb, int ldc, int Mreal, int Nreal,
    ll sAb, ll sAh, ll sBb, ll sBh, ll sCb, ll sCh,
    int nh, int KS, ll sCs) {
    extern __shared__ char smem[];
    uint32_t sbase = smem_u32(smem);
    int tid = threadIdx.x, wid = tid >> 5, lane = tid & 31;
    int z = blockIdx.z;
    int ks = z % KS, bh2 = z / KS;
    int hh = bh2 % nh, bb = bh2 / nh;
    int m0 = blockIdx.y * BMt, n0 = blockIdx.x * BNt;

    const bf16* A0 = Ah + bb * sAb + hh * sAh + (ll)ks * Kext + (size_t)m0 * lda;
    const bf16* A1 = Al + bb * sAb + hh * sAh + (ll)ks * Kext + (size_t)m0 * lda;
    const bf16* B0 = Bh + bb * sBb + hh * sBh + (ll)ks * Kext + (size_t)n0 * ldb;
    const bf16* B1 = Bl + bb * sBb + hh * sBh + (ll)ks * Kext + (size_t)n0 * ldb;

    int row = tid >> 1, cq = tid & 1, rx = row & 7;
    size_t   gA0 = (size_t)row * lda + cq * 8, gA1 = gA0 + 16;
    size_t   gB0 = (size_t)row * ldb + cq * 8, gB1 = gB0 + 16;
    uint32_t dh0 = row * 128 + ((cq)     ^ rx) * 16;
    uint32_t dh1 = row * 128 + ((cq + 2) ^ rx) * 16;
    uint32_t dl0 = row * 128 + ((cq + 4) ^ rx) * 16;
    uint32_t dl1 = row * 128 + ((cq + 6) ^ rx) * 16;

    int warp_m = wid >> 2, warp_n = wid & 3;
    int rl = lane & 15, cl = lane >> 4, arx = lane & 7;
    int rb = lane & 7,  cb = (lane >> 3) & 1;
    uint32_t arow[4], b4row[2];
#pragma unroll
    for (int i = 0; i < 4; i++) arow[i] = (warp_m * 64 + i * 16 + rl) * 128;
#pragma unroll
    for (int j2 = 0; j2 < 2; j2++)
        b4row[j2] = (warp_n * 32 + (j2 * 2 + (lane >> 4)) * 8 + rb) * 128;

    float acc[4][4][4];
#pragma unroll
    for (int i = 0; i < 4; i++)
#pragma unroll
        for (int j = 0; j < 4; j++)
#pragma unroll
            for (int q = 0; q < 4; q++) acc[i][j][q] = 0.f;

    const int NC = Kext >> 5;

#define ISSUE(c_) do {                                                        \
    size_t ko_ = (size_t)(c_) * 32;                                           \
    uint32_t st_ = sbase + ((c_) % NSTAGE) * STG_SZ;                          \
    cp_async16(st_ + dh0, A0 + ko_ + gA0);                                    \
    cp_async16(st_ + dh1, A0 + ko_ + gA1);                                    \
    cp_async16(st_ + dl0, A1 + ko_ + gA0);                                    \
    cp_async16(st_ + dl1, A1 + ko_ + gA1);                                    \
    cp_async16(st_ + 16384u + dh0, B0 + ko_ + gB0);                           \
    cp_async16(st_ + 16384u + dh1, B0 + ko_ + gB1);                           \
    cp_async16(st_ + 16384u + dl0, B1 + ko_ + gB0);                           \
    cp_async16(st_ + 16384u + dl1, B1 + ko_ + gB1);                           \
    asm volatile("cp.async.commit_group;" ::: "memory");                      \
} while (0)

    ISSUE(0);
    if (NC > 1) ISSUE(1);

    for (int c = 0; c < NC; c++) {
        if (c + 1 < NC) asm volatile("cp.async.wait_group 1;" ::: "memory");
        else            asm volatile("cp.async.wait_group 0;" ::: "memory");
        __syncthreads();
        if (c + 2 < NC) ISSUE(c + 2);

        uint32_t sa = sbase + (c % NSTAGE) * STG_SZ;
        uint32_t sb = sa + 16384u;
#pragma unroll
        for (int kk = 0; kk < 2; kk++) {
            uint32_t bh[4][2], blo[4][2], af[4][4];
#pragma unroll
            for (int j2 = 0; j2 < 2; j2++)
                ldsm_x4(&bh[j2 * 2][0],  sb + b4row[j2] + (((kk * 2 + cb)     ^ rb) << 4));
#pragma unroll
            for (int j2 = 0; j2 < 2; j2++)
                ldsm_x4(&blo[j2 * 2][0], sb + b4row[j2] + (((kk * 2 + cb + 4) ^ rb) << 4));
#pragma unroll
            for (int i = 0; i < 4; i++)
                ldsm_x4(af[i], sa + arow[i] + (((kk * 2 + cl)     ^ arx) << 4));
#pragma unroll
            for (int i = 0; i < 4; i++)
#pragma unroll
                for (int j = 0; j < 4; j++) mma16816(acc[i][j], af[i], bh[j]);
#pragma unroll
            for (int i = 0; i < 4; i++)
#pragma unroll
                for (int j = 0; j < 4; j++) mma16816(acc[i][j], af[i], blo[j]);
#pragma unroll
            for (int i = 0; i < 4; i++)
                ldsm_x4(af[i], sa + arow[i] + (((kk * 2 + cl + 4) ^ arx) << 4));
#pragma unroll
            for (int i = 0; i < 4; i++)
#pragma unroll
                for (int j = 0; j < 4; j++) mma16816(acc[i][j], af[i], bh[j]);
        }
    }

    ll cbase = bb * sCb + hh * sCh + (ll)ks * sCs;
#pragma unroll
    for (int i = 0; i < 4; i++) {
        int m = m0 + warp_m * 64 + i * 16 + (lane >> 2);
#pragma unroll
        for (int j = 0; j < 4; j++) {
            int n = n0 + warp_n * 32 + j * 8 + (lane & 3) * 2;
            if (n < Nreal) {
#pragma unroll
                for (int p = 0; p < 2; p++) {
                    int mm = m + p * 8;
                    if (mm < Mreal) {
                        if (EPI == 0) {
                            *(float2*)&C[cbase + (size_t)mm * ldc + n] =
                                make_float2(acc[i][j][p * 2], acc[i][j][p * 2 + 1]);
                        } else {
                            __nv_bfloat162 hp, lp;
                            packpair(acc[i][j][p * 2], acc[i][j][p * 2 + 1], hp, lp);
                            *(__nv_bfloat162*)&Ch[cbase + (size_t)mm * ldc + n] = hp;
                            *(__nv_bfloat162*)&Cl[cbase + (size_t)mm * ldc + n] = lp;
                        }
                    }
                }
            }
        }
    }
}

// ============ fp16 2-term warp-MMA GEMM: C = A @ (Bh + Bl)^T (step 6) ============
// A single fp16 (M x Kext), B fp16 hi/lo (N x Kext). Same tile/pipeline shape.
__global__ __launch_bounds__(256, 2) void mma_f16_2t_k(
    float* __restrict__ C,
    const __half* __restrict__ A, const __half* __restrict__ Bh,
    const __half* __restrict__ Bl,
    int Kext, int lda, int ldb, int ldc, int Mreal, int Nreal,
    ll sAb, ll sBb, ll sCb, int KS, ll sCs) {
    extern __shared__ char smem[];
    uint32_t sbase = smem_u32(smem);
    int tid = threadIdx.x, wid = tid >> 5, lane = tid & 31;
    int z = blockIdx.z;
    int ks = z % KS, bb = z / KS;
    int m0 = blockIdx.y * BMt, n0 = blockIdx.x * BNt;

    const __half* A0 = A  + bb * sAb + (ll)ks * Kext + (size_t)m0 * lda;
    const __half* B0 = Bh + bb * sBb + (ll)ks * Kext + (size_t)n0 * ldb;
    const __half* B1 = Bl + bb * sBb + (ll)ks * Kext + (size_t)n0 * ldb;

    int row = tid >> 1, cq = tid & 1, rx = row & 7;
    size_t   gA0 = (size_t)row * lda + cq * 8, gA1 = gA0 + 16;
    size_t   gB0 = (size_t)row * ldb + cq * 8, gB1 = gB0 + 16;
    uint32_t dh0 = row * 128 + ((cq)     ^ rx) * 16;
    uint32_t dh1 = row * 128 + ((cq + 2) ^ rx) * 16;
    uint32_t dl0 = row * 128 + ((cq + 4) ^ rx) * 16;
    uint32_t dl1 = row * 128 + ((cq + 6) ^ rx) * 16;

    int warp_m = wid >> 2, warp_n = wid & 3;
    int rl = lane & 15, cl = lane >> 4, arx = lane & 7;
    int rb = lane & 7,  cb = (lane >> 3) & 1;
    uint32_t arow[4], b4row[2];
#pragma unroll
    for (int i = 0; i < 4; i++) arow[i] = (warp_m * 64 + i * 16 + rl) * 128;
#pragma unroll
    for (int j2 = 0; j2 < 2; j2++)
        b4row[j2] = (warp_n * 32 + (j2 * 2 + (lane >> 4)) * 8 + rb) * 128;

    float acc[4][4][4];
#pragma unroll
    for (int i = 0; i < 4; i++)
#pragma unroll
        for (int j = 0; j < 4; j++)
#pragma unroll
            for (int q = 0; q < 4; q++) acc[i][j][q] = 0.f;

    const int NC = Kext >> 5;

#define ISSUE2(c_) do {                                                       \
    size_t ko_ = (size_t)(c_) * 32;                                           \
    uint32_t st_ = sbase + ((c_) % NSTAGE) * STG_SZ;                          \
    cp_async16(st_ + dh0, A0 + ko_ + gA0);                                    \
    cp_async16(st_ + dh1, A0 + ko_ + gA1);                                    \
    cp_async16(st_ + 16384u + dh0, B0 + ko_ + gB0);                           \
    cp_async16(st_ + 16384u + dh1, B0 + ko_ + gB1);                           \
    cp_async16(st_ + 16384u + dl0, B1 + ko_ + gB0);                           \
    cp_async16(st_ + 16384u + dl1, B1 + ko_ + gB1);                           \
    asm volatile("cp.async.commit_group;" ::: "memory");                      \
} while (0)

    ISSUE2(0);
    if (NC > 1) ISSUE2(1);

    for (int c = 0; c < NC; c++) {
        if (c + 1 < NC) asm volatile("cp.async.wait_group 1;" ::: "memory");
        else            asm volatile("cp.async.wait_group 0;" ::: "memory");
        __syncthreads();
        if (c + 2 < NC) ISSUE2(c + 2);

        uint32_t sa = sbase + (c % NSTAGE) * STG_SZ;
        uint32_t sb = sa + 16384u;
#pragma unroll
        for (int kk = 0; kk < 2; kk++) {
            uint32_t bh[4][2], blo[4][2], af[4][4];
#pragma unroll
            for (int j2 = 0; j2 < 2; j2++)
                ldsm_x4(&bh[j2 * 2][0],  sb + b4row[j2] + (((kk * 2 + cb)     ^ rb) << 4));
#pragma unroll
            for (int j2 = 0; j2 < 2; j2++)
                ldsm_x4(&blo[j2 * 2][0], sb + b4row[j2] + (((kk * 2 + cb + 4) ^ rb) << 4));
#pragma unroll
            for (int i = 0; i < 4; i++)
                ldsm_x4(af[i], sa + arow[i] + (((kk * 2 + cl) ^ arx) << 4));
#pragma unroll
            for (int i = 0; i < 4; i++)
#pragma unroll
                for (int j = 0; j < 4; j++) mma16816h(acc[i][j], af[i], bh[j]);
#pragma unroll
            for (int i = 0; i < 4; i++)
#pragma unroll
                for (int j = 0; j < 4; j++) mma16816h(acc[i][j], af[i], blo[j]);
        }
    }

    ll cbase = bb * sCb + (ll)ks * sCs;
#pragma unroll
    for (int i = 0; i < 4; i++) {
        int m = m0 + warp_m * 64 + i * 16 + (lane >> 2);
#pragma unroll
        for (int j = 0; j < 4; j++) {
            int n = n0 + warp_n * 32 + j * 8 + (lane & 3) * 2;
            if (n < Nreal) {
#pragma unroll
                for (int p = 0; p < 2; p++) {
                    int mm = m + p * 8;
                    if (mm < Mreal) {
                        *(float2*)&C[cbase + (size_t)mm * ldc + n] =
                            make_float2(acc[i][j][p * 2], acc[i][j][p * 2 + 1]);
                    }
                }
            }
        }
    }
}

// ---------------- x -> bf16 hi/lo straight + fp16 hi/lo transposed ----------------
__global__ __launch_bounds__(256) void convx_k(const float* __restrict__ x,
                                               bf16* __restrict__ xh, bf16* __restrict__ xl,
                                               __half* __restrict__ xth,
                                               __half* __restrict__ xtl) {
    __shared__ float ts[32][33];
    int b = blockIdx.z;
    int t0 = blockIdx.x * 32, d0 = blockIdx.y * 32;
    int tid = threadIdx.x;
    int r = tid >> 4, p = tid & 15;
#pragma unroll
    for (int it = 0; it < 2; it++) {
        int rr = r + it * 16;
        size_t o = ((size_t)b * Tt + t0 + rr) * Dd + d0 + 2 * p;
        float2 v = *(const float2*)(x + o);
        __nv_bfloat162 hp, lp; packpair(v.x, v.y, hp, lp);
        *(__nv_bfloat162*)(xh + o) = hp;
        *(__nv_bfloat162*)(xl + o) = lp;
        ts[rr][2 * p] = v.x; ts[rr][2 * p + 1] = v.y;
    }
    __syncthreads();
#pragma unroll
    for (int it = 0; it < 2; it++) {
        int dr = r + it * 16;
        float v0 = ts[2 * p][dr], v1 = ts[2 * p + 1][dr];
        __half2 hp, lp; packpairh(v0, v1, hp, lp);
        size_t o = ((size_t)b * Dd + d0 + dr) * Tt + t0 + 2 * p;
        *(__half2*)(xth + o) = hp;
        *(__half2*)(xtl + o) = lp;
    }
}

// ---------------- three straight weight conversions in one launch ----------------
__global__ __launch_bounds__(256) void convw3_k(
    const float* __restrict__ Wq, bf16* __restrict__ Wqh, bf16* __restrict__ Wql,
    const float* __restrict__ Wv, bf16* __restrict__ Wvh, bf16* __restrict__ Wvl,
    const float* __restrict__ Wo, bf16* __restrict__ Woh, bf16* __restrict__ Wol) {
    const float* W; bf16 *Wh, *Wl;
    if (blockIdx.y == 0)      { W = Wq; Wh = Wqh; Wl = Wql; }
    else if (blockIdx.y == 1) { W = Wv; Wh = Wvh; Wl = Wvl; }
    else                      { W = Wo; Wh = Woh; Wl = Wol; }
    for (int i = (blockIdx.x * 256 + threadIdx.x) * 2; i < Dd * Dd; i += gridDim.x * 512) {
        float2 v = *(const float2*)(W + i);
        __nv_bfloat162 hp, lp; packpair(v.x, v.y, hp, lp);
        *(__nv_bfloat162*)(Wh + i) = hp;
        *(__nv_bfloat162*)(Wl + i) = lp;
    }
}

// ---------------- weight fp32 -> transposed + scaled bf16 hi/lo ----------------
__global__ __launch_bounds__(256) void convwT_k(const float* __restrict__ W,
                                                bf16* __restrict__ Wh, bf16* __restrict__ Wl,
                                                float alpha) {
    __shared__ float ts[32][33];
    int r0 = blockIdx.x * 32, c0 = blockIdx.y * 32;
    int tx = threadIdx.x & 31, ty = threadIdx.x >> 5;
#pragma unroll
    for (int i = 0; i < 4; i++) {
        int rr = ty * 4 + i;
        ts[rr][tx] = W[(size_t)(r0 + rr) * Dd + c0 + tx];
    }
    __syncthreads();
    int r = threadIdx.x >> 4, p = threadIdx.x & 15;
#pragma unroll
    for (int it = 0; it < 2; it++) {
        int c = r + it * 16;
        float v0 = alpha * ts[2 * p][c], v1 = alpha * ts[2 * p + 1][c];
        __nv_bfloat162 hp, lp; packpair(v0, v1, hp, lp);
        size_t o = (size_t)(c0 + c) * Dd + r0 + 2 * p;
        *(__nv_bfloat162*)(Wh + o) = hp;
        *(__nv_bfloat162*)(Wl + o) = lp;
    }
}

// ---------------- gather x rows at idx, split to bf16 hi/lo ----------------
__global__ __launch_bounds__(256) void gather_xs_k(bf16* __restrict__ xsh,
                                                   bf16* __restrict__ xsl,
                                                   const float4* __restrict__ x,
                                                   const int* __restrict__ idx, int u) {
    int b = blockIdx.x / u, j = blockIdx.x % u;
    int t = idx[j];
    float4 v = x[((size_t)b * Tt + t) * (Dd / 4) + threadIdx.x];
    size_t o = ((size_t)b * u + j) * Dd + threadIdx.x * 4;
    __nv_bfloat162 hp, lp;
    packpair(v.x, v.y, hp, lp);
    *(__nv_bfloat162*)(xsh + o) = hp;
    *(__nv_bfloat162*)(xsl + o) = lp;
    packpair(v.z, v.w, hp, lp);
    *(__nv_bfloat162*)(xsh + o + 2) = hp;
    *(__nv_bfloat162*)(xsl + o + 2) = lp;
}

// ---------------- split-K reduce (4-way) -> bf16 hi/lo ----------------
__global__ __launch_bounds__(256) void redsplit4_k(const float* __restrict__ p,
                                                   bf16* __restrict__ oh, bf16* __restrict__ ol,
                                                   int n, int stride) {
    for (int i = (blockIdx.x * 256 + threadIdx.x) * 2; i < n; i += gridDim.x * 512) {
        float2 a0 = *(const float2*)(p + i);
        float2 a1 = *(const float2*)(p + i + stride);
        float2 a2 = *(const float2*)(p + i + 2 * stride);
        float2 a3 = *(const float2*)(p + i + 3 * stride);
        __nv_bfloat162 hp, lp;
        packpair(a0.x + a1.x + a2.x + a3.x, a0.y + a1.y + a2.y + a3.y, hp, lp);
        *(__nv_bfloat162*)(oh + i) = hp;
        *(__nv_bfloat162*)(ol + i) = lp;
    }
}

// ---------------- split-K reduce (2-way) -> bf16 hi/lo ----------------
__global__ __launch_bounds__(256) void redsplit2_k(const float* __restrict__ p,
                                                   bf16* __restrict__ oh, bf16* __restrict__ ol,
                                                   int n, ll stride) {
    for (int i = (blockIdx.x * 256 + threadIdx.x) * 2; i < n; i += gridDim.x * 512) {
        float2 a0 = *(const float2*)(p + i);
        float2 a1 = *(const float2*)(p + i + stride);
        __nv_bfloat162 hp, lp;
        packpair(a0.x + a1.x, a0.y + a1.y, hp, lp);
        *(__nv_bfloat162*)(oh + i) = hp;
        *(__nv_bfloat162*)(ol + i) = lp;
    }
}

// ---------------- softmax: UNNORMALIZED exp -> single fp16 + row sums ----------------
__global__ __launch_bounds__(256) void softmax_k(const float* __restrict__ s,
                                                 __half* __restrict__ ah,
                                                 float* __restrict__ rsum, int Hu, int mp) {
    __shared__ float red[256];
    int b = blockIdx.x / Hu, r = blockIdx.x % Hu;
    size_t base = ((size_t)b * mp + r) * Tt;
    int tid = threadIdx.x;
    float m = -3.4e38f;
    for (int t = tid * 2; t < Tt; t += 512) {
        float2 v = *(const float2*)(s + base + t);
        m = fmaxf(m, fmaxf(v.x, v.y));
    }
    red[tid] = m; __syncthreads();
    for (int o = 128; o > 0; o >>= 1) {
        if (tid < o) red[tid] = fmaxf(red[tid], red[tid + o]);
        __syncthreads();
    }
    float mx = red[0];
    __syncthreads();
    float sum = 0.f;
    for (int t = tid * 2; t < Tt; t += 512) {
        float2 v = *(const float2*)(s + base + t);
        float e0 = __expf(v.x - mx), e1 = __expf(v.y - mx);
        sum += e0 + e1;
        *(__half2*)(ah + base + t) = __floats2half2_rn(e0, e1);
    }
    red[tid] = sum; __syncthreads();
    for (int o = 128; o > 0; o >>= 1) {
        if (tid < o) red[tid] += red[tid + o];
        __syncthreads();
    }
    if (tid == 0) rsum[blockIdx.x] = red[0];
}

// ---------------- ctx -> per-token rows (normalized) + mean row, bf16 split ----------------
__global__ __launch_bounds__(64) void ctxrow_mean_k(bf16* __restrict__ crh,
                                                    bf16* __restrict__ crl,
                                                    const float* __restrict__ ctx,
                                                    const float* __restrict__ rsum,
                                                    int u, int Hu) {
    int b = blockIdx.x, h = blockIdx.y, d = threadIdx.x;
    float s = 0.f;
    for (int j = 0; j < u; j++) {
        float inv = 1.f / rsum[b * Hu + h * u + j];
        float v = ctx[((size_t)(b * Hh + h) * u + j) * DHh + d] * inv;
        bf16 hh, ll2; split2(v, hh, ll2);
        size_t o = ((size_t)b * (u + 1) + j) * Dd + h * DHh + d;
        crh[o] = hh; crl[o] = ll2;
        s += v;
    }
    bf16 hh, ll2; split2(s / (float)u, hh, ll2);
    size_t o = ((size_t)b * (u + 1) + u) * Dd + h * DHh + d;
    crh[o] = hh; crl[o] = ll2;
}

// ---------------- broadcast fill (8 rows/block) + scatter ----------------
__global__ __launch_bounds__(256) void fill_k(float4* __restrict__ y,
                                              const float4* __restrict__ ys,
                                              const float4* __restrict__ bo, int u) {
    int b = blockIdx.x / (Tt / 8);
    int tt0 = (blockIdx.x % (Tt / 8)) * 8;
    float4 v = ys[((size_t)b * (u + 1) + u) * 256 + threadIdx.x];
    float4 bb = bo[threadIdx.x];
    float4 o = make_float4(v.x + bb.x, v.y + bb.y, v.z + bb.z, v.w + bb.w);
    size_t base = ((size_t)b * Tt + tt0) * 256 + threadIdx.x;
#pragma unroll
    for (int i = 0; i < 8; i++) y[base + (size_t)i * 256] = o;
}
__global__ __launch_bounds__(256) void scatter_k(float4* __restrict__ y,
                                                 const float4* __restrict__ ys,
                                                 const float4* __restrict__ bo,
                                                 const int* __restrict__ idx, int u) {
    int b = blockIdx.x, j = blockIdx.y;
    int t = idx[j];
    float4 v = ys[((size_t)b * (u + 1) + j) * 256 + threadIdx.x];
    float4 bb = bo[threadIdx.x];
    y[((size_t)b * Tt + t) * 256 + threadIdx.x] =
        make_float4(v.x + bb.x, v.y + bb.y, v.z + bb.z, v.w + bb.w);
}

// ---------------- launch ----------------
extern "C" void kernel_launch(void* const* d_in, const int* in_sizes, int n_in,
                              void* d_out, int out_size) {
    const float* x  = (const float*)d_in[0];
    const float* Wq = (const float*)d_in[1];
    const float* Wk = (const float*)d_in[2];
    const float* Wv = (const float*)d_in[3];
    const float* Wo = (const float*)d_in[4];
    const float* bo = (const float*)d_in[5];
    const int* idx  = (const int*)d_in[6];
    int u = in_sizes[6];
    if (u > UMAX) u = UMAX;
    if (u < 1) u = 1;
    float* y = (float*)d_out;

    float *qsp, *sc, *rsum, *wxp, *ctx, *ys;
    bf16 *xsh, *xsl, *Wqh, *Wql, *WkTh, *WkTl, *Wvh, *Wvl, *Woh, *Wol;
    bf16 *Qsh, *Qsl, *Qth, *Qtl, *xh, *xl, *wxh, *wxl, *crh, *crl;
    __half *xthh, *xthl, *ahf;
    cudaGetSymbolAddress((void**)&xsh,  g_xsh);
    cudaGetSymbolAddress((void**)&xsl,  g_xsl);
    cudaGetSymbolAddress((void**)&Wqh,  g_Wqh);
    cudaGetSymbolAddress((void**)&Wql,  g_Wql);
    cudaGetSymbolAddress((void**)&WkTh, g_WkTh);
    cudaGetSymbolAddress((void**)&WkTl, g_WkTl);
    cudaGetSymbolAddress((void**)&Wvh,  g_Wvh);
    cudaGetSymbolAddress((void**)&Wvl,  g_Wvl);
    cudaGetSymbolAddress((void**)&Woh,  g_Woh);
    cudaGetSymbolAddress((void**)&Wol,  g_Wol);
    cudaGetSymbolAddress((void**)&qsp,  g_qsp);
    cudaGetSymbolAddress((void**)&Qsh,  g_Qsh);
    cudaGetSymbolAddress((void**)&Qsl,  g_Qsl);
    cudaGetSymbolAddress((void**)&Qth,  g_Qth);
    cudaGetSymbolAddress((void**)&Qtl,  g_Qtl);
    cudaGetSymbolAddress((void**)&xh,   g_xh);
    cudaGetSymbolAddress((void**)&xl,   g_xl);
    cudaGetSymbolAddress((void**)&xthh, g_xthh);
    cudaGetSymbolAddress((void**)&xthl, g_xthl);
    cudaGetSymbolAddress((void**)&sc,   g_sc);
    cudaGetSymbolAddress((void**)&ahf,  g_ahf);
    cudaGetSymbolAddress((void**)&rsum, g_rsum);
    cudaGetSymbolAddress((void**)&wxp,  g_wxp);
    cudaGetSymbolAddress((void**)&wxh,  g_wxh);
    cudaGetSymbolAddress((void**)&wxl,  g_wxl);
    cudaGetSymbolAddress((void**)&ctx,  g_ctx);
    cudaGetSymbolAddress((void**)&crh,  g_crh);
    cudaGetSymbolAddress((void**)&crl,  g_crl);
    cudaGetSymbolAddress((void**)&ys,   g_ys);

    const int Hu = Hh * u;
    const int mp = ((Hu + 127) / 128) * 128;
    const int Bu = Bb * u;
    const int bup = ((Bu + 127) / 128) * 128;
    const float scale = 0.125f;

    const int smem_n = NSTAGE * (int)STG_SZ;   // 98304
    cudaFuncSetAttribute(mma_gemm_k<0>, cudaFuncAttributeMaxDynamicSharedMemorySize, smem_n);
    cudaFuncSetAttribute(mma_gemm_k<1>, cudaFuncAttributeMaxDynamicSharedMemorySize, smem_n);
    cudaFuncSetAttribute(mma_f16_2t_k, cudaFuncAttributeMaxDynamicSharedMemorySize, smem_n);

    // 0) conversions
    convx_k<<<dim3(Tt / 32, Dd / 32, Bb), 256>>>(x, xh, xl, xthh, xthl);
    convw3_k<<<dim3(256, 3), 256>>>(Wq, Wqh, Wql, Wv, Wvh, Wvl, Wo, Woh, Wol);
    convwT_k<<<dim3(32, 32), 256>>>(Wk, WkTh, WkTl, scale);

    // 1) gather+split x rows at idx
    gather_xs_k<<<Bb * u, 256>>>(xsh, xsl, (const float4*)x, idx, u);

    // 2) Qs partials = xs @ Wq^T   (split-K=4)
    mma_gemm_k<0><<<dim3(Dd / BNt, bup / BMt, 4), 256, smem_n>>>(
        qsp, nullptr, nullptr, xsh, xsl, Wqh, Wql,
        256, Dd, Dd, Dd, Bu, Dd,
        0, 0, 0, 0, 0, 0, 1, 4, (ll)bup * Dd);
    redsplit4_k<<<512, 256>>>(qsp, Qsh, Qsl, Bu * Dd, bup * Dd);

    // 3) Qt[b,h] = Qs[b](cols h*64..) @ (scale*Wk_h)  -> bf16 hi/lo padded
    mma_gemm_k<1><<<dim3(Dd / BNt, 1, Bb * Hh), 256, smem_n>>>(
        nullptr, Qth, Qtl, Qsh, Qsl, WkTh, WkTl,
        DHh, Dd, Dd, Dd, u, Dd,
        (ll)u * Dd, (ll)DHh, 0, (ll)DHh, (ll)mp * Dd, (ll)u * Dd, Hh, 1, 0);

    // 4) scores[b] = Qt[b] @ x[b]^T   (bf16 3-term; only real Hu rows stored)
    mma_gemm_k<0><<<dim3(Tt / BNt, mp / BMt, Bb), 256, smem_n>>>(
        sc, nullptr, nullptr, Qth, Qtl, xh, xl,
        Dd, Dd, Dd, Tt, Hu, Tt,
        (ll)mp * Dd, 0, (ll)Tt * Dd, 0, (ll)mp * Tt, 0, 1, 1, 0);

    // 5) softmax -> unnormalized exp (single fp16) + row sums
    softmax_k<<<Bb * Hu, 256>>>(sc, ahf, rsum, Hu, mp);

    // 6) wx partials = e[b] @ x[b]   (fp16 2-term, split-K=2, B = x^T fp16 pair)
    mma_f16_2t_k<<<dim3(Dd / BNt, mp / BMt, Bb * 2), 256, smem_n>>>(
        wxp, ahf, xthh, xthl,
        Tt / 2, Tt, Tt, Dd, mp, Dd,
        (ll)mp * Tt, (ll)Dd * Tt, (ll)mp * Dd, 2, (ll)Bb * mp * Dd);
    redsplit2_k<<<1024, 256>>>(wxp, wxh, wxl, Bb * mp * Dd, (ll)Bb * mp * Dd);

    // 7) ctx[b,h] = wx[b,h] @ Wv_h^T   (bf16 3-term, fp32 out)
    mma_gemm_k<0><<<dim3(1, 1, Bb * Hh), 256, smem_n>>>(
        ctx, nullptr, nullptr, wxh, wxl, Wvh, Wvl,
        Dd, Dd, Dd, DHh, u, DHh,
        (ll)mp * Dd, (ll)u * Dd, 0, (ll)DHh * Dd, (ll)Hh * u * DHh, (ll)u * DHh, Hh, 1, 0);

    // 8) reorder ctx + normalize + mean row -> bf16 split
    ctxrow_mean_k<<<dim3(Bb, Hh), 64>>>(crh, crl, ctx, rsum, u, Hu);

    // 9) ys = cr @ Wo^T   (fp32 out)
    mma_gemm_k<0><<<dim3(Dd / BNt, 1, Bb), 256, smem_n>>>(
        ys, nullptr, nullptr, crh, crl, Woh, Wol,
        Dd, Dd, Dd, Dd, u + 1, Dd,
        (ll)(u + 1) * Dd, 0, 0, 0, (ll)(u + 1) * Dd, 0, 1, 1, 0);

    // 10) broadcast + scatter
    fill_k<<<Bb * (Tt / 8), 256>>>((float4*)y, (const float4*)ys, (const float4*)bo, u);
    scatter_k<<<dim3(Bb, u), 256>>>((float4*)y, (const float4*)ys, (const float4*)bo, idx, u);
}

// round 15
// speedup vs baseline: 1.6170x; 1.1278x over previous
#include <cuda_runtime.h>
#include <cuda_bf16.h>
#include <cuda_fp16.h>
#include <cstdint>

#define Bb   8
#define Tt   4096
#define Dd   1024
#define Hh   16
#define DHh  64
#define UMAX 64
#define MPMAX 1024
#define BUPMAX 512

typedef long long ll;
typedef __nv_bfloat16 bf16;

// ---------------- scratch (static __device__, allocation-free) ----------------
__device__ bf16  g_xsh[Bb * UMAX * Dd];
__device__ bf16  g_xsl[Bb * UMAX * Dd];
__device__ bf16  g_Wqh[Dd * Dd];
__device__ bf16  g_Wql[Dd * Dd];
__device__ bf16  g_WkTh[Dd * Dd];
__device__ bf16  g_WkTl[Dd * Dd];
__device__ bf16  g_Wvh[(Dd + 128) * Dd];     // row-padded for OOB-safe tile loads
__device__ bf16  g_Wvl[(Dd + 128) * Dd];
__device__ bf16  g_Woh[Dd * Dd];
__device__ bf16  g_Wol[Dd * Dd];
__device__ float g_qsp[4 * BUPMAX * Dd];     // step-2 split-K partials
__device__ bf16  g_Qsh[Bb * UMAX * Dd];
__device__ bf16  g_Qsl[Bb * UMAX * Dd];
__device__ __half g_Qth[(size_t)Bb * MPMAX * Dd];   // Qt fp16 hi
__device__ __half g_Qtl[(size_t)Bb * MPMAX * Dd];   // Qt fp16 lo
__device__ __half g_xf[(size_t)Bb * Tt * Dd];       // x straight, single fp16
__device__ __half g_xthh[(size_t)Bb * Dd * Tt];     // x^T fp16 hi
__device__ __half g_xthl[(size_t)Bb * Dd * Tt];     // x^T fp16 lo
__device__ float g_sc[(size_t)Bb * MPMAX * Tt];
__device__ __half g_ahf[(size_t)Bb * MPMAX * Tt];   // exp weights, single fp16
__device__ float g_rsum[Bb * Hh * UMAX];
__device__ float g_wxp[(size_t)2 * Bb * MPMAX * Dd];  // step-6 split-K partials
__device__ bf16  g_wxh[(size_t)Bb * MPMAX * Dd];
__device__ bf16  g_wxl[(size_t)Bb * MPMAX * Dd];
__device__ float g_ctx[Bb * Hh * UMAX * DHh];
__device__ bf16  g_crh[Bb * (UMAX + 2) * Dd];
__device__ bf16  g_crl[Bb * (UMAX + 2) * Dd];
__device__ float g_ys[Bb * (UMAX + 1) * Dd];

// ---------------- PTX helpers (sm_80/sm_90 portable only) ----------------
__device__ __forceinline__ uint32_t smem_u32(const void* p) {
    uint32_t a;
    asm("{ .reg .u64 t; cvta.to.shared.u64 t, %1; cvt.u32.u64 %0, t; }" : "=r"(a) : "l"(p));
    return a;
}
__device__ __forceinline__ void cp_async16(uint32_t s, const void* g) {
    asm volatile("cp.async.cg.shared.global [%0], [%1], 16;" :: "r"(s), "l"(g) : "memory");
}
__device__ __forceinline__ void ldsm_x4(uint32_t* r, uint32_t a) {
    asm volatile("ldmatrix.sync.aligned.m8n8.x4.shared.b16 {%0,%1,%2,%3}, [%4];"
                 : "=r"(r[0]), "=r"(r[1]), "=r"(r[2]), "=r"(r[3]) : "r"(a));
}
__device__ __forceinline__ void mma16816(float* c, const uint32_t* a, const uint32_t* b) {
    asm volatile(
        "mma.sync.aligned.m16n8k16.row.col.f32.bf16.bf16.f32 "
        "{%0,%1,%2,%3}, {%4,%5,%6,%7}, {%8,%9}, {%0,%1,%2,%3};"
        : "+f"(c[0]), "+f"(c[1]), "+f"(c[2]), "+f"(c[3])
        : "r"(a[0]), "r"(a[1]), "r"(a[2]), "r"(a[3]), "r"(b[0]), "r"(b[1]));
}
__device__ __forceinline__ void mma16816h(float* c, const uint32_t* a, const uint32_t* b) {
    asm volatile(
        "mma.sync.aligned.m16n8k16.row.col.f32.f16.f16.f32 "
        "{%0,%1,%2,%3}, {%4,%5,%6,%7}, {%8,%9}, {%0,%1,%2,%3};"
        : "+f"(c[0]), "+f"(c[1]), "+f"(c[2]), "+f"(c[3])
        : "r"(a[0]), "r"(a[1]), "r"(a[2]), "r"(a[3]), "r"(b[0]), "r"(b[1]));
}

__device__ __forceinline__ void split2(float v, bf16& h, bf16& l) {
    h = __float2bfloat16(v);
    l = __float2bfloat16(v - __bfloat162float(h));
}
__device__ __forceinline__ void packpair(float a, float b,
                                         __nv_bfloat162& hp, __nv_bfloat162& lp) {
    bf16 h0, l0, h1, l1; split2(a, h0, l0); split2(b, h1, l1);
    hp.x = h0; hp.y = h1; lp.x = l0; lp.y = l1;
}
__device__ __forceinline__ void packpairh(float a, float b,
                                          __half2& hp, __half2& lp) {
    __half h0 = __float2half_rn(a), h1 = __float2half_rn(b);
    __half l0 = __float2half_rn(a - __half2float(h0));
    __half l1 = __float2half_rn(b - __half2float(h1));
    hp = __halves2half2(h0, h1);
    lp = __halves2half2(l0, l1);
}

// ============ narrow merged-pass warp-MMA GEMM, bf16 3-term ============
// EPI=0: fp32 C out.  EPI=1: fp16 hi/lo split C out (Ch, Cl).
#define BMt 128
#define BNt 128
#define STG_SZ 32768u
#define NSTAGE 3

template <int EPI>
__global__ __launch_bounds__(256, 2) void mma_gemm_k(
    float* __restrict__ C, __half* __restrict__ Ch, __half* __restrict__ Cl,
    const bf16* __restrict__ Ah, const bf16* __restrict__ Al,
    const bf16* __restrict__ Bh, const bf16* __restrict__ Bl,
    int Kext, int lda, int ldb, int ldc, int Mreal, int Nreal,
    ll sAb, ll sAh, ll sBb, ll sBh, ll sCb, ll sCh,
    int nh, int KS, ll sCs) {
    extern __shared__ char smem[];
    uint32_t sbase = smem_u32(smem);
    int tid = threadIdx.x, wid = tid >> 5, lane = tid & 31;
    int z = blockIdx.z;
    int ks = z % KS, bh2 = z / KS;
    int hh = bh2 % nh, bb = bh2 / nh;
    int m0 = blockIdx.y * BMt, n0 = blockIdx.x * BNt;

    const bf16* A0 = Ah + bb * sAb + hh * sAh + (ll)ks * Kext + (size_t)m0 * lda;
    const bf16* A1 = Al + bb * sAb + hh * sAh + (ll)ks * Kext + (size_t)m0 * lda;
    const bf16* B0 = Bh + bb * sBb + hh * sBh + (ll)ks * Kext + (size_t)n0 * ldb;
    const bf16* B1 = Bl + bb * sBb + hh * sBh + (ll)ks * Kext + (size_t)n0 * ldb;

    int row = tid >> 1, cq = tid & 1, rx = row & 7;
    size_t   gA0 = (size_t)row * lda + cq * 8, gA1 = gA0 + 16;
    size_t   gB0 = (size_t)row * ldb + cq * 8, gB1 = gB0 + 16;
    uint32_t dh0 = row * 128 + ((cq)     ^ rx) * 16;
    uint32_t dh1 = row * 128 + ((cq + 2) ^ rx) * 16;
    uint32_t dl0 = row * 128 + ((cq + 4) ^ rx) * 16;
    uint32_t dl1 = row * 128 + ((cq + 6) ^ rx) * 16;

    int warp_m = wid >> 2, warp_n = wid & 3;
    int rl = lane & 15, cl = lane >> 4, arx = lane & 7;
    int rb = lane & 7,  cb = (lane >> 3) & 1;
    uint32_t arow[4], b4row[2];
#pragma unroll
    for (int i = 0; i < 4; i++) arow[i] = (warp_m * 64 + i * 16 + rl) * 128;
#pragma unroll
    for (int j2 = 0; j2 < 2; j2++)
        b4row[j2] = (warp_n * 32 + (j2 * 2 + (lane >> 4)) * 8 + rb) * 128;

    float acc[4][4][4];
#pragma unroll
    for (int i = 0; i < 4; i++)
#pragma unroll
        for (int j = 0; j < 4; j++)
#pragma unroll
            for (int q = 0; q < 4; q++) acc[i][j][q] = 0.f;

    const int NC = Kext >> 5;

#define ISSUE(c_) do {                                                        \
    size_t ko_ = (size_t)(c_) * 32;                                           \
    uint32_t st_ = sbase + ((c_) % NSTAGE) * STG_SZ;                          \
    cp_async16(st_ + dh0, A0 + ko_ + gA0);                                    \
    cp_async16(st_ + dh1, A0 + ko_ + gA1);                                    \
    cp_async16(st_ + dl0, A1 + ko_ + gA0);                                    \
    cp_async16(st_ + dl1, A1 + ko_ + gA1);                                    \
    cp_async16(st_ + 16384u + dh0, B0 + ko_ + gB0);                           \
    cp_async16(st_ + 16384u + dh1, B0 + ko_ + gB1);                           \
    cp_async16(st_ + 16384u + dl0, B1 + ko_ + gB0);                           \
    cp_async16(st_ + 16384u + dl1, B1 + ko_ + gB1);                           \
    asm volatile("cp.async.commit_group;" ::: "memory");                      \
} while (0)

    ISSUE(0);
    if (NC > 1) ISSUE(1);

    for (int c = 0; c < NC; c++) {
        if (c + 1 < NC) asm volatile("cp.async.wait_group 1;" ::: "memory");
        else            asm volatile("cp.async.wait_group 0;" ::: "memory");
        __syncthreads();
        if (c + 2 < NC) ISSUE(c + 2);

        uint32_t sa = sbase + (c % NSTAGE) * STG_SZ;
        uint32_t sb = sa + 16384u;
#pragma unroll
        for (int kk = 0; kk < 2; kk++) {
            uint32_t bh[4][2], blo[4][2], af[4][4];
#pragma unroll
            for (int j2 = 0; j2 < 2; j2++)
                ldsm_x4(&bh[j2 * 2][0],  sb + b4row[j2] + (((kk * 2 + cb)     ^ rb) << 4));
#pragma unroll
            for (int j2 = 0; j2 < 2; j2++)
                ldsm_x4(&blo[j2 * 2][0], sb + b4row[j2] + (((kk * 2 + cb + 4) ^ rb) << 4));
#pragma unroll
            for (int i = 0; i < 4; i++)
                ldsm_x4(af[i], sa + arow[i] + (((kk * 2 + cl)     ^ arx) << 4));
#pragma unroll
            for (int i = 0; i < 4; i++)
#pragma unroll
                for (int j = 0; j < 4; j++) mma16816(acc[i][j], af[i], bh[j]);
#pragma unroll
            for (int i = 0; i < 4; i++)
#pragma unroll
                for (int j = 0; j < 4; j++) mma16816(acc[i][j], af[i], blo[j]);
#pragma unroll
            for (int i = 0; i < 4; i++)
                ldsm_x4(af[i], sa + arow[i] + (((kk * 2 + cl + 4) ^ arx) << 4));
#pragma unroll
            for (int i = 0; i < 4; i++)
#pragma unroll
                for (int j = 0; j < 4; j++) mma16816(acc[i][j], af[i], bh[j]);
        }
    }

    ll cbase = bb * sCb + hh * sCh + (ll)ks * sCs;
#pragma unroll
    for (int i = 0; i < 4; i++) {
        int m = m0 + warp_m * 64 + i * 16 + (lane >> 2);
#pragma unroll
        for (int j = 0; j < 4; j++) {
            int n = n0 + warp_n * 32 + j * 8 + (lane & 3) * 2;
            if (n < Nreal) {
#pragma unroll
                for (int p = 0; p < 2; p++) {
                    int mm = m + p * 8;
                    if (mm < Mreal) {
                        if (EPI == 0) {
                            *(float2*)&C[cbase + (size_t)mm * ldc + n] =
                                make_float2(acc[i][j][p * 2], acc[i][j][p * 2 + 1]);
                        } else {
                            __half2 hp, lp;
                            packpairh(acc[i][j][p * 2], acc[i][j][p * 2 + 1], hp, lp);
                            *(__half2*)&Ch[cbase + (size_t)mm * ldc + n] = hp;
                            *(__half2*)&Cl[cbase + (size_t)mm * ldc + n] = lp;
                        }
                    }
                }
            }
        }
    }
}

// ============ fp16 2-term warp-MMA GEMM ============
// APAIR=0: C = A @ (Bh + Bl)^T    (A single fp16; step 6)
// APAIR=1: C = (Ah + Al) @ B^T    (B single fp16; step 4)
template <int APAIR>
__global__ __launch_bounds__(256, 2) void mma_f16_2t_k(
    float* __restrict__ C,
    const __half* __restrict__ Aa, const __half* __restrict__ Ab,
    const __half* __restrict__ Ba, const __half* __restrict__ Bbp,
    int Kext, int lda, int ldb, int ldc, int Mreal, int Nreal,
    ll sAb, ll sBb, ll sCb, int KS, ll sCs) {
    extern __shared__ char smem[];
    uint32_t sbase = smem_u32(smem);
    int tid = threadIdx.x, wid = tid >> 5, lane = tid & 31;
    int z = blockIdx.z;
    int ks = z % KS, bb = z / KS;
    int m0 = blockIdx.y * BMt, n0 = blockIdx.x * BNt;

    const __half* A0 = Aa + bb * sAb + (ll)ks * Kext + (size_t)m0 * lda;
    const __half* A1 = (APAIR ? Ab + bb * sAb + (ll)ks * Kext + (size_t)m0 * lda : nullptr);
    const __half* B0 = Ba + bb * sBb + (ll)ks * Kext + (size_t)n0 * ldb;
    const __half* B1 = (APAIR ? nullptr : Bbp + bb * sBb + (ll)ks * Kext + (size_t)n0 * ldb);

    int row = tid >> 1, cq = tid & 1, rx = row & 7;
    size_t   gA0 = (size_t)row * lda + cq * 8, gA1 = gA0 + 16;
    size_t   gB0 = (size_t)row * ldb + cq * 8, gB1 = gB0 + 16;
    uint32_t dh0 = row * 128 + ((cq)     ^ rx) * 16;
    uint32_t dh1 = row * 128 + ((cq + 2) ^ rx) * 16;
    uint32_t dl0 = row * 128 + ((cq + 4) ^ rx) * 16;
    uint32_t dl1 = row * 128 + ((cq + 6) ^ rx) * 16;

    int warp_m = wid >> 2, warp_n = wid & 3;
    int rl = lane & 15, cl = lane >> 4, arx = lane & 7;
    int rb = lane & 7,  cb = (lane >> 3) & 1;
    uint32_t arow[4], b4row[2];
#pragma unroll
    for (int i = 0; i < 4; i++) arow[i] = (warp_m * 64 + i * 16 + rl) * 128;
#pragma unroll
    for (int j2 = 0; j2 < 2; j2++)
        b4row[j2] = (warp_n * 32 + (j2 * 2 + (lane >> 4)) * 8 + rb) * 128;

    float acc[4][4][4];
#pragma unroll
    for (int i = 0; i < 4; i++)
#pragma unroll
        for (int j = 0; j < 4; j++)
#pragma unroll
            for (int q = 0; q < 4; q++) acc[i][j][q] = 0.f;

    const int NC = Kext >> 5;

#define ISSUE2(c_) do {                                                       \
    size_t ko_ = (size_t)(c_) * 32;                                           \
    uint32_t st_ = sbase + ((c_) % NSTAGE) * STG_SZ;                          \
    cp_async16(st_ + dh0, A0 + ko_ + gA0);                                    \
    cp_async16(st_ + dh1, A0 + ko_ + gA1);                                    \
    if (APAIR) {                                                              \
        cp_async16(st_ + dl0, A1 + ko_ + gA0);                                \
        cp_async16(st_ + dl1, A1 + ko_ + gA1);                                \
    }                                                                         \
    cp_async16(st_ + 16384u + dh0, B0 + ko_ + gB0);                           \
    cp_async16(st_ + 16384u + dh1, B0 + ko_ + gB1);                           \
    if (!APAIR) {                                                             \
        cp_async16(st_ + 16384u + dl0, B1 + ko_ + gB0);                       \
        cp_async16(st_ + 16384u + dl1, B1 + ko_ + gB1);                       \
    }                                                                         \
    asm volatile("cp.async.commit_group;" ::: "memory");                      \
} while (0)

    ISSUE2(0);
    if (NC > 1) ISSUE2(1);

    for (int c = 0; c < NC; c++) {
        if (c + 1 < NC) asm volatile("cp.async.wait_group 1;" ::: "memory");
        else            asm volatile("cp.async.wait_group 0;" ::: "memory");
        __syncthreads();
        if (c + 2 < NC) ISSUE2(c + 2);

        uint32_t sa = sbase + (c % NSTAGE) * STG_SZ;
        uint32_t sb = sa + 16384u;
#pragma unroll
        for (int kk = 0; kk < 2; kk++) {
            uint32_t bh[4][2], blo[4][2], af[4][4], af2[4][4];
#pragma unroll
            for (int j2 = 0; j2 < 2; j2++)
                ldsm_x4(&bh[j2 * 2][0], sb + b4row[j2] + (((kk * 2 + cb) ^ rb) << 4));
            if (!APAIR) {
#pragma unroll
                for (int j2 = 0; j2 < 2; j2++)
                    ldsm_x4(&blo[j2 * 2][0], sb + b4row[j2] + (((kk * 2 + cb + 4) ^ rb) << 4));
            }
#pragma unroll
            for (int i = 0; i < 4; i++)
                ldsm_x4(af[i], sa + arow[i] + (((kk * 2 + cl) ^ arx) << 4));
            if (APAIR) {
#pragma unroll
                for (int i = 0; i < 4; i++)
                    ldsm_x4(af2[i], sa + arow[i] + (((kk * 2 + cl + 4) ^ arx) << 4));
            }
#pragma unroll
            for (int i = 0; i < 4; i++)
#pragma unroll
                for (int j = 0; j < 4; j++) mma16816h(acc[i][j], af[i], bh[j]);
            if (APAIR) {
#pragma unroll
                for (int i = 0; i < 4; i++)
#pragma unroll
                    for (int j = 0; j < 4; j++) mma16816h(acc[i][j], af2[i], bh[j]);
            } else {
#pragma unroll
                for (int i = 0; i < 4; i++)
#pragma unroll
                    for (int j = 0; j < 4; j++) mma16816h(acc[i][j], af[i], blo[j]);
            }
        }
    }

    ll cbase = bb * sCb + (ll)ks * sCs;
#pragma unroll
    for (int i = 0; i < 4; i++) {
        int m = m0 + warp_m * 64 + i * 16 + (lane >> 2);
#pragma unroll
        for (int j = 0; j < 4; j++) {
            int n = n0 + warp_n * 32 + j * 8 + (lane & 3) * 2;
            if (n < Nreal) {
#pragma unroll
                for (int p = 0; p < 2; p++) {
                    int mm = m + p * 8;
                    if (mm < Mreal) {
                        *(float2*)&C[cbase + (size_t)mm * ldc + n] =
                            make_float2(acc[i][j][p * 2], acc[i][j][p * 2 + 1]);
                    }
                }
            }
        }
    }
}

// ---------------- x -> single fp16 straight + fp16 hi/lo transposed ----------------
__global__ __launch_bounds__(256) void convx_k(const float* __restrict__ x,
                                               __half* __restrict__ xf,
                                               __half* __restrict__ xth,
                                               __half* __restrict__ xtl) {
    __shared__ float ts[32][33];
    int b = blockIdx.z;
    int t0 = blockIdx.x * 32, d0 = blockIdx.y * 32;
    int tid = threadIdx.x;
    int r = tid >> 4, p = tid & 15;
#pragma unroll
    for (int it = 0; it < 2; it++) {
        int rr = r + it * 16;
        size_t o = ((size_t)b * Tt + t0 + rr) * Dd + d0 + 2 * p;
        float2 v = *(const float2*)(x + o);
        *(__half2*)(xf + o) = __floats2half2_rn(v.x, v.y);
        ts[rr][2 * p] = v.x; ts[rr][2 * p + 1] = v.y;
    }
    __syncthreads();
#pragma unroll
    for (int it = 0; it < 2; it++) {
        int dr = r + it * 16;
        float v0 = ts[2 * p][dr], v1 = ts[2 * p + 1][dr];
        __half2 hp, lp; packpairh(v0, v1, hp, lp);
        size_t o = ((size_t)b * Dd + d0 + dr) * Tt + t0 + 2 * p;
        *(__half2*)(xth + o) = hp;
        *(__half2*)(xtl + o) = lp;
    }
}

// ---------------- three straight weight conversions in one launch ----------------
__global__ __launch_bounds__(256) void convw3_k(
    const float* __restrict__ Wq, bf16* __restrict__ Wqh, bf16* __restrict__ Wql,
    const float* __restrict__ Wv, bf16* __restrict__ Wvh, bf16* __restrict__ Wvl,
    const float* __restrict__ Wo, bf16* __restrict__ Woh, bf16* __restrict__ Wol) {
    const float* W; bf16 *Wh, *Wl;
    if (blockIdx.y == 0)      { W = Wq; Wh = Wqh; Wl = Wql; }
    else if (blockIdx.y == 1) { W = Wv; Wh = Wvh; Wl = Wvl; }
    else                      { W = Wo; Wh = Woh; Wl = Wol; }
    for (int i = (blockIdx.x * 256 + threadIdx.x) * 2; i < Dd * Dd; i += gridDim.x * 512) {
        float2 v = *(const float2*)(W + i);
        __nv_bfloat162 hp, lp; packpair(v.x, v.y, hp, lp);
        *(__nv_bfloat162*)(Wh + i) = hp;
        *(__nv_bfloat162*)(Wl + i) = lp;
    }
}

// ---------------- weight fp32 -> transposed + scaled bf16 hi/lo ----------------
__global__ __launch_bounds__(256) void convwT_k(const float* __restrict__ W,
                                                bf16* __restrict__ Wh, bf16* __restrict__ Wl,
                                                float alpha) {
    __shared__ float ts[32][33];
    int r0 = blockIdx.x * 32, c0 = blockIdx.y * 32;
    int tx = threadIdx.x & 31, ty = threadIdx.x >> 5;
#pragma unroll
    for (int i = 0; i < 4; i++) {
        int rr = ty * 4 + i;
        ts[rr][tx] = W[(size_t)(r0 + rr) * Dd + c0 + tx];
    }
    __syncthreads();
    int r = threadIdx.x >> 4, p = threadIdx.x & 15;
#pragma unroll
    for (int it = 0; it < 2; it++) {
        int c = r + it * 16;
        float v0 = alpha * ts[2 * p][c], v1 = alpha * ts[2 * p + 1][c];
        __nv_bfloat162 hp, lp; packpair(v0, v1, hp, lp);
        size_t o = (size_t)(c0 + c) * Dd + r0 + 2 * p;
        *(__nv_bfloat162*)(Wh + o) = hp;
        *(__nv_bfloat162*)(Wl + o) = lp;
    }
}

// ---------------- gather x rows at idx, split to bf16 hi/lo ----------------
__global__ __launch_bounds__(256) void gather_xs_k(bf16* __restrict__ xsh,
                                                   bf16* __restrict__ xsl,
                                                   const float4* __restrict__ x,
                                                   const int* __restrict__ idx, int u) {
    int b = blockIdx.x / u, j = blockIdx.x % u;
    int t = idx[j];
    float4 v = x[((size_t)b * Tt + t) * (Dd / 4) + threadIdx.x];
    size_t o = ((size_t)b * u + j) * Dd + threadIdx.x * 4;
    __nv_bfloat162 hp, lp;
    packpair(v.x, v.y, hp, lp);
    *(__nv_bfloat162*)(xsh + o) = hp;
    *(__nv_bfloat162*)(xsl + o) = lp;
    packpair(v.z, v.w, hp, lp);
    *(__nv_bfloat162*)(xsh + o + 2) = hp;
    *(__nv_bfloat162*)(xsl + o + 2) = lp;
}

// ---------------- split-K reduce (4-way) -> bf16 hi/lo ----------------
__global__ __launch_bounds__(256) void redsplit4_k(const float* __restrict__ p,
                                                   bf16* __restrict__ oh, bf16* __restrict__ ol,
                                                   int n, int stride) {
    for (int i = (blockIdx.x * 256 + threadIdx.x) * 2; i < n; i += gridDim.x * 512) {
        float2 a0 = *(const float2*)(p + i);
        float2 a1 = *(const float2*)(p + i + stride);
        float2 a2 = *(const float2*)(p + i + 2 * stride);
        float2 a3 = *(const float2*)(p + i + 3 * stride);
        __nv_bfloat162 hp, lp;
        packpair(a0.x + a1.x + a2.x + a3.x, a0.y + a1.y + a2.y + a3.y, hp, lp);
        *(__nv_bfloat162*)(oh + i) = hp;
        *(__nv_bfloat162*)(ol + i) = lp;
    }
}

// ---------------- split-K reduce (2-way) -> bf16 hi/lo ----------------
__global__ __launch_bounds__(256) void redsplit2_k(const float* __restrict__ p,
                                                   bf16* __restrict__ oh, bf16* __restrict__ ol,
                                                   int n, ll stride) {
    for (int i = (blockIdx.x * 256 + threadIdx.x) * 2; i < n; i += gridDim.x * 512) {
        float2 a0 = *(const float2*)(p + i);
        float2 a1 = *(const float2*)(p + i + stride);
        __nv_bfloat162 hp, lp;
        packpair(a0.x + a1.x, a0.y + a1.y, hp, lp);
        *(__nv_bfloat162*)(oh + i) = hp;
        *(__nv_bfloat162*)(ol + i) = lp;
    }
}

// ---------------- softmax: UNNORMALIZED exp -> single fp16 + row sums ----------------
__global__ __launch_bounds__(256) void softmax_k(const float* __restrict__ s,
                                                 __half* __restrict__ ah,
                                                 float* __restrict__ rsum, int Hu, int mp) {
    __shared__ float red[256];
    int b = blockIdx.x / Hu, r = blockIdx.x % Hu;
    size_t base = ((size_t)b * mp + r) * Tt;
    int tid = threadIdx.x;
    float m = -3.4e38f;
    for (int t = tid * 2; t < Tt; t += 512) {
        float2 v = *(const float2*)(s + base + t);
        m = fmaxf(m, fmaxf(v.x, v.y));
    }
    red[tid] = m; __syncthreads();
    for (int o = 128; o > 0; o >>= 1) {
        if (tid < o) red[tid] = fmaxf(red[tid], red[tid + o]);
        __syncthreads();
    }
    float mx = red[0];
    __syncthreads();
    float sum = 0.f;
    for (int t = tid * 2; t < Tt; t += 512) {
        float2 v = *(const float2*)(s + base + t);
        float e0 = __expf(v.x - mx), e1 = __expf(v.y - mx);
        sum += e0 + e1;
        *(__half2*)(ah + base + t) = __floats2half2_rn(e0, e1);
    }
    red[tid] = sum; __syncthreads();
    for (int o = 128; o > 0; o >>= 1) {
        if (tid < o) red[tid] += red[tid + o];
        __syncthreads();
    }
    if (tid == 0) rsum[blockIdx.x] = red[0];
}

// ---------------- ctx -> per-token rows (normalized) + mean row, bf16 split ----------------
__global__ __launch_bounds__(64) void ctxrow_mean_k(bf16* __restrict__ crh,
                                                    bf16* __restrict__ crl,
                                                    const float* __restrict__ ctx,
                                                    const float* __restrict__ rsum,
                                                    int u, int Hu) {
    int b = blockIdx.x, h = blockIdx.y, d = threadIdx.x;
    float s = 0.f;
    for (int j = 0; j < u; j++) {
        float inv = 1.f / rsum[b * Hu + h * u + j];
        float v = ctx[((size_t)(b * Hh + h) * u + j) * DHh + d] * inv;
        bf16 hh, ll2; split2(v, hh, ll2);
        size_t o = ((size_t)b * (u + 1) + j) * Dd + h * DHh + d;
        crh[o] = hh; crl[o] = ll2;
        s += v;
    }
    bf16 hh, ll2; split2(s / (float)u, hh, ll2);
    size_t o = ((size_t)b * (u + 1) + u) * Dd + h * DHh + d;
    crh[o] = hh; crl[o] = ll2;
}

// ---------------- broadcast fill (8 rows/block) + scatter ----------------
__global__ __launch_bounds__(256) void fill_k(float4* __restrict__ y,
                                              const float4* __restrict__ ys,
                                              const float4* __restrict__ bo, int u) {
    int b = blockIdx.x / (Tt / 8);
    int tt0 = (blockIdx.x % (Tt / 8)) * 8;
    float4 v = ys[((size_t)b * (u + 1) + u) * 256 + threadIdx.x];
    float4 bb = bo[threadIdx.x];
    float4 o = make_float4(v.x + bb.x, v.y + bb.y, v.z + bb.z, v.w + bb.w);
    size_t base = ((size_t)b * Tt + tt0) * 256 + threadIdx.x;
#pragma unroll
    for (int i = 0; i < 8; i++) y[base + (size_t)i * 256] = o;
}
__global__ __launch_bounds__(256) void scatter_k(float4* __restrict__ y,
                                                 const float4* __restrict__ ys,
                                                 const float4* __restrict__ bo,
                                                 const int* __restrict__ idx, int u) {
    int b = blockIdx.x, j = blockIdx.y;
    int t = idx[j];
    float4 v = ys[((size_t)b * (u + 1) + j) * 256 + threadIdx.x];
    float4 bb = bo[threadIdx.x];
    y[((size_t)b * Tt + t) * 256 + threadIdx.x] =
        make_float4(v.x + bb.x, v.y + bb.y, v.z + bb.z, v.w + bb.w);
}

// ---------------- launch ----------------
extern "C" void kernel_launch(void* const* d_in, const int* in_sizes, int n_in,
                              void* d_out, int out_size) {
    const float* x  = (const float*)d_in[0];
    const float* Wq = (const float*)d_in[1];
    const float* Wk = (const float*)d_in[2];
    const float* Wv = (const float*)d_in[3];
    const float* Wo = (const float*)d_in[4];
    const float* bo = (const float*)d_in[5];
    const int* idx  = (const int*)d_in[6];
    int u = in_sizes[6];
    if (u > UMAX) u = UMAX;
    if (u < 1) u = 1;
    float* y = (float*)d_out;

    float *qsp, *sc, *rsum, *wxp, *ctx, *ys;
    bf16 *xsh, *xsl, *Wqh, *Wql, *WkTh, *WkTl, *Wvh, *Wvl, *Woh, *Wol;
    bf16 *Qsh, *Qsl, *wxh, *wxl, *crh, *crl;
    __half *Qth, *Qtl, *xf, *xthh, *xthl, *ahf;
    cudaGetSymbolAddress((void**)&xsh,  g_xsh);
    cudaGetSymbolAddress((void**)&xsl,  g_xsl);
    cudaGetSymbolAddress((void**)&Wqh,  g_Wqh);
    cudaGetSymbolAddress((void**)&Wql,  g_Wql);
    cudaGetSymbolAddress((void**)&WkTh, g_WkTh);
    cudaGetSymbolAddress((void**)&WkTl, g_WkTl);
    cudaGetSymbolAddress((void**)&Wvh,  g_Wvh);
    cudaGetSymbolAddress((void**)&Wvl,  g_Wvl);
    cudaGetSymbolAddress((void**)&Woh,  g_Woh);
    cudaGetSymbolAddress((void**)&Wol,  g_Wol);
    cudaGetSymbolAddress((void**)&qsp,  g_qsp);
    cudaGetSymbolAddress((void**)&Qsh,  g_Qsh);
    cudaGetSymbolAddress((void**)&Qsl,  g_Qsl);
    cudaGetSymbolAddress((void**)&Qth,  g_Qth);
    cudaGetSymbolAddress((void**)&Qtl,  g_Qtl);
    cudaGetSymbolAddress((void**)&xf,   g_xf);
    cudaGetSymbolAddress((void**)&xthh, g_xthh);
    cudaGetSymbolAddress((void**)&xthl, g_xthl);
    cudaGetSymbolAddress((void**)&sc,   g_sc);
    cudaGetSymbolAddress((void**)&ahf,  g_ahf);
    cudaGetSymbolAddress((void**)&rsum, g_rsum);
    cudaGetSymbolAddress((void**)&wxp,  g_wxp);
    cudaGetSymbolAddress((void**)&wxh,  g_wxh);
    cudaGetSymbolAddress((void**)&wxl,  g_wxl);
    cudaGetSymbolAddress((void**)&ctx,  g_ctx);
    cudaGetSymbolAddress((void**)&crh,  g_crh);
    cudaGetSymbolAddress((void**)&crl,  g_crl);
    cudaGetSymbolAddress((void**)&ys,   g_ys);

    const int Hu = Hh * u;
    const int mp = ((Hu + 127) / 128) * 128;
    const int Bu = Bb * u;
    const int bup = ((Bu + 127) / 128) * 128;
    const float scale = 0.125f;

    const int smem_n = NSTAGE * (int)STG_SZ;   // 98304
    cudaFuncSetAttribute(mma_gemm_k<0>, cudaFuncAttributeMaxDynamicSharedMemorySize, smem_n);
    cudaFuncSetAttribute(mma_gemm_k<1>, cudaFuncAttributeMaxDynamicSharedMemorySize, smem_n);
    cudaFuncSetAttribute(mma_f16_2t_k<0>, cudaFuncAttributeMaxDynamicSharedMemorySize, smem_n);
    cudaFuncSetAttribute(mma_f16_2t_k<1>, cudaFuncAttributeMaxDynamicSharedMemorySize, smem_n);

    // 0) conversions
    convx_k<<<dim3(Tt / 32, Dd / 32, Bb), 256>>>(x, xf, xthh, xthl);
    convw3_k<<<dim3(256, 3), 256>>>(Wq, Wqh, Wql, Wv, Wvh, Wvl, Wo, Woh, Wol);
    convwT_k<<<dim3(32, 32), 256>>>(Wk, WkTh, WkTl, scale);

    // 1) gather+split x rows at idx
    gather_xs_k<<<Bb * u, 256>>>(xsh, xsl, (const float4*)x, idx, u);

    // 2) Qs partials = xs @ Wq^T   (bf16 3-term, split-K=4)
    mma_gemm_k<0><<<dim3(Dd / BNt, bup / BMt, 4), 256, smem_n>>>(
        qsp, nullptr, nullptr, xsh, xsl, Wqh, Wql,
        256, Dd, Dd, Dd, Bu, Dd,
        0, 0, 0, 0, 0, 0, 1, 4, (ll)bup * Dd);
    redsplit4_k<<<512, 256>>>(qsp, Qsh, Qsl, Bu * Dd, bup * Dd);

    // 3) Qt[b,h] = Qs[b](cols h*64..) @ (scale*Wk_h)  -> fp16 hi/lo padded
    mma_gemm_k<1><<<dim3(Dd / BNt, 1, Bb * Hh), 256, smem_n>>>(
        nullptr, Qth, Qtl, Qsh, Qsl, WkTh, WkTl,
        DHh, Dd, Dd, Dd, u, Dd,
        (ll)u * Dd, (ll)DHh, 0, (ll)DHh, (ll)mp * Dd, (ll)u * Dd, Hh, 1, 0);

    // 4) scores[b] = (Qt_h + Qt_l)[b] @ xf[b]^T   (fp16 2-term, APAIR=1)
    mma_f16_2t_k<1><<<dim3(Tt / BNt, mp / BMt, Bb), 256, smem_n>>>(
        sc, Qth, Qtl, xf, nullptr,
        Dd, Dd, Dd, Tt, Hu, Tt,
        (ll)mp * Dd, (ll)Tt * Dd, (ll)mp * Tt, 1, 0);

    // 5) softmax -> unnormalized exp (single fp16) + row sums
    softmax_k<<<Bb * Hu, 256>>>(sc, ahf, rsum, Hu, mp);

    // 6) wx partials = e[b] @ x[b]   (fp16 2-term APAIR=0, split-K=2, B = x^T pair)
    mma_f16_2t_k<0><<<dim3(Dd / BNt, mp / BMt, Bb * 2), 256, smem_n>>>(
        wxp, ahf, nullptr, xthh, xthl,
        Tt / 2, Tt, Tt, Dd, mp, Dd,
        (ll)mp * Tt, (ll)Dd * Tt, (ll)mp * Dd, 2, (ll)Bb * mp * Dd);
    redsplit2_k<<<1024, 256>>>(wxp, wxh, wxl, Bb * mp * Dd, (ll)Bb * mp * Dd);

    // 7) ctx[b,h] = wx[b,h] @ Wv_h^T   (bf16 3-term, fp32 out)
    mma_gemm_k<0><<<dim3(1, 1, Bb * Hh), 256, smem_n>>>(
        ctx, nullptr, nullptr, wxh, wxl, Wvh, Wvl,
        Dd, Dd, Dd, DHh, u, DHh,
        (ll)mp * Dd, (ll)u * Dd, 0, (ll)DHh * Dd, (ll)Hh * u * DHh, (ll)u * DHh, Hh, 1, 0);

    // 8) reorder ctx + normalize + mean row -> bf16 split
    ctxrow_mean_k<<<dim3(Bb, Hh), 64>>>(crh, crl, ctx, rsum, u, Hu);

    // 9) ys = cr @ Wo^T   (bf16 3-term, fp32 out)
    mma_gemm_k<0><<<dim3(Dd / BNt, 1, Bb), 256, smem_n>>>(
        ys, nullptr, nullptr, crh, crl, Woh, Wol,
        Dd, Dd, Dd, Dd, u + 1, Dd,
        (ll)(u + 1) * Dd, 0, 0, 0, (ll)(u + 1) * Dd, 0, 1, 1, 0);

    // 10) broadcast + scatter
    fill_k<<<Bb * (Tt / 8), 256>>>((float4*)y, (const float4*)ys, (const float4*)bo, u);
    scatter_k<<<dim3(Bb, u), 256>>>((float4*)y, (const float4*)ys, (const float4*)bo, idx, u);
}

// round 16
// speedup vs baseline: 2.3369x; 1.4452x over previous
#include <cuda_runtime.h>
#include <cuda_bf16.h>
#include <cuda_fp16.h>
#include <cstdint>

#define Bb   8
#define Tt   4096
#define Dd   1024
#define Hh   16
#define DHh  64
#define UMAX 64
#define MPMAX 1024
#define BUPMAX 512

typedef long long ll;
typedef __nv_bfloat16 bf16;

// ---------------- scratch (static __device__, allocation-free) ----------------
__device__ bf16  g_xsh[Bb * UMAX * Dd];
__device__ bf16  g_xsl[Bb * UMAX * Dd];
__device__ bf16  g_Wqh[Dd * Dd];
__device__ bf16  g_Wql[Dd * Dd];
__device__ bf16  g_WkTh[Dd * Dd];
__device__ bf16  g_WkTl[Dd * Dd];
__device__ bf16  g_Wvh[(Dd + 128) * Dd];     // row-padded for OOB-safe tile loads
__device__ bf16  g_Wvl[(Dd + 128) * Dd];
__device__ bf16  g_Woh[Dd * Dd];
__device__ bf16  g_Wol[Dd * Dd];
__device__ float g_qsp[4 * BUPMAX * Dd];     // step-2 split-K partials
__device__ bf16  g_Qsh[Bb * UMAX * Dd];
__device__ bf16  g_Qsl[Bb * UMAX * Dd];
__device__ __half g_Qt[(size_t)Bb * MPMAX * Dd];    // Qt single fp16
__device__ __half g_xf[(size_t)Bb * Tt * Dd];       // x straight, single fp16
__device__ __half g_xth[(size_t)Bb * Dd * Tt];      // x^T single fp16
__device__ float g_sc[(size_t)Bb * MPMAX * Tt];
__device__ __half g_ahf[(size_t)Bb * MPMAX * Tt];   // exp weights, single fp16
__device__ float g_rsum[Bb * Hh * UMAX];
__device__ float g_wxp[(size_t)2 * Bb * MPMAX * Dd];  // step-6 split-K partials
__device__ bf16  g_wxh[(size_t)Bb * MPMAX * Dd];
__device__ bf16  g_wxl[(size_t)Bb * MPMAX * Dd];
__device__ float g_ctx[Bb * Hh * UMAX * DHh];
__device__ bf16  g_crh[Bb * (UMAX + 2) * Dd];
__device__ bf16  g_crl[Bb * (UMAX + 2) * Dd];
__device__ float g_ys[Bb * (UMAX + 1) * Dd];

// ---------------- PTX helpers (sm_80/sm_90 portable only) ----------------
__device__ __forceinline__ uint32_t smem_u32(const void* p) {
    uint32_t a;
    asm("{ .reg .u64 t; cvta.to.shared.u64 t, %1; cvt.u32.u64 %0, t; }" : "=r"(a) : "l"(p));
    return a;
}
__device__ __forceinline__ void cp_async16(uint32_t s, const void* g) {
    asm volatile("cp.async.cg.shared.global [%0], [%1], 16;" :: "r"(s), "l"(g) : "memory");
}
__device__ __forceinline__ void ldsm_x4(uint32_t* r, uint32_t a) {
    asm volatile("ldmatrix.sync.aligned.m8n8.x4.shared.b16 {%0,%1,%2,%3}, [%4];"
                 : "=r"(r[0]), "=r"(r[1]), "=r"(r[2]), "=r"(r[3]) : "r"(a));
}
__device__ __forceinline__ void mma16816(float* c, const uint32_t* a, const uint32_t* b) {
    asm volatile(
        "mma.sync.aligned.m16n8k16.row.col.f32.bf16.bf16.f32 "
        "{%0,%1,%2,%3}, {%4,%5,%6,%7}, {%8,%9}, {%0,%1,%2,%3};"
        : "+f"(c[0]), "+f"(c[1]), "+f"(c[2]), "+f"(c[3])
        : "r"(a[0]), "r"(a[1]), "r"(a[2]), "r"(a[3]), "r"(b[0]), "r"(b[1]));
}
__device__ __forceinline__ void mma16816h(float* c, const uint32_t* a, const uint32_t* b) {
    asm volatile(
        "mma.sync.aligned.m16n8k16.row.col.f32.f16.f16.f32 "
        "{%0,%1,%2,%3}, {%4,%5,%6,%7}, {%8,%9}, {%0,%1,%2,%3};"
        : "+f"(c[0]), "+f"(c[1]), "+f"(c[2]), "+f"(c[3])
        : "r"(a[0]), "r"(a[1]), "r"(a[2]), "r"(a[3]), "r"(b[0]), "r"(b[1]));
}

__device__ __forceinline__ void split2(float v, bf16& h, bf16& l) {
    h = __float2bfloat16(v);
    l = __float2bfloat16(v - __bfloat162float(h));
}
__device__ __forceinline__ void packpair(float a, float b,
                                         __nv_bfloat162& hp, __nv_bfloat162& lp) {
    bf16 h0, l0, h1, l1; split2(a, h0, l0); split2(b, h1, l1);
    hp.x = h0; hp.y = h1; lp.x = l0; lp.y = l1;
}

// ============ narrow merged-pass warp-MMA GEMM, bf16 3-term ============
// EPI=0: fp32 C out.  EPI=1: single-fp16 C out (Ch).
#define BMt 128
#define BNt 128
#define STG_SZ 32768u
#define NSTAGE 3

template <int EPI>
__global__ __launch_bounds__(256, 2) void mma_gemm_k(
    float* __restrict__ C, __half* __restrict__ Ch,
    const bf16* __restrict__ Ah, const bf16* __restrict__ Al,
    const bf16* __restrict__ Bh, const bf16* __restrict__ Bl,
    int Kext, int lda, int ldb, int ldc, int Mreal, int Nreal,
    ll sAb, ll sAh, ll sBb, ll sBh, ll sCb, ll sCh,
    int nh, int KS, ll sCs) {
    extern __shared__ char smem[];
    uint32_t sbase = smem_u32(smem);
    int tid = threadIdx.x, wid = tid >> 5, lane = tid & 31;
    int z = blockIdx.z;
    int ks = z % KS, bh2 = z / KS;
    int hh = bh2 % nh, bb = bh2 / nh;
    int m0 = blockIdx.y * BMt, n0 = blockIdx.x * BNt;

    const bf16* A0 = Ah + bb * sAb + hh * sAh + (ll)ks * Kext + (size_t)m0 * lda;
    const bf16* A1 = Al + bb * sAb + hh * sAh + (ll)ks * Kext + (size_t)m0 * lda;
    const bf16* B0 = Bh + bb * sBb + hh * sBh + (ll)ks * Kext + (size_t)n0 * ldb;
    const bf16* B1 = Bl + bb * sBb + hh * sBh + (ll)ks * Kext + (size_t)n0 * ldb;

    int row = tid >> 1, cq = tid & 1, rx = row & 7;
    size_t   gA0 = (size_t)row * lda + cq * 8, gA1 = gA0 + 16;
    size_t   gB0 = (size_t)row * ldb + cq * 8, gB1 = gB0 + 16;
    uint32_t dh0 = row * 128 + ((cq)     ^ rx) * 16;
    uint32_t dh1 = row * 128 + ((cq + 2) ^ rx) * 16;
    uint32_t dl0 = row * 128 + ((cq + 4) ^ rx) * 16;
    uint32_t dl1 = row * 128 + ((cq + 6) ^ rx) * 16;

    int warp_m = wid >> 2, warp_n = wid & 3;
    int rl = lane & 15, cl = lane >> 4, arx = lane & 7;
    int rb = lane & 7,  cb = (lane >> 3) & 1;
    uint32_t arow[4], b4row[2];
#pragma unroll
    for (int i = 0; i < 4; i++) arow[i] = (warp_m * 64 + i * 16 + rl) * 128;
#pragma unroll
    for (int j2 = 0; j2 < 2; j2++)
        b4row[j2] = (warp_n * 32 + (j2 * 2 + (lane >> 4)) * 8 + rb) * 128;

    float acc[4][4][4];
#pragma unroll
    for (int i = 0; i < 4; i++)
#pragma unroll
        for (int j = 0; j < 4; j++)
#pragma unroll
            for (int q = 0; q < 4; q++) acc[i][j][q] = 0.f;

    const int NC = Kext >> 5;

#define ISSUE(c_) do {                                                        \
    size_t ko_ = (size_t)(c_) * 32;                                           \
    uint32_t st_ = sbase + ((c_) % NSTAGE) * STG_SZ;                          \
    cp_async16(st_ + dh0, A0 + ko_ + gA0);                                    \
    cp_async16(st_ + dh1, A0 + ko_ + gA1);                                    \
    cp_async16(st_ + dl0, A1 + ko_ + gA0);                                    \
    cp_async16(st_ + dl1, A1 + ko_ + gA1);                                    \
    cp_async16(st_ + 16384u + dh0, B0 + ko_ + gB0);                           \
    cp_async16(st_ + 16384u + dh1, B0 + ko_ + gB1);                           \
    cp_async16(st_ + 16384u + dl0, B1 + ko_ + gB0);                           \
    cp_async16(st_ + 16384u + dl1, B1 + ko_ + gB1);                           \
    asm volatile("cp.async.commit_group;" ::: "memory");                      \
} while (0)

    ISSUE(0);
    if (NC > 1) ISSUE(1);

    for (int c = 0; c < NC; c++) {
        if (c + 1 < NC) asm volatile("cp.async.wait_group 1;" ::: "memory");
        else            asm volatile("cp.async.wait_group 0;" ::: "memory");
        __syncthreads();
        if (c + 2 < NC) ISSUE(c + 2);

        uint32_t sa = sbase + (c % NSTAGE) * STG_SZ;
        uint32_t sb = sa + 16384u;
#pragma unroll
        for (int kk = 0; kk < 2; kk++) {
            uint32_t bh[4][2], blo[4][2], af[4][4];
#pragma unroll
            for (int j2 = 0; j2 < 2; j2++)
                ldsm_x4(&bh[j2 * 2][0],  sb + b4row[j2] + (((kk * 2 + cb)     ^ rb) << 4));
#pragma unroll
            for (int j2 = 0; j2 < 2; j2++)
                ldsm_x4(&blo[j2 * 2][0], sb + b4row[j2] + (((kk * 2 + cb + 4) ^ rb) << 4));
#pragma unroll
            for (int i = 0; i < 4; i++)
                ldsm_x4(af[i], sa + arow[i] + (((kk * 2 + cl)     ^ arx) << 4));
#pragma unroll
            for (int i = 0; i < 4; i++)
#pragma unroll
                for (int j = 0; j < 4; j++) mma16816(acc[i][j], af[i], bh[j]);
#pragma unroll
            for (int i = 0; i < 4; i++)
#pragma unroll
                for (int j = 0; j < 4; j++) mma16816(acc[i][j], af[i], blo[j]);
#pragma unroll
            for (int i = 0; i < 4; i++)
                ldsm_x4(af[i], sa + arow[i] + (((kk * 2 + cl + 4) ^ arx) << 4));
#pragma unroll
            for (int i = 0; i < 4; i++)
#pragma unroll
                for (int j = 0; j < 4; j++) mma16816(acc[i][j], af[i], bh[j]);
        }
    }

    ll cbase = bb * sCb + hh * sCh + (ll)ks * sCs;
#pragma unroll
    for (int i = 0; i < 4; i++) {
        int m = m0 + warp_m * 64 + i * 16 + (lane >> 2);
#pragma unroll
        for (int j = 0; j < 4; j++) {
            int n = n0 + warp_n * 32 + j * 8 + (lane & 3) * 2;
            if (n < Nreal) {
#pragma unroll
                for (int p = 0; p < 2; p++) {
                    int mm = m + p * 8;
                    if (mm < Mreal) {
                        if (EPI == 0) {
                            *(float2*)&C[cbase + (size_t)mm * ldc + n] =
                                make_float2(acc[i][j][p * 2], acc[i][j][p * 2 + 1]);
                        } else {
                            *(__half2*)&Ch[cbase + (size_t)mm * ldc + n] =
                                __floats2half2_rn(acc[i][j][p * 2], acc[i][j][p * 2 + 1]);
                        }
                    }
                }
            }
        }
    }
}

// ============ single-term fp16 warp-MMA GEMM: C = A @ B^T (steps 4, 6) ============
// A (M x Kext) fp16, B (N x Kext) fp16. 4 cp.async + 6 ldsm + 16 HMMA per kk.
__global__ __launch_bounds__(256, 2) void mma_f16_1t_k(
    float* __restrict__ C,
    const __half* __restrict__ A, const __half* __restrict__ B,
    int Kext, int lda, int ldb, int ldc, int Mreal, int Nreal,
    ll sAb, ll sBb, ll sCb, int KS, ll sCs) {
    extern __shared__ char smem[];
    uint32_t sbase = smem_u32(smem);
    int tid = threadIdx.x, wid = tid >> 5, lane = tid & 31;
    int z = blockIdx.z;
    int ks = z % KS, bb = z / KS;
    int m0 = blockIdx.y * BMt, n0 = blockIdx.x * BNt;

    const __half* A0 = A + bb * sAb + (ll)ks * Kext + (size_t)m0 * lda;
    const __half* B0 = B + bb * sBb + (ll)ks * Kext + (size_t)n0 * ldb;

    int row = tid >> 1, cq = tid & 1, rx = row & 7;
    size_t   gA0 = (size_t)row * lda + cq * 8, gA1 = gA0 + 16;
    size_t   gB0 = (size_t)row * ldb + cq * 8, gB1 = gB0 + 16;
    uint32_t dh0 = row * 128 + ((cq)     ^ rx) * 16;
    uint32_t dh1 = row * 128 + ((cq + 2) ^ rx) * 16;

    int warp_m = wid >> 2, warp_n = wid & 3;
    int rl = lane & 15, cl = lane >> 4, arx = lane & 7;
    int rb = lane & 7,  cb = (lane >> 3) & 1;
    uint32_t arow[4], b4row[2];
#pragma unroll
    for (int i = 0; i < 4; i++) arow[i] = (warp_m * 64 + i * 16 + rl) * 128;
#pragma unroll
    for (int j2 = 0; j2 < 2; j2++)
        b4row[j2] = (warp_n * 32 + (j2 * 2 + (lane >> 4)) * 8 + rb) * 128;

    float acc[4][4][4];
#pragma unroll
    for (int i = 0; i < 4; i++)
#pragma unroll
        for (int j = 0; j < 4; j++)
#pragma unroll
            for (int q = 0; q < 4; q++) acc[i][j][q] = 0.f;

    const int NC = Kext >> 5;

#define ISSUE1(c_) do {                                                       \
    size_t ko_ = (size_t)(c_) * 32;                                           \
    uint32_t st_ = sbase + ((c_) % NSTAGE) * STG_SZ;                          \
    cp_async16(st_ + dh0, A0 + ko_ + gA0);                                    \
    cp_async16(st_ + dh1, A0 + ko_ + gA1);                                    \
    cp_async16(st_ + 16384u + dh0, B0 + ko_ + gB0);                           \
    cp_async16(st_ + 16384u + dh1, B0 + ko_ + gB1);                           \
    asm volatile("cp.async.commit_group;" ::: "memory");                      \
} while (0)

    ISSUE1(0);
    if (NC > 1) ISSUE1(1);

    for (int c = 0; c < NC; c++) {
        if (c + 1 < NC) asm volatile("cp.async.wait_group 1;" ::: "memory");
        else            asm volatile("cp.async.wait_group 0;" ::: "memory");
        __syncthreads();
        if (c + 2 < NC) ISSUE1(c + 2);

        uint32_t sa = sbase + (c % NSTAGE) * STG_SZ;
        uint32_t sb = sa + 16384u;
#pragma unroll
        for (int kk = 0; kk < 2; kk++) {
            uint32_t bh[4][2], af[4][4];
#pragma unroll
            for (int j2 = 0; j2 < 2; j2++)
                ldsm_x4(&bh[j2 * 2][0], sb + b4row[j2] + (((kk * 2 + cb) ^ rb) << 4));
#pragma unroll
            for (int i = 0; i < 4; i++)
                ldsm_x4(af[i], sa + arow[i] + (((kk * 2 + cl) ^ arx) << 4));
#pragma unroll
            for (int i = 0; i < 4; i++)
#pragma unroll
                for (int j = 0; j < 4; j++) mma16816h(acc[i][j], af[i], bh[j]);
        }
    }

    ll cbase = bb * sCb + (ll)ks * sCs;
#pragma unroll
    for (int i = 0; i < 4; i++) {
        int m = m0 + warp_m * 64 + i * 16 + (lane >> 2);
#pragma unroll
        for (int j = 0; j < 4; j++) {
            int n = n0 + warp_n * 32 + j * 8 + (lane & 3) * 2;
            if (n < Nreal) {
#pragma unroll
                for (int p = 0; p < 2; p++) {
                    int mm = m + p * 8;
                    if (mm < Mreal) {
                        *(float2*)&C[cbase + (size_t)mm * ldc + n] =
                            make_float2(acc[i][j][p * 2], acc[i][j][p * 2 + 1]);
                    }
                }
            }
        }
    }
}

// ---------------- x -> single fp16 straight + single fp16 transposed ----------------
__global__ __launch_bounds__(256) void convx_k(const float* __restrict__ x,
                                               __half* __restrict__ xf,
                                               __half* __restrict__ xth) {
    __shared__ float ts[32][33];
    int b = blockIdx.z;
    int t0 = blockIdx.x * 32, d0 = blockIdx.y * 32;
    int tid = threadIdx.x;
    int r = tid >> 4, p = tid & 15;
#pragma unroll
    for (int it = 0; it < 2; it++) {
        int rr = r + it * 16;
        size_t o = ((size_t)b * Tt + t0 + rr) * Dd + d0 + 2 * p;
        float2 v = *(const float2*)(x + o);
        *(__half2*)(xf + o) = __floats2half2_rn(v.x, v.y);
        ts[rr][2 * p] = v.x; ts[rr][2 * p + 1] = v.y;
    }
    __syncthreads();
#pragma unroll
    for (int it = 0; it < 2; it++) {
        int dr = r + it * 16;
        float v0 = ts[2 * p][dr], v1 = ts[2 * p + 1][dr];
        size_t o = ((size_t)b * Dd + d0 + dr) * Tt + t0 + 2 * p;
        *(__half2*)(xth + o) = __floats2half2_rn(v0, v1);
    }
}

// ---------------- three straight weight conversions in one launch ----------------
__global__ __launch_bounds__(256) void convw3_k(
    const float* __restrict__ Wq, bf16* __restrict__ Wqh, bf16* __restrict__ Wql,
    const float* __restrict__ Wv, bf16* __restrict__ Wvh, bf16* __restrict__ Wvl,
    const float* __restrict__ Wo, bf16* __restrict__ Woh, bf16* __restrict__ Wol) {
    const float* W; bf16 *Wh, *Wl;
    if (blockIdx.y == 0)      { W = Wq; Wh = Wqh; Wl = Wql; }
    else if (blockIdx.y == 1) { W = Wv; Wh = Wvh; Wl = Wvl; }
    else                      { W = Wo; Wh = Woh; Wl = Wol; }
    for (int i = (blockIdx.x * 256 + threadIdx.x) * 2; i < Dd * Dd; i += gridDim.x * 512) {
        float2 v = *(const float2*)(W + i);
        __nv_bfloat162 hp, lp; packpair(v.x, v.y, hp, lp);
        *(__nv_bfloat162*)(Wh + i) = hp;
        *(__nv_bfloat162*)(Wl + i) = lp;
    }
}

// ---------------- weight fp32 -> transposed + scaled bf16 hi/lo ----------------
__global__ __launch_bounds__(256) void convwT_k(const float* __restrict__ W,
                                                bf16* __restrict__ Wh, bf16* __restrict__ Wl,
                                                float alpha) {
    __shared__ float ts[32][33];
    int r0 = blockIdx.x * 32, c0 = blockIdx.y * 32;
    int tx = threadIdx.x & 31, ty = threadIdx.x >> 5;
#pragma unroll
    for (int i = 0; i < 4; i++) {
        int rr = ty * 4 + i;
        ts[rr][tx] = W[(size_t)(r0 + rr) * Dd + c0 + tx];
    }
    __syncthreads();
    int r = threadIdx.x >> 4, p = threadIdx.x & 15;
#pragma unroll
    for (int it = 0; it < 2; it++) {
        int c = r + it * 16;
        float v0 = alpha * ts[2 * p][c], v1 = alpha * ts[2 * p + 1][c];
        __nv_bfloat162 hp, lp; packpair(v0, v1, hp, lp);
        size_t o = (size_t)(c0 + c) * Dd + r0 + 2 * p;
        *(__nv_bfloat162*)(Wh + o) = hp;
        *(__nv_bfloat162*)(Wl + o) = lp;
    }
}

// ---------------- gather x rows at idx, split to bf16 hi/lo ----------------
__global__ __launch_bounds__(256) void gather_xs_k(bf16* __restrict__ xsh,
                                                   bf16* __restrict__ xsl,
                                                   const float4* __restrict__ x,
                                                   const int* __restrict__ idx, int u) {
    int b = blockIdx.x / u, j = blockIdx.x % u;
    int t = idx[j];
    float4 v = x[((size_t)b * Tt + t) * (Dd / 4) + threadIdx.x];
    size_t o = ((size_t)b * u + j) * Dd + threadIdx.x * 4;
    __nv_bfloat162 hp, lp;
    packpair(v.x, v.y, hp, lp);
    *(__nv_bfloat162*)(xsh + o) = hp;
    *(__nv_bfloat162*)(xsl + o) = lp;
    packpair(v.z, v.w, hp, lp);
    *(__nv_bfloat162*)(xsh + o + 2) = hp;
    *(__nv_bfloat162*)(xsl + o + 2) = lp;
}

// ---------------- split-K reduce (4-way) -> bf16 hi/lo ----------------
__global__ __launch_bounds__(256) void redsplit4_k(const float* __restrict__ p,
                                                   bf16* __restrict__ oh, bf16* __restrict__ ol,
                                                   int n, int stride) {
    for (int i = (blockIdx.x * 256 + threadIdx.x) * 2; i < n; i += gridDim.x * 512) {
        float2 a0 = *(const float2*)(p + i);
        float2 a1 = *(const float2*)(p + i + stride);
        float2 a2 = *(const float2*)(p + i + 2 * stride);
        float2 a3 = *(const float2*)(p + i + 3 * stride);
        __nv_bfloat162 hp, lp;
        packpair(a0.x + a1.x + a2.x + a3.x, a0.y + a1.y + a2.y + a3.y, hp, lp);
        *(__nv_bfloat162*)(oh + i) = hp;
        *(__nv_bfloat162*)(ol + i) = lp;
    }
}

// ---------------- split-K reduce (2-way) -> bf16 hi/lo ----------------
__global__ __launch_bounds__(256) void redsplit2_k(const float* __restrict__ p,
                                                   bf16* __restrict__ oh, bf16* __restrict__ ol,
                                                   int n, ll stride) {
    for (int i = (blockIdx.x * 256 + threadIdx.x) * 2; i < n; i += gridDim.x * 512) {
        float2 a0 = *(const float2*)(p + i);
        float2 a1 = *(const float2*)(p + i + stride);
        __nv_bfloat162 hp, lp;
        packpair(a0.x + a1.x, a0.y + a1.y, hp, lp);
        *(__nv_bfloat162*)(oh + i) = hp;
        *(__nv_bfloat162*)(ol + i) = lp;
    }
}

// ---------------- softmax: UNNORMALIZED exp -> single fp16 + row sums ----------------
__global__ __launch_bounds__(256) void softmax_k(const float* __restrict__ s,
                                                 __half* __restrict__ ah,
                                                 float* __restrict__ rsum, int Hu, int mp) {
    __shared__ float red[256];
    int b = blockIdx.x / Hu, r = blockIdx.x % Hu;
    size_t base = ((size_t)b * mp + r) * Tt;
    int tid = threadIdx.x;
    float m = -3.4e38f;
    for (int t = tid * 2; t < Tt; t += 512) {
        float2 v = *(const float2*)(s + base + t);
        m = fmaxf(m, fmaxf(v.x, v.y));
    }
    red[tid] = m; __syncthreads();
    for (int o = 128; o > 0; o >>= 1) {
        if (tid < o) red[tid] = fmaxf(red[tid], red[tid + o]);
        __syncthreads();
    }
    float mx = red[0];
    __syncthreads();
    float sum = 0.f;
    for (int t = tid * 2; t < Tt; t += 512) {
        float2 v = *(const float2*)(s + base + t);
        float e0 = __expf(v.x - mx), e1 = __expf(v.y - mx);
        sum += e0 + e1;
        *(__half2*)(ah + base + t) = __floats2half2_rn(e0, e1);
    }
    red[tid] = sum; __syncthreads();
    for (int o = 128; o > 0; o >>= 1) {
        if (tid < o) red[tid] += red[tid + o];
        __syncthreads();
    }
    if (tid == 0) rsum[blockIdx.x] = red[0];
}

// ---------------- ctx -> per-token rows (normalized) + mean row, bf16 split ----------------
__global__ __launch_bounds__(64) void ctxrow_mean_k(bf16* __restrict__ crh,
                                                    bf16* __restrict__ crl,
                                                    const float* __restrict__ ctx,
                                                    const float* __restrict__ rsum,
                                                    int u, int Hu) {
    int b = blockIdx.x, h = blockIdx.y, d = threadIdx.x;
    float s = 0.f;
    for (int j = 0; j < u; j++) {
        float inv = 1.f / rsum[b * Hu + h * u + j];
        float v = ctx[((size_t)(b * Hh + h) * u + j) * DHh + d] * inv;
        bf16 hh, ll2; split2(v, hh, ll2);
        size_t o = ((size_t)b * (u + 1) + j) * Dd + h * DHh + d;
        crh[o] = hh; crl[o] = ll2;
        s += v;
    }
    bf16 hh, ll2; split2(s / (float)u, hh, ll2);
    size_t o = ((size_t)b * (u + 1) + u) * Dd + h * DHh + d;
    crh[o] = hh; crl[o] = ll2;
}

// ---------------- broadcast fill (8 rows/block) + scatter ----------------
__global__ __launch_bounds__(256) void fill_k(float4* __restrict__ y,
                                              const float4* __restrict__ ys,
                                              const float4* __restrict__ bo, int u) {
    int b = blockIdx.x / (Tt / 8);
    int tt0 = (blockIdx.x % (Tt / 8)) * 8;
    float4 v = ys[((size_t)b * (u + 1) + u) * 256 + threadIdx.x];
    float4 bb = bo[threadIdx.x];
    float4 o = make_float4(v.x + bb.x, v.y + bb.y, v.z + bb.z, v.w + bb.w);
    size_t base = ((size_t)b * Tt + tt0) * 256 + threadIdx.x;
#pragma unroll
    for (int i = 0; i < 8; i++) y[base + (size_t)i * 256] = o;
}
__global__ __launch_bounds__(256) void scatter_k(float4* __restrict__ y,
                                                 const float4* __restrict__ ys,
                                                 const float4* __restrict__ bo,
                                                 const int* __restrict__ idx, int u) {
    int b = blockIdx.x, j = blockIdx.y;
    int t = idx[j];
    float4 v = ys[((size_t)b * (u + 1) + j) * 256 + threadIdx.x];
    float4 bb = bo[threadIdx.x];
    y[((size_t)b * Tt + t) * 256 + threadIdx.x] =
        make_float4(v.x + bb.x, v.y + bb.y, v.z + bb.z, v.w + bb.w);
}

// ---------------- launch ----------------
extern "C" void kernel_launch(void* const* d_in, const int* in_sizes, int n_in,
                              void* d_out, int out_size) {
    const float* x  = (const float*)d_in[0];
    const float* Wq = (const float*)d_in[1];
    const float* Wk = (const float*)d_in[2];
    const float* Wv = (const float*)d_in[3];
    const float* Wo = (const float*)d_in[4];
    const float* bo = (const float*)d_in[5];
    const int* idx  = (const int*)d_in[6];
    int u = in_sizes[6];
    if (u > UMAX) u = UMAX;
    if (u < 1) u = 1;
    float* y = (float*)d_out;

    float *qsp, *sc, *rsum, *wxp, *ctx, *ys;
    bf16 *xsh, *xsl, *Wqh, *Wql, *WkTh, *WkTl, *Wvh, *Wvl, *Woh, *Wol;
    bf16 *Qsh, *Qsl, *wxh, *wxl, *crh, *crl;
    __half *Qt, *xf, *xth, *ahf;
    cudaGetSymbolAddress((void**)&xsh,  g_xsh);
    cudaGetSymbolAddress((void**)&xsl,  g_xsl);
    cudaGetSymbolAddress((void**)&Wqh,  g_Wqh);
    cudaGetSymbolAddress((void**)&Wql,  g_Wql);
    cudaGetSymbolAddress((void**)&WkTh, g_WkTh);
    cudaGetSymbolAddress((void**)&WkTl, g_WkTl);
    cudaGetSymbolAddress((void**)&Wvh,  g_Wvh);
    cudaGetSymbolAddress((void**)&Wvl,  g_Wvl);
    cudaGetSymbolAddress((void**)&Woh,  g_Woh);
    cudaGetSymbolAddress((void**)&Wol,  g_Wol);
    cudaGetSymbolAddress((void**)&qsp,  g_qsp);
    cudaGetSymbolAddress((void**)&Qsh,  g_Qsh);
    cudaGetSymbolAddress((void**)&Qsl,  g_Qsl);
    cudaGetSymbolAddress((void**)&Qt,   g_Qt);
    cudaGetSymbolAddress((void**)&xf,   g_xf);
    cudaGetSymbolAddress((void**)&xth,  g_xth);
    cudaGetSymbolAddress((void**)&sc,   g_sc);
    cudaGetSymbolAddress((void**)&ahf,  g_ahf);
    cudaGetSymbolAddress((void**)&rsum, g_rsum);
    cudaGetSymbolAddress((void**)&wxp,  g_wxp);
    cudaGetSymbolAddress((void**)&wxh,  g_wxh);
    cudaGetSymbolAddress((void**)&wxl,  g_wxl);
    cudaGetSymbolAddress((void**)&ctx,  g_ctx);
    cudaGetSymbolAddress((void**)&crh,  g_crh);
    cudaGetSymbolAddress((void**)&crl,  g_crl);
    cudaGetSymbolAddress((void**)&ys,   g_ys);

    const int Hu = Hh * u;
    const int mp = ((Hu + 127) / 128) * 128;
    const int Bu = Bb * u;
    const int bup = ((Bu + 127) / 128) * 128;
    const float scale = 0.125f;

    const int smem_n = NSTAGE * (int)STG_SZ;   // 98304
    cudaFuncSetAttribute(mma_gemm_k<0>, cudaFuncAttributeMaxDynamicSharedMemorySize, smem_n);
    cudaFuncSetAttribute(mma_gemm_k<1>, cudaFuncAttributeMaxDynamicSharedMemorySize, smem_n);
    cudaFuncSetAttribute(mma_f16_1t_k, cudaFuncAttributeMaxDynamicSharedMemorySize, smem_n);

    // 0) conversions
    convx_k<<<dim3(Tt / 32, Dd / 32, Bb), 256>>>(x, xf, xth);
    convw3_k<<<dim3(256, 3), 256>>>(Wq, Wqh, Wql, Wv, Wvh, Wvl, Wo, Woh, Wol);
    convwT_k<<<dim3(32, 32), 256>>>(Wk, WkTh, WkTl, scale);

    // 1) gather+split x rows at idx
    gather_xs_k<<<Bb * u, 256>>>(xsh, xsl, (const float4*)x, idx, u);

    // 2) Qs partials = xs @ Wq^T   (bf16 3-term, split-K=4)
    mma_gemm_k<0><<<dim3(Dd / BNt, bup / BMt, 4), 256, smem_n>>>(
        qsp, nullptr, xsh, xsl, Wqh, Wql,
        256, Dd, Dd, Dd, Bu, Dd,
        0, 0, 0, 0, 0, 0, 1, 4, (ll)bup * Dd);
    redsplit4_k<<<512, 256>>>(qsp, Qsh, Qsl, Bu * Dd, bup * Dd);

    // 3) Qt[b,h] = Qs[b](cols h*64..) @ (scale*Wk_h)  -> single fp16, padded
    mma_gemm_k<1><<<dim3(Dd / BNt, 1, Bb * Hh), 256, smem_n>>>(
        nullptr, Qt, Qsh, Qsl, WkTh, WkTl,
        DHh, Dd, Dd, Dd, u, Dd,
        (ll)u * Dd, (ll)DHh, 0, (ll)DHh, (ll)mp * Dd, (ll)u * Dd, Hh, 1, 0);

    // 4) scores[b] = Qt[b] @ xf[b]^T   (fp16 1-term)
    mma_f16_1t_k<<<dim3(Tt / BNt, mp / BMt, Bb), 256, smem_n>>>(
        sc, Qt, xf,
        Dd, Dd, Dd, Tt, Hu, Tt,
        (ll)mp * Dd, (ll)Tt * Dd, (ll)mp * Tt, 1, 0);

    // 5) softmax -> unnormalized exp (single fp16) + row sums
    softmax_k<<<Bb * Hu, 256>>>(sc, ahf, rsum, Hu, mp);

    // 6) wx partials = e[b] @ x[b]   (fp16 1-term, split-K=2, B = x^T)
    mma_f16_1t_k<<<dim3(Dd / BNt, mp / BMt, Bb * 2), 256, smem_n>>>(
        wxp, ahf, xth,
        Tt / 2, Tt, Tt, Dd, mp, Dd,
        (ll)mp * Tt, (ll)Dd * Tt, (ll)mp * Dd, 2, (ll)Bb * mp * Dd);
    redsplit2_k<<<1024, 256>>>(wxp, wxh, wxl, Bb * mp * Dd, (ll)Bb * mp * Dd);

    // 7) ctx[b,h] = wx[b,h] @ Wv_h^T   (bf16 3-term, fp32 out)
    mma_gemm_k<0><<<dim3(1, 1, Bb * Hh), 256, smem_n>>>(
        ctx, nullptr, wxh, wxl, Wvh, Wvl,
        Dd, Dd, Dd, DHh, u, DHh,
        (ll)mp * Dd, (ll)u * Dd, 0, (ll)DHh * Dd, (ll)Hh * u * DHh, (ll)u * DHh, Hh, 1, 0);

    // 8) reorder ctx + normalize + mean row -> bf16 split
    ctxrow_mean_k<<<dim3(Bb, Hh), 64>>>(crh, crl, ctx, rsum, u, Hu);

    // 9) ys = cr @ Wo^T   (bf16 3-term, fp32 out)
    mma_gemm_k<0><<<dim3(Dd / BNt, 1, Bb), 256, smem_n>>>(
        ys, nullptr, crh, crl, Woh, Wol,
        Dd, Dd, Dd, Dd, u + 1, Dd,
        (ll)(u + 1) * Dd, 0, 0, 0, (ll)(u + 1) * Dd, 0, 1, 1, 0);

    // 10) broadcast + scatter
    fill_k<<<Bb * (Tt / 8), 256>>>((float4*)y, (const float4*)ys, (const float4*)bo, u);
    scatter_k<<<dim3(Bb, u), 256>>>((float4*)y, (const float4*)ys, (const float4*)bo, idx, u);
}